// round 4
// baseline (speedup 1.0000x reference)
#include <cuda_runtime.h>
#include <math.h>
#include <stdint.h>
#define NI 16384
#define NB 256

__device__ float g_y1[102760448];
__device__ float g_y2[102760448];
__device__ float g_y2p[102760448];
__device__ float g_y3[8388608];
__device__ float g_W2t[65536];
__device__ float g_W3t[3211264];
__device__ float g_Wc[32768];
__device__ float g_cb[64];
__device__ float g_mean[6][512], g_rstd[6][512];
__device__ float g_spart[16384];
__device__ float g_z[524288];
__device__ float g_loc[NI];
__device__ float g_klrow[NI];
__device__ int   g_arg[NB];
__device__ float g_term[NB];
__device__ float g_rec[NB];
__device__ float g_t1[131072];
__device__ float g_t2[1605632];
__device__ float g_t3[1605632];

__device__ __forceinline__ float2 bsum2(float2 v) {
    __shared__ float2 sh[32];
    int lane = threadIdx.x & 31, w = threadIdx.x >> 5;
#pragma unroll
    for (int o = 16; o > 0; o >>= 1) { v.x += __shfl_xor_sync(~0u, v.x, o); v.y += __shfl_xor_sync(~0u, v.y, o); }
    __syncthreads();
    if (lane == 0) sh[w] = v;
    __syncthreads();
    int nw = (blockDim.x + 31) >> 5;
    if (w == 0) {
        v = (lane < nw) ? sh[lane] : make_float2(0.f, 0.f);
#pragma unroll
        for (int o = 16; o > 0; o >>= 1) { v.x += __shfl_xor_sync(~0u, v.x, o); v.y += __shfl_xor_sync(~0u, v.y, o); }
    }
    return v;
}

__global__ void prep_kernel(const float* W2, const float* W3, const float* Wm, const float* Wlv,
                            const float* W4, const float* b4, const float* bm, const float* blv) {
    int i = blockIdx.x * 256 + threadIdx.x;
    if (i < 65536) g_W2t[i] = W2[(i & 127) * 512 + (i >> 7)];
    for (int j = i; j < 3211264; j += 12544 * 256)
        g_W3t[j] = W3[(size_t)(j & 511) * 6272 + (j >> 9)];
    if (i < 32768) {
        int ic = i >> 6, r = i & 63;
        const float* row = (r < 32) ? (Wm + r * 200) : (Wlv + (r - 32) * 200);
        float s = 0.f;
        for (int j = 0; j < 200; j++) s += row[j] * W4[j * 512 + ic];
        g_Wc[ic * 64 + r] = s;
        if (ic == 0) {
            float cb = (r < 32) ? bm[r] : blv[r - 32];
            for (int j = 0; j < 200; j++) cb += row[j] * b4[j];
            g_cb[r] = cb;
        }
    }
}

__global__ void __launch_bounds__(256) conv1_kernel(const float* __restrict__ bag, const float* __restrict__ W1) {
    __shared__ float xs[784], ws[512];
    int n = blockIdx.x, tid = threadIdx.x;
    for (int i = tid; i < 784; i += 256) xs[i] = bag[(size_t)n * 784 + i];
    for (int i = tid; i < 512; i += 256) ws[i] = W1[i];
    __syncthreads();
    int oc = tid >> 3, sub = tid & 7;
    float w[16];
#pragma unroll
    for (int t = 0; t < 16; t++) w[t] = ws[oc * 16 + t];
    for (int p = sub; p < 196; p += 8) {
        int oy = p / 14, ox = p - (p / 14) * 14;
        float a = 0.f;
#pragma unroll
        for (int ky = 0; ky < 4; ky++) {
            int iy = 2 * oy - 1 + ky;
            if ((unsigned)iy < 28u)
#pragma unroll
                for (int kx = 0; kx < 4; kx++) {
                    int ix = 2 * ox - 1 + kx;
                    if ((unsigned)ix < 28u) a += xs[iy * 28 + ix] * w[ky * 4 + kx];
                }
        }
        g_y1[(size_t)n * 6272 + oc * 196 + p] = a;
    }
}

__global__ void __launch_bounds__(256) stats_part(const float* __restrict__ src, int HW, int Nn, int sN, int sC, int sI) {
    int c = blockIdx.x, p = blockIdx.y, P = gridDim.y, tid = threadIdx.x;
    int total = Nn * HW;
    float s = 0.f, q = 0.f;
    for (int j = p * 256 + tid; j < total; j += P * 256) {
        int n = j / HW, i = j - n * HW;
        float v = src[(size_t)n * sN + (size_t)c * sC + (size_t)i * sI];
        s += v; q += v * v;
    }
    float2 r = bsum2(make_float2(s, q));
    if (tid == 0) { g_spart[(c * P + p) * 2] = r.x; g_spart[(c * P + p) * 2 + 1] = r.y; }
}

__global__ void stats_fin(int id, int P, int count) {
    int c = threadIdx.x;
    float s = 0.f, q = 0.f;
    for (int p = 0; p < P; p++) { s += g_spart[(c * P + p) * 2]; q += g_spart[(c * P + p) * 2 + 1]; }
    float m = s / count;
    g_mean[id][c] = m;
    g_rstd[id][c] = rsqrtf(q / count - m * m + 1e-5f);
}

__global__ void __launch_bounds__(256) conv2_gemm() {
    __shared__ float As[16][132], Bs[16][132], sm[32], sr[32];
    int tid = threadIdx.x;
    if (tid < 32) { sm[tid] = g_mean[0][tid]; sr[tid] = g_rstd[0][tid]; }
    int M0 = blockIdx.x * 128;
    int abase[8]; unsigned aval = 0;
#pragma unroll
    for (int q = 0; q < 8; q++) {
        int idx = q * 256 + tid, kk = idx >> 7, mm = idx & 127;
        int m = M0 + mm, n = m / 49, p = m - n * 49;
        int oy = p / 7, ox = p - (p / 7) * 7;
        int iy = 2 * oy - 1 + (kk >> 2), ix = 2 * ox - 1 + (kk & 3);
        if (iy >= 0 && iy < 14 && ix >= 0 && ix < 14) aval |= 1u << q;
        abase[q] = n * 6272 + iy * 14 + ix;
    }
    __syncthreads();
    float acc[8][8] = {};
    int ty = tid >> 4, tx = tid & 15;
    for (int kt = 0; kt < 32; kt++) {
        float mc = sm[kt], rc = sr[kt];
#pragma unroll
        for (int q = 0; q < 8; q++) {
            int idx = q * 256 + tid;
            float v = 0.f;
            if (aval & (1u << q)) v = fmaxf((g_y1[abase[q] + kt * 196] - mc) * rc, 0.f);
            As[idx >> 7][idx & 127] = v;
            Bs[idx >> 7][idx & 127] = g_W2t[(kt * 16 + (idx >> 7)) * 128 + (idx & 127)];
        }
        __syncthreads();
#pragma unroll
        for (int k = 0; k < 16; k++) {
            float4 a0 = *(const float4*)&As[k][ty * 8], a1 = *(const float4*)&As[k][ty * 8 + 4];
            float4 b0 = *(const float4*)&Bs[k][tx * 8], b1 = *(const float4*)&Bs[k][tx * 8 + 4];
            float av[8] = {a0.x, a0.y, a0.z, a0.w, a1.x, a1.y, a1.z, a1.w};
            float bv[8] = {b0.x, b0.y, b0.z, b0.w, b1.x, b1.y, b1.z, b1.w};
#pragma unroll
            for (int i = 0; i < 8; i++)
#pragma unroll
                for (int j = 0; j < 8; j++) acc[i][j] += av[i] * bv[j];
        }
        __syncthreads();
    }
#pragma unroll
    for (int i = 0; i < 8; i++) {
        float* d = &g_y2[(size_t)(M0 + ty * 8 + i) * 128 + tx * 8];
        *(float4*)d = make_float4(acc[i][0], acc[i][1], acc[i][2], acc[i][3]);
        *(float4*)(d + 4) = make_float4(acc[i][4], acc[i][5], acc[i][6], acc[i][7]);
    }
}

__global__ void __launch_bounds__(256) pack2_kernel() {
    __shared__ float t[49 * 133];
    int n = blockIdx.x, tid = threadIdx.x;
    for (int i = tid; i < 6272; i += 256) t[(i >> 7) * 133 + (i & 127)] = g_y2[(size_t)n * 6272 + i];
    __syncthreads();
    for (int o = tid; o < 6272; o += 256) {
        int c = o / 49, p = o - c * 49;
        g_y2p[(size_t)n * 6272 + o] = fmaxf((t[p * 133 + c] - g_mean[1][c]) * g_rstd[1][c], 0.f);
    }
}

__global__ void __launch_bounds__(256) conv3_gemm() {
    __shared__ float As[16][132], Bs[16][132];
    int tid = threadIdx.x, M0 = blockIdx.x * 128, N0 = blockIdx.y * 128;
    float acc[8][8] = {};
    int ty = tid >> 4, tx = tid & 15;
    for (int kt = 0; kt < 392; kt++) {
#pragma unroll
        for (int q = 0; q < 8; q++) {
            int idx = q * 256 + tid;
            As[idx & 15][idx >> 4] = g_y2p[(size_t)(M0 + (idx >> 4)) * 6272 + kt * 16 + (idx & 15)];
            Bs[idx >> 7][idx & 127] = g_W3t[(size_t)(kt * 16 + (idx >> 7)) * 512 + N0 + (idx & 127)];
        }
        __syncthreads();
#pragma unroll
        for (int k = 0; k < 16; k++) {
            float4 a0 = *(const float4*)&As[k][ty * 8], a1 = *(const float4*)&As[k][ty * 8 + 4];
            float4 b0 = *(const float4*)&Bs[k][tx * 8], b1 = *(const float4*)&Bs[k][tx * 8 + 4];
            float av[8] = {a0.x, a0.y, a0.z, a0.w, a1.x, a1.y, a1.z, a1.w};
            float bv[8] = {b0.x, b0.y, b0.z, b0.w, b1.x, b1.y, b1.z, b1.w};
#pragma unroll
            for (int i = 0; i < 8; i++)
#pragma unroll
                for (int j = 0; j < 8; j++) acc[i][j] += av[i] * bv[j];
        }
        __syncthreads();
    }
#pragma unroll
    for (int i = 0; i < 8; i++) {
        float* d = &g_y3[(size_t)(M0 + ty * 8 + i) * 512 + N0 + tx * 8];
        *(float4*)d = make_float4(acc[i][0], acc[i][1], acc[i][2], acc[i][3]);
        *(float4*)(d + 4) = make_float4(acc[i][4], acc[i][5], acc[i][6], acc[i][7]);
    }
}

__global__ void __launch_bounds__(64) latent_kernel(const float* __restrict__ eps, const float* __restrict__ Wfc,
                                                    const float* __restrict__ bfc) {
    __shared__ float sa[512], smu[32], slv[32];
    int n = blockIdx.x, tid = threadIdx.x;
    for (int i = tid; i < 512; i += 64)
        sa[i] = fmaxf((g_y3[(size_t)n * 512 + i] - g_mean[2][i]) * g_rstd[2][i], 0.f);
    __syncthreads();
    float dot = g_cb[tid];
#pragma unroll 8
    for (int ic = 0; ic < 512; ic++) dot += sa[ic] * g_Wc[ic * 64 + tid];
    if (tid < 32) smu[tid] = dot; else slv[tid - 32] = dot;
    __syncthreads();
    if (tid < 32) {
        float mu = smu[tid], lv = slv[tid], sd = expf(0.5f * lv);
        float z = mu + sd * eps[(size_t)n * 32 + tid];
        g_z[(size_t)n * 32 + tid] = z;
        float kl = mu * mu + sd * sd - lv - 1.f;
        float lc = z * Wfc[tid];
#pragma unroll
        for (int o = 16; o > 0; o >>= 1) { kl += __shfl_xor_sync(~0u, kl, o); lc += __shfl_xor_sync(~0u, lc, o); }
        if (tid == 0) { g_klrow[n] = kl; g_loc[n] = lc + bfc[0]; }
    }
}

__global__ void __launch_bounds__(256) bagmax_kernel(const int* __restrict__ bi, const float* __restrict__ lab) {
    __shared__ float sv[8]; __shared__ int si[8]; __shared__ float smx;
    int b = blockIdx.x, tid = threadIdx.x, lane = tid & 31, w = tid >> 5;
    float mx = -3.4e38f;
    for (int n = tid; n < NI; n += 256) if (bi[n] == b) mx = fmaxf(mx, g_loc[n]);
#pragma unroll
    for (int o = 16; o > 0; o >>= 1) mx = fmaxf(mx, __shfl_xor_sync(~0u, mx, o));
    if (lane == 0) sv[w] = mx;
    __syncthreads();
    if (tid == 0) { float v = sv[0]; for (int i = 1; i < 8; i++) v = fmaxf(v, sv[i]); smx = v; }
    __syncthreads();
    float mval = smx; int mn = NI;
    for (int n = tid; n < NI; n += 256) if (bi[n] == b && g_loc[n] == mval) mn = min(mn, n);
#pragma unroll
    for (int o = 16; o > 0; o >>= 1) mn = min(mn, __shfl_xor_sync(~0u, mn, o));
    if (lane == 0) si[w] = mn;
    __syncthreads();
    if (tid == 0) {
        int a = si[0]; for (int i = 1; i < 8; i++) a = min(a, si[i]);
        g_arg[b] = a;
        float M = g_loc[a], y = lab[b];
        g_term[b] = fmaxf(M, 0.f) - M * y + log1pf(expf(-fabsf(M)));
    }
}

__global__ void __launch_bounds__(512) dec1_kernel(const float* __restrict__ D1) {
    __shared__ float zz[32];
    int b = blockIdx.x, tid = threadIdx.x;
    if (tid < 32) zz[tid] = g_z[(size_t)g_arg[b] * 32 + tid];
    __syncthreads();
    float a = 0.f;
#pragma unroll
    for (int ic = 0; ic < 32; ic++) a += zz[ic] * D1[ic * 512 + tid];
    g_t1[b * 512 + tid] = a;
}

__global__ void __launch_bounds__(256) dec2_kernel(const float* __restrict__ D2) {
    __shared__ float at[4096];
    int B0 = blockIdx.x * 8, tid = threadIdx.x;
    for (int i = tid; i < 4096; i += 256) {
        int bl = i >> 9, ic = i & 511;
        at[ic * 8 + bl] = fmaxf((g_t1[(B0 + bl) * 512 + ic] - g_mean[3][ic]) * g_rstd[3][ic], 0.f);
    }
    __syncthreads();
    for (int o = tid; o < 6272; o += 256) {
        float acc[8] = {};
        for (int ic = 0; ic < 512; ic++) {
            float w = D2[(size_t)ic * 6272 + o];
            float4 x0 = *(const float4*)&at[ic * 8], x1 = *(const float4*)&at[ic * 8 + 4];
            acc[0] += x0.x * w; acc[1] += x0.y * w; acc[2] += x0.z * w; acc[3] += x0.w * w;
            acc[4] += x1.x * w; acc[5] += x1.y * w; acc[6] += x1.z * w; acc[7] += x1.w * w;
        }
#pragma unroll
        for (int j = 0; j < 8; j++) g_t2[(size_t)(B0 + j) * 6272 + o] = acc[j];
    }
}

__global__ void __launch_bounds__(256) dec3_kernel(const float* __restrict__ D3) {
    __shared__ float a2[6272], wt[2048];
    int b = blockIdx.x, tid = threadIdx.x;
    for (int i = tid; i < 6272; i += 256) {
        int c = i / 49;
        a2[i] = fmaxf((g_t2[(size_t)b * 6272 + i] - g_mean[4][c]) * g_rstd[4][c], 0.f);
    }
    __syncthreads();
    int oy = tid / 14, ox = tid - (tid / 14) * 14;
    for (int oc = 0; oc < 32; oc++) {
        for (int i = tid; i < 2048; i += 256) wt[i] = D3[(i >> 4) * 512 + oc * 16 + (i & 15)];
        __syncthreads();
        if (tid < 196) {
            float a = 0.f;
#pragma unroll
            for (int ky = 0; ky < 4; ky++) {
                int t = oy + 1 - ky;
                if (t >= 0 && !(t & 1) && (t >> 1) < 7) {
                    int iy = t >> 1;
#pragma unroll
                    for (int kx = 0; kx < 4; kx++) {
                        int u = ox + 1 - kx;
                        if (u >= 0 && !(u & 1) && (u >> 1) < 7) {
                            int sB = iy * 7 + (u >> 1), wB = ky * 4 + kx;
#pragma unroll 16
                            for (int ic = 0; ic < 128; ic++) a += a2[ic * 49 + sB] * wt[ic * 16 + wB];
                        }
                    }
                }
            }
            g_t3[(size_t)b * 6272 + oc * 196 + tid] = a;
        }
        __syncthreads();
    }
}

__global__ void __launch_bounds__(256) dec4_kernel(const float* __restrict__ D4, const float* __restrict__ d4,
                                                   const float* __restrict__ bag) {
    __shared__ float a3[6272], w4s[512];
    int b = blockIdx.x, tid = threadIdx.x;
    for (int i = tid; i < 6272; i += 256) {
        int c = i / 196;
        a3[i] = fmaxf((g_t3[(size_t)b * 6272 + i] - g_mean[5][c]) * g_rstd[5][c], 0.f);
    }
    for (int i = tid; i < 512; i += 256) w4s[i] = D4[i];
    __syncthreads();
    float bias = d4[0]; int arg = g_arg[b];
    float sq = 0.f;
    for (int o = tid; o < 784; o += 256) {
        int oy = o / 28, ox = o - (o / 28) * 28;
        float a = bias;
#pragma unroll
        for (int ky = 0; ky < 4; ky++) {
            int t = oy + 1 - ky;
            if (t >= 0 && !(t & 1) && (t >> 1) < 14) {
                int iy = t >> 1;
#pragma unroll
                for (int kx = 0; kx < 4; kx++) {
                    int u = ox + 1 - kx;
                    if (u >= 0 && !(u & 1) && (u >> 1) < 14) {
                        int sB = iy * 14 + (u >> 1), wB = ky * 4 + kx;
#pragma unroll
                        for (int ic = 0; ic < 32; ic++) a += a3[ic * 196 + sB] * w4s[ic * 16 + wB];
                    }
                }
            }
        }
        float s = 1.f / (1.f + expf(-a));
        float d = s - bag[(size_t)arg * 784 + o];
        sq += d * d;
    }
    float2 r = bsum2(make_float2(sq, 0.f));
    if (tid == 0) g_rec[b] = r.x;
}

__global__ void __launch_bounds__(256) final_kernel(float* __restrict__ out) {
    int tid = threadIdx.x;
    float kl = 0.f;
    for (int n = tid; n < NI; n += 256) kl += g_klrow[n];
    float tm = 0.f, rc = 0.f;
    if (tid < NB) { tm = g_term[tid]; rc = g_rec[tid]; }
    float2 a = bsum2(make_float2(kl, tm));
    __syncthreads();
    float2 bb = bsum2(make_float2(rc, 0.f));
    if (tid == 0) {
        out[0] = bb.x / (256.f * 784.f);
        out[1] = 0.5f * a.x / (16384.f * 32.f);
        out[2] = a.y / 256.f;
    }
}

extern "C" void kernel_launch(void* const* d_in, const int* in_sizes, int n_in,
                              void* d_out, int out_size) {
    const float* bag = (const float*)d_in[0];
    const int* bag_idx = (const int*)d_in[1];
    const float* lab = (const float*)d_in[2];
    const float* eps = (const float*)d_in[3];
    const float* W1 = (const float*)d_in[4];
    const float* W2 = (const float*)d_in[6];
    const float* W3 = (const float*)d_in[8];
    const float* W4 = (const float*)d_in[10];
    const float* b4 = (const float*)d_in[11];
    const float* Wm = (const float*)d_in[12];
    const float* bm = (const float*)d_in[13];
    const float* Wlv = (const float*)d_in[14];
    const float* blv = (const float*)d_in[15];
    const float* Wfc = (const float*)d_in[16];
    const float* bfc = (const float*)d_in[17];
    const float* D1 = (const float*)d_in[18];
    const float* D2 = (const float*)d_in[20];
    const float* D3 = (const float*)d_in[22];
    const float* D4 = (const float*)d_in[24];
    const float* d4 = (const float*)d_in[25];

    float *y1, *y2, *y2p, *y3, *t1, *t2, *t3;
    cudaGetSymbolAddress((void**)&y1, g_y1);
    cudaGetSymbolAddress((void**)&y2, g_y2);
    cudaGetSymbolAddress((void**)&y2p, g_y2p);
    cudaGetSymbolAddress((void**)&y3, g_y3);
    cudaGetSymbolAddress((void**)&t1, g_t1);
    cudaGetSymbolAddress((void**)&t2, g_t2);
    cudaGetSymbolAddress((void**)&t3, g_t3);

    prep_kernel<<<12544, 256>>>(W2, W3, Wm, Wlv, W4, b4, bm, blv);
    conv1_kernel<<<NI, 256>>>(bag, W1);
    stats_part<<<dim3(32, 8), 256>>>(y1, 196, NI, 6272, 196, 1);
    stats_fin<<<1, 32>>>(0, 8, NI * 196);
    conv2_gemm<<<6272, 256>>>();
    stats_part<<<dim3(128, 8), 256>>>(y2, 1, NI * 49, 128, 1, 0);
    stats_fin<<<1, 128>>>(1, 8, NI * 49);
    pack2_kernel<<<NI, 256>>>();
    conv3_gemm<<<dim3(128, 4), 256>>>();
    stats_part<<<dim3(512, 8), 256>>>(y3, 1, NI, 512, 1, 0);
    stats_fin<<<1, 512>>>(2, 8, NI);
    latent_kernel<<<NI, 64>>>(eps, Wfc, bfc);
    bagmax_kernel<<<NB, 256>>>(bag_idx, lab);
    dec1_kernel<<<NB, 512>>>(D1);
    stats_part<<<dim3(512, 2), 256>>>(t1, 1, NB, 512, 1, 0);
    stats_fin<<<1, 512>>>(3, 2, NB);
    dec2_kernel<<<32, 256>>>(D2);
    stats_part<<<dim3(128, 2), 256>>>(t2, 49, NB, 6272, 49, 1);
    stats_fin<<<1, 128>>>(4, 2, NB * 49);
    dec3_kernel<<<NB, 256>>>(D3);
    stats_part<<<dim3(32, 2), 256>>>(t3, 196, NB, 6272, 196, 1);
    stats_fin<<<1, 32>>>(5, 2, NB * 196);
    dec4_kernel<<<NB, 256>>>(D4, d4, bag);
    final_kernel<<<1, 256>>>((float*)d_out);
}

// round 5
// speedup vs baseline: 1.0754x; 1.0754x over previous
#include <cuda_runtime.h>
#include <math.h>
#include <stdint.h>
#define NI 16384
#define NB 256

__device__ float g_y1[102760448];
__device__ float g_y2[102760448];
__device__ float g_y2p[102760448];
__device__ float g_y3[8388608];
__device__ float g_W2t[65536];
__device__ float g_W3t[3211264];
__device__ float g_Wc[32768];
__device__ float g_cb[64];
__device__ float g_mean[6][512], g_rstd[6][512];
__device__ float g_spart[16384];
__device__ float g_z[524288];
__device__ float g_loc[NI];
__device__ float g_klrow[NI];
__device__ int   g_arg[NB];
__device__ float g_term[NB];
__device__ float g_rec[NB];
__device__ float g_t1[131072];
__device__ float g_t2[1605632];
__device__ float g_t3[1605632];

__device__ __forceinline__ float2 bsum2(float2 v) {
    __shared__ float2 sh[32];
    int lane = threadIdx.x & 31, w = threadIdx.x >> 5;
#pragma unroll
    for (int o = 16; o > 0; o >>= 1) { v.x += __shfl_xor_sync(~0u, v.x, o); v.y += __shfl_xor_sync(~0u, v.y, o); }
    __syncthreads();
    if (lane == 0) sh[w] = v;
    __syncthreads();
    int nw = (blockDim.x + 31) >> 5;
    if (w == 0) {
        v = (lane < nw) ? sh[lane] : make_float2(0.f, 0.f);
#pragma unroll
        for (int o = 16; o > 0; o >>= 1) { v.x += __shfl_xor_sync(~0u, v.x, o); v.y += __shfl_xor_sync(~0u, v.y, o); }
    }
    return v;
}

__global__ void prep_kernel(const float* W2, const float* W3, const float* Wm, const float* Wlv,
                            const float* W4, const float* b4, const float* bm, const float* blv) {
    int i = blockIdx.x * 256 + threadIdx.x;
    if (i < 65536) g_W2t[i] = W2[(i & 127) * 512 + (i >> 7)];
    for (int j = i; j < 3211264; j += 12544 * 256)
        g_W3t[j] = W3[(size_t)(j & 511) * 6272 + (j >> 9)];
    if (i < 32768) {
        int ic = i >> 6, r = i & 63;
        const float* row = (r < 32) ? (Wm + r * 200) : (Wlv + (r - 32) * 200);
        float s = 0.f;
        for (int j = 0; j < 200; j++) s += row[j] * W4[j * 512 + ic];
        g_Wc[ic * 64 + r] = s;
        if (ic == 0) {
            float cb = (r < 32) ? bm[r] : blv[r - 32];
            for (int j = 0; j < 200; j++) cb += row[j] * b4[j];
            g_cb[r] = cb;
        }
    }
}

__global__ void __launch_bounds__(256) conv1_kernel(const float* __restrict__ bag, const float* __restrict__ W1) {
    __shared__ float xs[784], ws[512];
    int n = blockIdx.x, tid = threadIdx.x;
    for (int i = tid; i < 784; i += 256) xs[i] = bag[(size_t)n * 784 + i];
    for (int i = tid; i < 512; i += 256) ws[i] = W1[i];
    __syncthreads();
    int oc = tid >> 3, sub = tid & 7;
    float w[16];
#pragma unroll
    for (int t = 0; t < 16; t++) w[t] = ws[oc * 16 + t];
    for (int p = sub; p < 196; p += 8) {
        int oy = p / 14, ox = p - (p / 14) * 14;
        float a = 0.f;
#pragma unroll
        for (int ky = 0; ky < 4; ky++) {
            int iy = 2 * oy - 1 + ky;
            if ((unsigned)iy < 28u)
#pragma unroll
                for (int kx = 0; kx < 4; kx++) {
                    int ix = 2 * ox - 1 + kx;
                    if ((unsigned)ix < 28u) a += xs[iy * 28 + ix] * w[ky * 4 + kx];
                }
        }
        g_y1[(size_t)n * 6272 + oc * 196 + p] = a;
    }
}

__global__ void __launch_bounds__(256) stats_part(const float* __restrict__ src, int HW, int Nn, int sN, int sC, int sI) {
    int c = blockIdx.x, p = blockIdx.y, P = gridDim.y, tid = threadIdx.x;
    int total = Nn * HW;
    float s = 0.f, q = 0.f;
    for (int j = p * 256 + tid; j < total; j += P * 256) {
        int n = j / HW, i = j - n * HW;
        float v = src[(size_t)n * sN + (size_t)c * sC + (size_t)i * sI];
        s += v; q += v * v;
    }
    float2 r = bsum2(make_float2(s, q));
    if (tid == 0) { g_spart[(c * P + p) * 2] = r.x; g_spart[(c * P + p) * 2 + 1] = r.y; }
}

__global__ void stats_fin(int id, int P, int count) {
    int c = threadIdx.x;
    float s = 0.f, q = 0.f;
    for (int p = 0; p < P; p++) { s += g_spart[(c * P + p) * 2]; q += g_spart[(c * P + p) * 2 + 1]; }
    float m = s / count;
    g_mean[id][c] = m;
    g_rstd[id][c] = rsqrtf(q / count - m * m + 1e-5f);
}

// conv2 implicit-im2col GEMM, M=802816 N=128 K=512, k-tile 8, double-buffered (1 sync/iter).
// BN1 finalize folded into prologue (reads g_spart, P=8, 32 ch).
__global__ void __launch_bounds__(256) conv2_gemm() {
    __shared__ float As[2][8][132], Bs[2][8][132];
    __shared__ float sm[32], sr[32];
    int tid = threadIdx.x;
    if (tid < 32) {
        float s = 0.f, q = 0.f;
#pragma unroll
        for (int p = 0; p < 8; p++) { s += g_spart[(tid * 8 + p) * 2]; q += g_spart[(tid * 8 + p) * 2 + 1]; }
        float cnt = (float)NI * 196.f, m = s / cnt;
        sm[tid] = m; sr[tid] = rsqrtf(q / cnt - m * m + 1e-5f);
    }
    int M0 = blockIdx.x * 128;
    int aoff[4][2]; unsigned aval = 0;
#pragma unroll
    for (int q = 0; q < 4; q++) {
        int idx = q * 256 + tid, kk = idx >> 7, mm = idx & 127;
        int m = M0 + mm, n = m / 49, p = m - n * 49;
        int oy = p / 7, ox = p - (p / 7) * 7;
#pragma unroll
        for (int par = 0; par < 2; par++) {
            int r = kk + par * 8;
            int iy = 2 * oy - 1 + (r >> 2), ix = 2 * ox - 1 + (r & 3);
            if (iy >= 0 && iy < 14 && ix >= 0 && ix < 14) aval |= 1u << (q * 2 + par);
            aoff[q][par] = n * 6272 + iy * 14 + ix;
        }
    }
    __syncthreads();
    // prologue: load kt=0 (par=0, ic=0) into stage 0
#pragma unroll
    for (int q = 0; q < 4; q++) {
        int idx = q * 256 + tid, kk = idx >> 7, mm = idx & 127;
        float v = 0.f;
        if (aval & (1u << (q * 2))) v = fmaxf((g_y1[aoff[q][0]] - sm[0]) * sr[0], 0.f);
        As[0][kk][mm] = v;
        Bs[0][kk][mm] = g_W2t[kk * 128 + mm];
    }
    __syncthreads();
    float acc[8][8] = {};
    int ty = tid >> 4, tx = tid & 15;
    for (int kt = 0; kt < 64; kt++) {
        int cur = kt & 1, nxt = cur ^ 1;
        if (kt < 63) {
            int k0 = (kt + 1) * 8, par = (kt + 1) & 1, ic = k0 >> 4;
            float mc = sm[ic], rc = sr[ic];
#pragma unroll
            for (int q = 0; q < 4; q++) {
                int idx = q * 256 + tid, kk = idx >> 7, mm = idx & 127;
                float v = 0.f;
                if (aval & (1u << (q * 2 + par))) v = fmaxf((g_y1[aoff[q][par] + ic * 196] - mc) * rc, 0.f);
                As[nxt][kk][mm] = v;
                Bs[nxt][kk][mm] = g_W2t[(k0 + kk) * 128 + mm];
            }
        }
#pragma unroll
        for (int k = 0; k < 8; k++) {
            float4 a0 = *(const float4*)&As[cur][k][ty * 8], a1 = *(const float4*)&As[cur][k][ty * 8 + 4];
            float4 b0 = *(const float4*)&Bs[cur][k][tx * 8], b1 = *(const float4*)&Bs[cur][k][tx * 8 + 4];
            float av[8] = {a0.x, a0.y, a0.z, a0.w, a1.x, a1.y, a1.z, a1.w};
            float bv[8] = {b0.x, b0.y, b0.z, b0.w, b1.x, b1.y, b1.z, b1.w};
#pragma unroll
            for (int i = 0; i < 8; i++)
#pragma unroll
                for (int j = 0; j < 8; j++) acc[i][j] += av[i] * bv[j];
        }
        __syncthreads();
    }
#pragma unroll
    for (int i = 0; i < 8; i++) {
        float* d = &g_y2[(size_t)(M0 + ty * 8 + i) * 128 + tx * 8];
        *(float4*)d = make_float4(acc[i][0], acc[i][1], acc[i][2], acc[i][3]);
        *(float4*)(d + 4) = make_float4(acc[i][4], acc[i][5], acc[i][6], acc[i][7]);
    }
}

// pack2 with BN2 finalize folded in (g_spart, P=8, 128 ch)
__global__ void __launch_bounds__(256) pack2_kernel() {
    __shared__ float t[49 * 133];
    __shared__ float m2[128], r2[128];
    int n = blockIdx.x, tid = threadIdx.x;
    if (tid < 128) {
        float s = 0.f, q = 0.f;
#pragma unroll
        for (int p = 0; p < 8; p++) { s += g_spart[(tid * 8 + p) * 2]; q += g_spart[(tid * 8 + p) * 2 + 1]; }
        float cnt = (float)NI * 49.f, m = s / cnt;
        m2[tid] = m; r2[tid] = rsqrtf(q / cnt - m * m + 1e-5f);
    }
    for (int i = tid; i < 6272; i += 256) t[(i >> 7) * 133 + (i & 127)] = g_y2[(size_t)n * 6272 + i];
    __syncthreads();
    for (int o = tid; o < 6272; o += 256) {
        int c = o / 49, p = o - c * 49;
        g_y2p[(size_t)n * 6272 + o] = fmaxf((t[p * 133 + c] - m2[c]) * r2[c], 0.f);
    }
}

// conv3 GEMM, M=16384 N=512 K=6272, k-tile 8, double-buffered (1 sync/iter)
__global__ void __launch_bounds__(256) conv3_gemm() {
    __shared__ float As[2][8][132], Bs[2][8][132];
    int tid = threadIdx.x, M0 = blockIdx.x * 128, N0 = blockIdx.y * 128;
    int akk = tid & 7, amm = tid >> 3;    // + q*32
    // prologue kt=0
#pragma unroll
    for (int q = 0; q < 4; q++) {
        As[0][akk][amm + q * 32] = g_y2p[(size_t)(M0 + amm + q * 32) * 6272 + akk];
        int idx = q * 256 + tid;
        Bs[0][idx >> 7][idx & 127] = g_W3t[(size_t)(idx >> 7) * 512 + N0 + (idx & 127)];
    }
    __syncthreads();
    float acc[8][8] = {};
    int ty = tid >> 4, tx = tid & 15;
    for (int kt = 0; kt < 784; kt++) {
        int cur = kt & 1, nxt = cur ^ 1;
        if (kt < 783) {
            int k0 = (kt + 1) * 8;
#pragma unroll
            for (int q = 0; q < 4; q++) {
                As[nxt][akk][amm + q * 32] = g_y2p[(size_t)(M0 + amm + q * 32) * 6272 + k0 + akk];
                int idx = q * 256 + tid;
                Bs[nxt][idx >> 7][idx & 127] = g_W3t[(size_t)(k0 + (idx >> 7)) * 512 + N0 + (idx & 127)];
            }
        }
#pragma unroll
        for (int k = 0; k < 8; k++) {
            float4 a0 = *(const float4*)&As[cur][k][ty * 8], a1 = *(const float4*)&As[cur][k][ty * 8 + 4];
            float4 b0 = *(const float4*)&Bs[cur][k][tx * 8], b1 = *(const float4*)&Bs[cur][k][tx * 8 + 4];
            float av[8] = {a0.x, a0.y, a0.z, a0.w, a1.x, a1.y, a1.z, a1.w};
            float bv[8] = {b0.x, b0.y, b0.z, b0.w, b1.x, b1.y, b1.z, b1.w};
#pragma unroll
            for (int i = 0; i < 8; i++)
#pragma unroll
                for (int j = 0; j < 8; j++) acc[i][j] += av[i] * bv[j];
        }
        __syncthreads();
    }
#pragma unroll
    for (int i = 0; i < 8; i++) {
        float* d = &g_y3[(size_t)(M0 + ty * 8 + i) * 512 + N0 + tx * 8];
        *(float4*)d = make_float4(acc[i][0], acc[i][1], acc[i][2], acc[i][3]);
        *(float4*)(d + 4) = make_float4(acc[i][4], acc[i][5], acc[i][6], acc[i][7]);
    }
}

__global__ void __launch_bounds__(64) latent_kernel(const float* __restrict__ eps, const float* __restrict__ Wfc,
                                                    const float* __restrict__ bfc) {
    __shared__ float sa[512], smu[32], slv[32];
    int n = blockIdx.x, tid = threadIdx.x;
    for (int i = tid; i < 512; i += 64)
        sa[i] = fmaxf((g_y3[(size_t)n * 512 + i] - g_mean[2][i]) * g_rstd[2][i], 0.f);
    __syncthreads();
    float dot = g_cb[tid];
#pragma unroll 8
    for (int ic = 0; ic < 512; ic++) dot += sa[ic] * g_Wc[ic * 64 + tid];
    if (tid < 32) smu[tid] = dot; else slv[tid - 32] = dot;
    __syncthreads();
    if (tid < 32) {
        float mu = smu[tid], lv = slv[tid], sd = expf(0.5f * lv);
        float z = mu + sd * eps[(size_t)n * 32 + tid];
        g_z[(size_t)n * 32 + tid] = z;
        float kl = mu * mu + sd * sd - lv - 1.f;
        float lc = z * Wfc[tid];
#pragma unroll
        for (int o = 16; o > 0; o >>= 1) { kl += __shfl_xor_sync(~0u, kl, o); lc += __shfl_xor_sync(~0u, lc, o); }
        if (tid == 0) { g_klrow[n] = kl; g_loc[n] = lc + bfc[0]; }
    }
}

__global__ void __launch_bounds__(256) bagmax_kernel(const int* __restrict__ bi, const float* __restrict__ lab) {
    __shared__ float sv[8]; __shared__ int si[8]; __shared__ float smx;
    int b = blockIdx.x, tid = threadIdx.x, lane = tid & 31, w = tid >> 5;
    float mx = -3.4e38f;
    for (int n = tid; n < NI; n += 256) if (bi[n] == b) mx = fmaxf(mx, g_loc[n]);
#pragma unroll
    for (int o = 16; o > 0; o >>= 1) mx = fmaxf(mx, __shfl_xor_sync(~0u, mx, o));
    if (lane == 0) sv[w] = mx;
    __syncthreads();
    if (tid == 0) { float v = sv[0]; for (int i = 1; i < 8; i++) v = fmaxf(v, sv[i]); smx = v; }
    __syncthreads();
    float mval = smx; int mn = NI;
    for (int n = tid; n < NI; n += 256) if (bi[n] == b && g_loc[n] == mval) mn = min(mn, n);
#pragma unroll
    for (int o = 16; o > 0; o >>= 1) mn = min(mn, __shfl_xor_sync(~0u, mn, o));
    if (lane == 0) si[w] = mn;
    __syncthreads();
    if (tid == 0) {
        int a = si[0]; for (int i = 1; i < 8; i++) a = min(a, si[i]);
        g_arg[b] = a;
        float M = g_loc[a], y = lab[b];
        g_term[b] = fmaxf(M, 0.f) - M * y + log1pf(expf(-fabsf(M)));
    }
}

__global__ void __launch_bounds__(512) dec1_kernel(const float* __restrict__ D1) {
    __shared__ float zz[32];
    int b = blockIdx.x, tid = threadIdx.x;
    if (tid < 32) zz[tid] = g_z[(size_t)g_arg[b] * 32 + tid];
    __syncthreads();
    float a = 0.f;
#pragma unroll
    for (int ic = 0; ic < 32; ic++) a += zz[ic] * D1[ic * 512 + tid];
    g_t1[b * 512 + tid] = a;
}

__global__ void __launch_bounds__(256) dec2_kernel(const float* __restrict__ D2) {
    __shared__ float at[4096];
    int B0 = blockIdx.x * 8, tid = threadIdx.x;
    for (int i = tid; i < 4096; i += 256) {
        int bl = i >> 9, ic = i & 511;
        at[ic * 8 + bl] = fmaxf((g_t1[(B0 + bl) * 512 + ic] - g_mean[3][ic]) * g_rstd[3][ic], 0.f);
    }
    __syncthreads();
    for (int o = tid; o < 6272; o += 256) {
        float acc[8] = {};
        for (int ic = 0; ic < 512; ic++) {
            float w = D2[(size_t)ic * 6272 + o];
            float4 x0 = *(const float4*)&at[ic * 8], x1 = *(const float4*)&at[ic * 8 + 4];
            acc[0] += x0.x * w; acc[1] += x0.y * w; acc[2] += x0.z * w; acc[3] += x0.w * w;
            acc[4] += x1.x * w; acc[5] += x1.y * w; acc[6] += x1.z * w; acc[7] += x1.w * w;
        }
#pragma unroll
        for (int j = 0; j < 8; j++) g_t2[(size_t)(B0 + j) * 6272 + o] = acc[j];
    }
}

__global__ void __launch_bounds__(256) dec3_kernel(const float* __restrict__ D3) {
    __shared__ float a2[6272], wt[2048];
    int b = blockIdx.x, tid = threadIdx.x;
    for (int i = tid; i < 6272; i += 256) {
        int c = i / 49;
        a2[i] = fmaxf((g_t2[(size_t)b * 6272 + i] - g_mean[4][c]) * g_rstd[4][c], 0.f);
    }
    __syncthreads();
    int oy = tid / 14, ox = tid - (tid / 14) * 14;
    for (int oc = 0; oc < 32; oc++) {
        for (int i = tid; i < 2048; i += 256) wt[i] = D3[(i >> 4) * 512 + oc * 16 + (i & 15)];
        __syncthreads();
        if (tid < 196) {
            float a = 0.f;
#pragma unroll
            for (int ky = 0; ky < 4; ky++) {
                int t = oy + 1 - ky;
                if (t >= 0 && !(t & 1) && (t >> 1) < 7) {
                    int iy = t >> 1;
#pragma unroll
                    for (int kx = 0; kx < 4; kx++) {
                        int u = ox + 1 - kx;
                        if (u >= 0 && !(u & 1) && (u >> 1) < 7) {
                            int sB = iy * 7 + (u >> 1), wB = ky * 4 + kx;
#pragma unroll 16
                            for (int ic = 0; ic < 128; ic++) a += a2[ic * 49 + sB] * wt[ic * 16 + wB];
                        }
                    }
                }
            }
            g_t3[(size_t)b * 6272 + oc * 196 + tid] = a;
        }
        __syncthreads();
    }
}

__global__ void __launch_bounds__(256) dec4_kernel(const float* __restrict__ D4, const float* __restrict__ d4,
                                                   const float* __restrict__ bag) {
    __shared__ float a3[6272], w4s[512];
    int b = blockIdx.x, tid = threadIdx.x;
    for (int i = tid; i < 6272; i += 256) {
        int c = i / 196;
        a3[i] = fmaxf((g_t3[(size_t)b * 6272 + i] - g_mean[5][c]) * g_rstd[5][c], 0.f);
    }
    for (int i = tid; i < 512; i += 256) w4s[i] = D4[i];
    __syncthreads();
    float bias = d4[0]; int arg = g_arg[b];
    float sq = 0.f;
    for (int o = tid; o < 784; o += 256) {
        int oy = o / 28, ox = o - (o / 28) * 28;
        float a = bias;
#pragma unroll
        for (int ky = 0; ky < 4; ky++) {
            int t = oy + 1 - ky;
            if (t >= 0 && !(t & 1) && (t >> 1) < 14) {
                int iy = t >> 1;
#pragma unroll
                for (int kx = 0; kx < 4; kx++) {
                    int u = ox + 1 - kx;
                    if (u >= 0 && !(u & 1) && (u >> 1) < 14) {
                        int sB = iy * 14 + (u >> 1), wB = ky * 4 + kx;
#pragma unroll
                        for (int ic = 0; ic < 32; ic++) a += a3[ic * 196 + sB] * w4s[ic * 16 + wB];
                    }
                }
            }
        }
        float s = 1.f / (1.f + expf(-a));
        float d = s - bag[(size_t)arg * 784 + o];
        sq += d * d;
    }
    float2 r = bsum2(make_float2(sq, 0.f));
    if (tid == 0) g_rec[b] = r.x;
}

__global__ void __launch_bounds__(256) final_kernel(float* __restrict__ out) {
    int tid = threadIdx.x;
    float kl = 0.f;
    for (int n = tid; n < NI; n += 256) kl += g_klrow[n];
    float tm = 0.f, rc = 0.f;
    if (tid < NB) { tm = g_term[tid]; rc = g_rec[tid]; }
    float2 a = bsum2(make_float2(kl, tm));
    __syncthreads();
    float2 bb = bsum2(make_float2(rc, 0.f));
    if (tid == 0) {
        out[0] = bb.x / (256.f * 784.f);
        out[1] = 0.5f * a.x / (16384.f * 32.f);
        out[2] = a.y / 256.f;
    }
}

extern "C" void kernel_launch(void* const* d_in, const int* in_sizes, int n_in,
                              void* d_out, int out_size) {
    const float* bag = (const float*)d_in[0];
    const int* bag_idx = (const int*)d_in[1];
    const float* lab = (const float*)d_in[2];
    const float* eps = (const float*)d_in[3];
    const float* W1 = (const float*)d_in[4];
    const float* W2 = (const float*)d_in[6];
    const float* W3 = (const float*)d_in[8];
    const float* W4 = (const float*)d_in[10];
    const float* b4 = (const float*)d_in[11];
    const float* Wm = (const float*)d_in[12];
    const float* bm = (const float*)d_in[13];
    const float* Wlv = (const float*)d_in[14];
    const float* blv = (const float*)d_in[15];
    const float* Wfc = (const float*)d_in[16];
    const float* bfc = (const float*)d_in[17];
    const float* D1 = (const float*)d_in[18];
    const float* D2 = (const float*)d_in[20];
    const float* D3 = (const float*)d_in[22];
    const float* D4 = (const float*)d_in[24];
    const float* d4 = (const float*)d_in[25];

    float *y1, *y2, *y3, *t1, *t2, *t3;
    cudaGetSymbolAddress((void**)&y1, g_y1);
    cudaGetSymbolAddress((void**)&y2, g_y2);
    cudaGetSymbolAddress((void**)&y3, g_y3);
    cudaGetSymbolAddress((void**)&t1, g_t1);
    cudaGetSymbolAddress((void**)&t2, g_t2);
    cudaGetSymbolAddress((void**)&t3, g_t3);

    prep_kernel<<<12544, 256>>>(W2, W3, Wm, Wlv, W4, b4, bm, blv);   // 0
    conv1_kernel<<<NI, 256>>>(bag, W1);                              // 1
    stats_part<<<dim3(32, 8), 256>>>(y1, 196, NI, 6272, 196, 1);     // 2
    conv2_gemm<<<6272, 256>>>();                                     // 3 (BN1 fin folded)
    stats_part<<<dim3(128, 8), 256>>>(y2, 1, NI * 49, 128, 1, 0);    // 4
    pack2_kernel<<<NI, 256>>>();                                     // 5 (BN2 fin folded)
    conv3_gemm<<<dim3(128, 4), 256>>>();                             // 6
    stats_part<<<dim3(512, 8), 256>>>(y3, 1, NI, 512, 1, 0);         // 7
    stats_fin<<<1, 512>>>(2, 8, NI);                                 // 8
    latent_kernel<<<NI, 64>>>(eps, Wfc, bfc);
    bagmax_kernel<<<NB, 256>>>(bag_idx, lab);
    dec1_kernel<<<NB, 512>>>(D1);
    stats_part<<<dim3(512, 2), 256>>>(t1, 1, NB, 512, 1, 0);
    stats_fin<<<1, 512>>>(3, 2, NB);
    dec2_kernel<<<32, 256>>>(D2);
    stats_part<<<dim3(128, 2), 256>>>(t2, 49, NB, 6272, 49, 1);
    stats_fin<<<1, 128>>>(4, 2, NB * 49);
    dec3_kernel<<<NB, 256>>>(D3);
    stats_part<<<dim3(32, 2), 256>>>(t3, 196, NB, 6272, 196, 1);
    stats_fin<<<1, 32>>>(5, 2, NB * 196);
    dec4_kernel<<<NB, 256>>>(D4, d4, bag);
    final_kernel<<<1, 256>>>((float*)d_out);
}

// round 6
// speedup vs baseline: 1.1252x; 1.0463x over previous
#include <cuda_runtime.h>
#include <math.h>
#include <stdint.h>
#define NI 16384
#define NB 256

__device__ float g_y1[102760448];
__device__ float g_y2[102760448];          // packed raw conv2 out: [n][c*49+p]
__device__ float g_y3[8388608];
__device__ float g_W2t[65536];
__device__ float g_W3t[3211264];
__device__ float g_Wc[32768];
__device__ float g_cb[64];
__device__ float g_mean[6][512], g_rstd[6][512];
__device__ float g_spart[16384];
__device__ float g_z[524288];
__device__ float g_loc[NI];
__device__ float g_klrow[NI];
__device__ int   g_arg[NB];
__device__ float g_term[NB];
__device__ float g_rec[NB];
__device__ float g_t1[131072];
__device__ float g_t2[1605632];
__device__ float g_t3[1605632];

__device__ __forceinline__ float2 bsum2(float2 v) {
    __shared__ float2 sh[32];
    int lane = threadIdx.x & 31, w = threadIdx.x >> 5;
#pragma unroll
    for (int o = 16; o > 0; o >>= 1) { v.x += __shfl_xor_sync(~0u, v.x, o); v.y += __shfl_xor_sync(~0u, v.y, o); }
    __syncthreads();
    if (lane == 0) sh[w] = v;
    __syncthreads();
    int nw = (blockDim.x + 31) >> 5;
    if (w == 0) {
        v = (lane < nw) ? sh[lane] : make_float2(0.f, 0.f);
#pragma unroll
        for (int o = 16; o > 0; o >>= 1) { v.x += __shfl_xor_sync(~0u, v.x, o); v.y += __shfl_xor_sync(~0u, v.y, o); }
    }
    return v;
}

__global__ void prep_kernel(const float* W2, const float* W3, const float* Wm, const float* Wlv,
                            const float* W4, const float* b4, const float* bm, const float* blv) {
    int i = blockIdx.x * 256 + threadIdx.x;
    if (i < 65536) g_W2t[i] = W2[(i & 127) * 512 + (i >> 7)];
    for (int j = i; j < 3211264; j += 12544 * 256)
        g_W3t[j] = W3[(size_t)(j & 511) * 6272 + (j >> 9)];
    if (i < 32768) {
        int ic = i >> 6, r = i & 63;
        const float* row = (r < 32) ? (Wm + r * 200) : (Wlv + (r - 32) * 200);
        float s = 0.f;
        for (int j = 0; j < 200; j++) s += row[j] * W4[j * 512 + ic];
        g_Wc[ic * 64 + r] = s;
        if (ic == 0) {
            float cb = (r < 32) ? bm[r] : blv[r - 32];
            for (int j = 0; j < 200; j++) cb += row[j] * b4[j];
            g_cb[r] = cb;
        }
    }
}

__global__ void __launch_bounds__(256) conv1_kernel(const float* __restrict__ bag, const float* __restrict__ W1) {
    __shared__ float xs[784], ws[512];
    int n = blockIdx.x, tid = threadIdx.x;
    for (int i = tid; i < 784; i += 256) xs[i] = bag[(size_t)n * 784 + i];
    for (int i = tid; i < 512; i += 256) ws[i] = W1[i];
    __syncthreads();
    int oc = tid >> 3, sub = tid & 7;
    float w[16];
#pragma unroll
    for (int t = 0; t < 16; t++) w[t] = ws[oc * 16 + t];
    for (int p = sub; p < 196; p += 8) {
        int oy = p / 14, ox = p - (p / 14) * 14;
        float a = 0.f;
#pragma unroll
        for (int ky = 0; ky < 4; ky++) {
            int iy = 2 * oy - 1 + ky;
            if ((unsigned)iy < 28u)
#pragma unroll
                for (int kx = 0; kx < 4; kx++) {
                    int ix = 2 * ox - 1 + kx;
                    if ((unsigned)ix < 28u) a += xs[iy * 28 + ix] * w[ky * 4 + kx];
                }
        }
        g_y1[(size_t)n * 6272 + oc * 196 + p] = a;
    }
}

__global__ void __launch_bounds__(256) stats_part(const float* __restrict__ src, int HW, int Nn, int sN, int sC, int sI) {
    int c = blockIdx.x, p = blockIdx.y, P = gridDim.y, tid = threadIdx.x;
    int total = Nn * HW;
    float s = 0.f, q = 0.f;
    for (int j = p * 256 + tid; j < total; j += P * 256) {
        int n = j / HW, i = j - n * HW;
        float v = src[(size_t)n * sN + (size_t)c * sC + (size_t)i * sI];
        s += v; q += v * v;
    }
    float2 r = bsum2(make_float2(s, q));
    if (tid == 0) { g_spart[(c * P + p) * 2] = r.x; g_spart[(c * P + p) * 2 + 1] = r.y; }
}

__global__ void stats_fin(int id, int P, int count) {
    int c = threadIdx.x;
    float s = 0.f, q = 0.f;
    for (int p = 0; p < P; p++) { s += g_spart[(c * P + p) * 2]; q += g_spart[(c * P + p) * 2 + 1]; }
    float m = s / count;
    g_mean[id][c] = m;
    g_rstd[id][c] = rsqrtf(q / count - m * m + 1e-5f);
}

// conv2 implicit-im2col GEMM, M=802816 N=128 K=512. KT=16 (one ic), double-buffered.
// BN1 finalize folded in; epilogue smem-transposes and stores packed [n][oc*49+p].
__global__ void __launch_bounds__(256) conv2_gemm() {
    __shared__ float As[2][16][132], Bs[2][16][132];
    __shared__ float sm[32], sr[32];
    int tid = threadIdx.x;
    if (tid < 32) {
        float s = 0.f, q = 0.f;
#pragma unroll
        for (int p = 0; p < 8; p++) { s += g_spart[(tid * 8 + p) * 2]; q += g_spart[(tid * 8 + p) * 2 + 1]; }
        float cnt = (float)NI * 196.f, m = s / cnt;
        sm[tid] = m; sr[tid] = rsqrtf(q / cnt - m * m + 1e-5f);
    }
    int M0 = blockIdx.x * 128;
    int aoff[8]; unsigned aval = 0;
#pragma unroll
    for (int q = 0; q < 8; q++) {
        int idx = q * 256 + tid, kk = idx >> 7, mm = idx & 127;
        int m = M0 + mm, n = m / 49, p = m - n * 49;
        int oy = p / 7, ox = p - (p / 7) * 7;
        int iy = 2 * oy - 1 + (kk >> 2), ix = 2 * ox - 1 + (kk & 3);
        if (iy >= 0 && iy < 14 && ix >= 0 && ix < 14) aval |= 1u << q;
        aoff[q] = n * 6272 + iy * 14 + ix;
    }
    __syncthreads();
    // prologue ic=0
    {
        float mc = sm[0], rc = sr[0];
#pragma unroll
        for (int q = 0; q < 8; q++) {
            int idx = q * 256 + tid, kk = idx >> 7, mm = idx & 127;
            float v = 0.f;
            if (aval & (1u << q)) v = fmaxf((g_y1[aoff[q]] - mc) * rc, 0.f);
            As[0][kk][mm] = v;
            Bs[0][kk][mm] = g_W2t[kk * 128 + mm];
        }
    }
    __syncthreads();
    float acc[8][8] = {};
    int ty = tid >> 4, tx = tid & 15;
    for (int ic = 0; ic < 32; ic++) {
        int cur = ic & 1, nxt = cur ^ 1;
        if (ic < 31) {
            float mc = sm[ic + 1], rc = sr[ic + 1];
            int base = (ic + 1) * 196, k0 = (ic + 1) * 16;
#pragma unroll
            for (int q = 0; q < 8; q++) {
                int idx = q * 256 + tid, kk = idx >> 7, mm = idx & 127;
                float v = 0.f;
                if (aval & (1u << q)) v = fmaxf((g_y1[aoff[q] + base] - mc) * rc, 0.f);
                As[nxt][kk][mm] = v;
                Bs[nxt][kk][mm] = g_W2t[(k0 + kk) * 128 + mm];
            }
        }
#pragma unroll
        for (int k = 0; k < 16; k++) {
            float4 a0 = *(const float4*)&As[cur][k][ty * 8], a1 = *(const float4*)&As[cur][k][ty * 8 + 4];
            float4 b0 = *(const float4*)&Bs[cur][k][tx * 8], b1 = *(const float4*)&Bs[cur][k][tx * 8 + 4];
            float av[8] = {a0.x, a0.y, a0.z, a0.w, a1.x, a1.y, a1.z, a1.w};
            float bv[8] = {b0.x, b0.y, b0.z, b0.w, b1.x, b1.y, b1.z, b1.w};
#pragma unroll
            for (int i = 0; i < 8; i++)
#pragma unroll
                for (int j = 0; j < 8; j++) acc[i][j] += av[i] * bv[j];
        }
        __syncthreads();
    }
    // epilogue: transpose 128x128 tile via smem (4 chunks of 32 oc), store packed
    float* tr = &As[0][0][0];   // 2*16*132 = 4224 = 128*33 floats
#pragma unroll
    for (int ch = 0; ch < 4; ch++) {
        if ((tx >> 2) == ch) {
#pragma unroll
            for (int i = 0; i < 8; i++)
#pragma unroll
                for (int j = 0; j < 8; j++)
                    tr[(ty * 8 + i) * 33 + (tx & 3) * 8 + j] = acc[i][j];
        }
        __syncthreads();
        for (int t = tid; t < 4096; t += 256) {
            int row = t & 127, ocl = t >> 7;
            int m = M0 + row, n = m / 49, p = m - n * 49;
            g_y2[(size_t)n * 6272 + (ch * 32 + ocl) * 49 + p] = tr[row * 33 + ocl];
        }
        __syncthreads();
    }
}

// conv3 GEMM, M=16384 N=512 K=6272. KT=16 double-buffered; BN2+ReLU fused into A loader.
__global__ void __launch_bounds__(256) conv3_gemm() {
    __shared__ float As[2][16][132], Bs[2][16][132];
    __shared__ float m2s[128], r2s[128];
    int tid = threadIdx.x;
    if (tid < 128) {
        float s = 0.f, q = 0.f;
#pragma unroll
        for (int p = 0; p < 8; p++) { s += g_spart[(tid * 8 + p) * 2]; q += g_spart[(tid * 8 + p) * 2 + 1]; }
        float cnt = (float)NI * 49.f, m = s / cnt;
        m2s[tid] = m; r2s[tid] = rsqrtf(q / cnt - m * m + 1e-5f);
    }
    int M0 = blockIdx.x * 128, N0 = blockIdx.y * 128;
    __syncthreads();
    // prologue k0=0
#pragma unroll
    for (int q = 0; q < 2; q++) {
        int fidx = q * 256 + tid, mm = fidx >> 2, kq = (fidx & 3) * 4;
        float4 v = *(const float4*)&g_y2[(size_t)(M0 + mm) * 6272 + kq];
        As[0][kq + 0][mm] = fmaxf((v.x - m2s[(kq + 0) / 49]) * r2s[(kq + 0) / 49], 0.f);
        As[0][kq + 1][mm] = fmaxf((v.y - m2s[(kq + 1) / 49]) * r2s[(kq + 1) / 49], 0.f);
        As[0][kq + 2][mm] = fmaxf((v.z - m2s[(kq + 2) / 49]) * r2s[(kq + 2) / 49], 0.f);
        As[0][kq + 3][mm] = fmaxf((v.w - m2s[(kq + 3) / 49]) * r2s[(kq + 3) / 49], 0.f);
    }
#pragma unroll
    for (int q = 0; q < 8; q++) {
        int idx = q * 256 + tid;
        Bs[0][idx >> 7][idx & 127] = g_W3t[(size_t)(idx >> 7) * 512 + N0 + (idx & 127)];
    }
    __syncthreads();
    float acc[8][8] = {};
    int ty = tid >> 4, tx = tid & 15;
    for (int kt = 0; kt < 392; kt++) {
        int cur = kt & 1, nxt = cur ^ 1;
        if (kt < 391) {
            int k0 = (kt + 1) * 16;
#pragma unroll
            for (int q = 0; q < 2; q++) {
                int fidx = q * 256 + tid, mm = fidx >> 2, kq = (fidx & 3) * 4;
                float4 v = *(const float4*)&g_y2[(size_t)(M0 + mm) * 6272 + k0 + kq];
                int c0 = (k0 + kq) / 49, c1 = (k0 + kq + 1) / 49, c2 = (k0 + kq + 2) / 49, c3 = (k0 + kq + 3) / 49;
                As[nxt][kq + 0][mm] = fmaxf((v.x - m2s[c0]) * r2s[c0], 0.f);
                As[nxt][kq + 1][mm] = fmaxf((v.y - m2s[c1]) * r2s[c1], 0.f);
                As[nxt][kq + 2][mm] = fmaxf((v.z - m2s[c2]) * r2s[c2], 0.f);
                As[nxt][kq + 3][mm] = fmaxf((v.w - m2s[c3]) * r2s[c3], 0.f);
            }
#pragma unroll
            for (int q = 0; q < 8; q++) {
                int idx = q * 256 + tid;
                Bs[nxt][idx >> 7][idx & 127] = g_W3t[(size_t)(k0 + (idx >> 7)) * 512 + N0 + (idx & 127)];
            }
        }
#pragma unroll
        for (int k = 0; k < 16; k++) {
            float4 a0 = *(const float4*)&As[cur][k][ty * 8], a1 = *(const float4*)&As[cur][k][ty * 8 + 4];
            float4 b0 = *(const float4*)&Bs[cur][k][tx * 8], b1 = *(const float4*)&Bs[cur][k][tx * 8 + 4];
            float av[8] = {a0.x, a0.y, a0.z, a0.w, a1.x, a1.y, a1.z, a1.w};
            float bv[8] = {b0.x, b0.y, b0.z, b0.w, b1.x, b1.y, b1.z, b1.w};
#pragma unroll
            for (int i = 0; i < 8; i++)
#pragma unroll
                for (int j = 0; j < 8; j++) acc[i][j] += av[i] * bv[j];
        }
        __syncthreads();
    }
#pragma unroll
    for (int i = 0; i < 8; i++) {
        float* d = &g_y3[(size_t)(M0 + ty * 8 + i) * 512 + N0 + tx * 8];
        *(float4*)d = make_float4(acc[i][0], acc[i][1], acc[i][2], acc[i][3]);
        *(float4*)(d + 4) = make_float4(acc[i][4], acc[i][5], acc[i][6], acc[i][7]);
    }
}

__global__ void __launch_bounds__(64) latent_kernel(const float* __restrict__ eps, const float* __restrict__ Wfc,
                                                    const float* __restrict__ bfc) {
    __shared__ float sa[512], smu[32], slv[32];
    int n = blockIdx.x, tid = threadIdx.x;
    for (int i = tid; i < 512; i += 64)
        sa[i] = fmaxf((g_y3[(size_t)n * 512 + i] - g_mean[2][i]) * g_rstd[2][i], 0.f);
    __syncthreads();
    float dot = g_cb[tid];
#pragma unroll 8
    for (int ic = 0; ic < 512; ic++) dot += sa[ic] * g_Wc[ic * 64 + tid];
    if (tid < 32) smu[tid] = dot; else slv[tid - 32] = dot;
    __syncthreads();
    if (tid < 32) {
        float mu = smu[tid], lv = slv[tid], sd = expf(0.5f * lv);
        float z = mu + sd * eps[(size_t)n * 32 + tid];
        g_z[(size_t)n * 32 + tid] = z;
        float kl = mu * mu + sd * sd - lv - 1.f;
        float lc = z * Wfc[tid];
#pragma unroll
        for (int o = 16; o > 0; o >>= 1) { kl += __shfl_xor_sync(~0u, kl, o); lc += __shfl_xor_sync(~0u, lc, o); }
        if (tid == 0) { g_klrow[n] = kl; g_loc[n] = lc + bfc[0]; }
    }
}

__global__ void __launch_bounds__(256) bagmax_kernel(const int* __restrict__ bi, const float* __restrict__ lab) {
    __shared__ float sv[8]; __shared__ int si[8]; __shared__ float smx;
    int b = blockIdx.x, tid = threadIdx.x, lane = tid & 31, w = tid >> 5;
    float mx = -3.4e38f;
    for (int n = tid; n < NI; n += 256) if (bi[n] == b) mx = fmaxf(mx, g_loc[n]);
#pragma unroll
    for (int o = 16; o > 0; o >>= 1) mx = fmaxf(mx, __shfl_xor_sync(~0u, mx, o));
    if (lane == 0) sv[w] = mx;
    __syncthreads();
    if (tid == 0) { float v = sv[0]; for (int i = 1; i < 8; i++) v = fmaxf(v, sv[i]); smx = v; }
    __syncthreads();
    float mval = smx; int mn = NI;
    for (int n = tid; n < NI; n += 256) if (bi[n] == b && g_loc[n] == mval) mn = min(mn, n);
#pragma unroll
    for (int o = 16; o > 0; o >>= 1) mn = min(mn, __shfl_xor_sync(~0u, mn, o));
    if (lane == 0) si[w] = mn;
    __syncthreads();
    if (tid == 0) {
        int a = si[0]; for (int i = 1; i < 8; i++) a = min(a, si[i]);
        g_arg[b] = a;
        float M = g_loc[a], y = lab[b];
        g_term[b] = fmaxf(M, 0.f) - M * y + log1pf(expf(-fabsf(M)));
    }
}

__global__ void __launch_bounds__(512) dec1_kernel(const float* __restrict__ D1) {
    __shared__ float zz[32];
    int b = blockIdx.x, tid = threadIdx.x;
    if (tid < 32) zz[tid] = g_z[(size_t)g_arg[b] * 32 + tid];
    __syncthreads();
    float a = 0.f;
#pragma unroll
    for (int ic = 0; ic < 32; ic++) a += zz[ic] * D1[ic * 512 + tid];
    g_t1[b * 512 + tid] = a;
}

__global__ void __launch_bounds__(256) dec2_kernel(const float* __restrict__ D2) {
    __shared__ float at[4096];
    int B0 = blockIdx.x * 8, tid = threadIdx.x;
    for (int i = tid; i < 4096; i += 256) {
        int bl = i >> 9, ic = i & 511;
        at[ic * 8 + bl] = fmaxf((g_t1[(B0 + bl) * 512 + ic] - g_mean[3][ic]) * g_rstd[3][ic], 0.f);
    }
    __syncthreads();
    for (int o = tid; o < 6272; o += 256) {
        float acc[8] = {};
        for (int ic = 0; ic < 512; ic++) {
            float w = D2[(size_t)ic * 6272 + o];
            float4 x0 = *(const float4*)&at[ic * 8], x1 = *(const float4*)&at[ic * 8 + 4];
            acc[0] += x0.x * w; acc[1] += x0.y * w; acc[2] += x0.z * w; acc[3] += x0.w * w;
            acc[4] += x1.x * w; acc[5] += x1.y * w; acc[6] += x1.z * w; acc[7] += x1.w * w;
        }
#pragma unroll
        for (int j = 0; j < 8; j++) g_t2[(size_t)(B0 + j) * 6272 + o] = acc[j];
    }
}

__global__ void __launch_bounds__(256) dec3_kernel(const float* __restrict__ D3) {
    __shared__ float a2[6272], wt[2048];
    int b = blockIdx.x, tid = threadIdx.x;
    for (int i = tid; i < 6272; i += 256) {
        int c = i / 49;
        a2[i] = fmaxf((g_t2[(size_t)b * 6272 + i] - g_mean[4][c]) * g_rstd[4][c], 0.f);
    }
    __syncthreads();
    int oy = tid / 14, ox = tid - (tid / 14) * 14;
    for (int oc = 0; oc < 32; oc++) {
        for (int i = tid; i < 2048; i += 256) wt[i] = D3[(i >> 4) * 512 + oc * 16 + (i & 15)];
        __syncthreads();
        if (tid < 196) {
            float a = 0.f;
#pragma unroll
            for (int ky = 0; ky < 4; ky++) {
                int t = oy + 1 - ky;
                if (t >= 0 && !(t & 1) && (t >> 1) < 7) {
                    int iy = t >> 1;
#pragma unroll
                    for (int kx = 0; kx < 4; kx++) {
                        int u = ox + 1 - kx;
                        if (u >= 0 && !(u & 1) && (u >> 1) < 7) {
                            int sB = iy * 7 + (u >> 1), wB = ky * 4 + kx;
#pragma unroll 16
                            for (int ic = 0; ic < 128; ic++) a += a2[ic * 49 + sB] * wt[ic * 16 + wB];
                        }
                    }
                }
            }
            g_t3[(size_t)b * 6272 + oc * 196 + tid] = a;
        }
        __syncthreads();
    }
}

__global__ void __launch_bounds__(256) dec4_kernel(const float* __restrict__ D4, const float* __restrict__ d4,
                                                   const float* __restrict__ bag) {
    __shared__ float a3[6272], w4s[512];
    int b = blockIdx.x, tid = threadIdx.x;
    for (int i = tid; i < 6272; i += 256) {
        int c = i / 196;
        a3[i] = fmaxf((g_t3[(size_t)b * 6272 + i] - g_mean[5][c]) * g_rstd[5][c], 0.f);
    }
    for (int i = tid; i < 512; i += 256) w4s[i] = D4[i];
    __syncthreads();
    float bias = d4[0]; int arg = g_arg[b];
    float sq = 0.f;
    for (int o = tid; o < 784; o += 256) {
        int oy = o / 28, ox = o - (o / 28) * 28;
        float a = bias;
#pragma unroll
        for (int ky = 0; ky < 4; ky++) {
            int t = oy + 1 - ky;
            if (t >= 0 && !(t & 1) && (t >> 1) < 14) {
                int iy = t >> 1;
#pragma unroll
                for (int kx = 0; kx < 4; kx++) {
                    int u = ox + 1 - kx;
                    if (u >= 0 && !(u & 1) && (u >> 1) < 14) {
                        int sB = iy * 14 + (u >> 1), wB = ky * 4 + kx;
#pragma unroll
                        for (int ic = 0; ic < 32; ic++) a += a3[ic * 196 + sB] * w4s[ic * 16 + wB];
                    }
                }
            }
        }
        float s = 1.f / (1.f + expf(-a));
        float d = s - bag[(size_t)arg * 784 + o];
        sq += d * d;
    }
    float2 r = bsum2(make_float2(sq, 0.f));
    if (tid == 0) g_rec[b] = r.x;
}

__global__ void __launch_bounds__(256) final_kernel(float* __restrict__ out) {
    int tid = threadIdx.x;
    float kl = 0.f;
    for (int n = tid; n < NI; n += 256) kl += g_klrow[n];
    float tm = 0.f, rc = 0.f;
    if (tid < NB) { tm = g_term[tid]; rc = g_rec[tid]; }
    float2 a = bsum2(make_float2(kl, tm));
    __syncthreads();
    float2 bb = bsum2(make_float2(rc, 0.f));
    if (tid == 0) {
        out[0] = bb.x / (256.f * 784.f);
        out[1] = 0.5f * a.x / (16384.f * 32.f);
        out[2] = a.y / 256.f;
    }
}

extern "C" void kernel_launch(void* const* d_in, const int* in_sizes, int n_in,
                              void* d_out, int out_size) {
    const float* bag = (const float*)d_in[0];
    const int* bag_idx = (const int*)d_in[1];
    const float* lab = (const float*)d_in[2];
    const float* eps = (const float*)d_in[3];
    const float* W1 = (const float*)d_in[4];
    const float* W2 = (const float*)d_in[6];
    const float* W3 = (const float*)d_in[8];
    const float* W4 = (const float*)d_in[10];
    const float* b4 = (const float*)d_in[11];
    const float* Wm = (const float*)d_in[12];
    const float* bm = (const float*)d_in[13];
    const float* Wlv = (const float*)d_in[14];
    const float* blv = (const float*)d_in[15];
    const float* Wfc = (const float*)d_in[16];
    const float* bfc = (const float*)d_in[17];
    const float* D1 = (const float*)d_in[18];
    const float* D2 = (const float*)d_in[20];
    const float* D3 = (const float*)d_in[22];
    const float* D4 = (const float*)d_in[24];
    const float* d4 = (const float*)d_in[25];

    float *y1, *y2, *y3, *t1, *t2, *t3;
    cudaGetSymbolAddress((void**)&y1, g_y1);
    cudaGetSymbolAddress((void**)&y2, g_y2);
    cudaGetSymbolAddress((void**)&y3, g_y3);
    cudaGetSymbolAddress((void**)&t1, g_t1);
    cudaGetSymbolAddress((void**)&t2, g_t2);
    cudaGetSymbolAddress((void**)&t3, g_t3);

    prep_kernel<<<12544, 256>>>(W2, W3, Wm, Wlv, W4, b4, bm, blv);   // 0
    conv1_kernel<<<NI, 256>>>(bag, W1);                              // 1
    stats_part<<<dim3(32, 8), 256>>>(y1, 196, NI, 6272, 196, 1);     // 2
    conv2_gemm<<<6272, 256>>>();                                     // 3 (BN1 fin folded, packed store)
    stats_part<<<dim3(128, 8), 256>>>(y2, 49, NI, 6272, 49, 1);      // 4 (packed layout)
    conv3_gemm<<<dim3(128, 4), 256>>>();                             // 5 (BN2 fin + ReLU folded)
    stats_part<<<dim3(512, 8), 256>>>(y3, 1, NI, 512, 1, 0);         // 6
    stats_fin<<<1, 512>>>(2, 8, NI);                                 // 7
    latent_kernel<<<NI, 64>>>(eps, Wfc, bfc);
    bagmax_kernel<<<NB, 256>>>(bag_idx, lab);
    dec1_kernel<<<NB, 512>>>(D1);
    stats_part<<<dim3(512, 2), 256>>>(t1, 1, NB, 512, 1, 0);
    stats_fin<<<1, 512>>>(3, 2, NB);
    dec2_kernel<<<32, 256>>>(D2);
    stats_part<<<dim3(128, 2), 256>>>(t2, 49, NB, 6272, 49, 1);
    stats_fin<<<1, 128>>>(4, 2, NB * 49);
    dec3_kernel<<<NB, 256>>>(D3);
    stats_part<<<dim3(32, 2), 256>>>(t3, 196, NB, 6272, 196, 1);
    stats_fin<<<1, 32>>>(5, 2, NB * 196);
    dec4_kernel<<<NB, 256>>>(D4, d4, bag);
    final_kernel<<<1, 256>>>((float*)d_out);
}

// round 9
// speedup vs baseline: 1.3472x; 1.1972x over previous
#include <cuda_runtime.h>
#include <cuda_bf16.h>
#include <math.h>
#include <stdint.h>
#define NI 16384
#define NB 256

__device__ float g_y1[102760448];
__device__ float g_y2[102760448];          // packed raw conv2 out: [n][c*49+p]
__device__ float g_y3[8388608];
__device__ float g_W2t[65536];
__device__ __nv_bfloat16 g_W3h[3211264], g_W3l[3211264];
__device__ float g_Wc[32768];
__device__ float g_cb[64];
__device__ float g_mean[6][512], g_rstd[6][512];
__device__ float g_spart[16384];
__device__ float g_z[524288];
__device__ float g_loc[NI];
__device__ float g_klrow[NI];
__device__ int   g_arg[NB];
__device__ float g_term[NB];
__device__ float g_rec[NB];
__device__ float g_t1[131072];
__device__ float g_t2[1605632];
__device__ float g_t3[1605632];

__device__ __forceinline__ uint32_t smem_u32(const void* p) {
    uint32_t a;
    asm("{ .reg .u64 t; cvta.to.shared.u64 t, %1; cvt.u32.u64 %0, t; }" : "=r"(a) : "l"(p));
    return a;
}
__device__ __forceinline__ void ldsm4(uint32_t* r, uint32_t addr) {
    asm volatile("ldmatrix.sync.aligned.m8n8.x4.shared.b16 {%0,%1,%2,%3}, [%4];"
        : "=r"(r[0]), "=r"(r[1]), "=r"(r[2]), "=r"(r[3]) : "r"(addr));
}
__device__ __forceinline__ void mma_bf16(float* c, const uint32_t* a, const uint32_t* b) {
    asm volatile("mma.sync.aligned.m16n8k16.row.col.f32.bf16.bf16.f32 "
        "{%0,%1,%2,%3}, {%4,%5,%6,%7}, {%8,%9}, {%0,%1,%2,%3};"
        : "+f"(c[0]), "+f"(c[1]), "+f"(c[2]), "+f"(c[3])
        : "r"(a[0]), "r"(a[1]), "r"(a[2]), "r"(a[3]), "r"(b[0]), "r"(b[1]));
}

__device__ __forceinline__ float2 bsum2(float2 v) {
    __shared__ float2 sh[32];
    int lane = threadIdx.x & 31, w = threadIdx.x >> 5;
#pragma unroll
    for (int o = 16; o > 0; o >>= 1) { v.x += __shfl_xor_sync(~0u, v.x, o); v.y += __shfl_xor_sync(~0u, v.y, o); }
    __syncthreads();
    if (lane == 0) sh[w] = v;
    __syncthreads();
    int nw = (blockDim.x + 31) >> 5;
    if (w == 0) {
        v = (lane < nw) ? sh[lane] : make_float2(0.f, 0.f);
#pragma unroll
        for (int o = 16; o > 0; o >>= 1) { v.x += __shfl_xor_sync(~0u, v.x, o); v.y += __shfl_xor_sync(~0u, v.y, o); }
    }
    return v;
}

__global__ void prep_kernel(const float* W2, const float* W3, const float* Wm, const float* Wlv,
                            const float* W4, const float* b4, const float* bm, const float* blv) {
    int i = blockIdx.x * 256 + threadIdx.x;
    if (i < 65536) g_W2t[i] = W2[(i & 127) * 512 + (i >> 7)];
    if (i < 3211264) {
        float w = W3[i];
        __nv_bfloat16 h = __float2bfloat16(w);
        g_W3h[i] = h;
        g_W3l[i] = __float2bfloat16(w - __bfloat162float(h));
    }
    if (i < 32768) {
        int ic = i >> 6, r = i & 63;
        const float* row = (r < 32) ? (Wm + r * 200) : (Wlv + (r - 32) * 200);
        float s = 0.f;
        for (int j = 0; j < 200; j++) s += row[j] * W4[j * 512 + ic];
        g_Wc[ic * 64 + r] = s;
        if (ic == 0) {
            float cb = (r < 32) ? bm[r] : blv[r - 32];
            for (int j = 0; j < 200; j++) cb += row[j] * b4[j];
            g_cb[r] = cb;
        }
    }
}

__global__ void __launch_bounds__(256) conv1_kernel(const float* __restrict__ bag, const float* __restrict__ W1) {
    __shared__ float xs[784], ws[512];
    int n = blockIdx.x, tid = threadIdx.x;
    for (int i = tid; i < 784; i += 256) xs[i] = bag[(size_t)n * 784 + i];
    for (int i = tid; i < 512; i += 256) ws[i] = W1[i];
    __syncthreads();
    int oc = tid >> 3, sub = tid & 7;
    float w[16];
#pragma unroll
    for (int t = 0; t < 16; t++) w[t] = ws[oc * 16 + t];
    for (int p = sub; p < 196; p += 8) {
        int oy = p / 14, ox = p - (p / 14) * 14;
        float a = 0.f;
#pragma unroll
        for (int ky = 0; ky < 4; ky++) {
            int iy = 2 * oy - 1 + ky;
            if ((unsigned)iy < 28u)
#pragma unroll
                for (int kx = 0; kx < 4; kx++) {
                    int ix = 2 * ox - 1 + kx;
                    if ((unsigned)ix < 28u) a += xs[iy * 28 + ix] * w[ky * 4 + kx];
                }
        }
        g_y1[(size_t)n * 6272 + oc * 196 + p] = a;
    }
}

__global__ void __launch_bounds__(256) stats_part(const float* __restrict__ src, int HW, int Nn, int sN, int sC, int sI) {
    int c = blockIdx.x, p = blockIdx.y, P = gridDim.y, tid = threadIdx.x;
    int total = Nn * HW;
    float s = 0.f, q = 0.f;
    for (int j = p * 256 + tid; j < total; j += P * 256) {
        int n = j / HW, i = j - n * HW;
        float v = src[(size_t)n * sN + (size_t)c * sC + (size_t)i * sI];
        s += v; q += v * v;
    }
    float2 r = bsum2(make_float2(s, q));
    if (tid == 0) { g_spart[(c * P + p) * 2] = r.x; g_spart[(c * P + p) * 2 + 1] = r.y; }
}

__global__ void stats_fin(int id, int P, int count) {
    int c = threadIdx.x;
    float s = 0.f, q = 0.f;
    for (int p = 0; p < P; p++) { s += g_spart[(c * P + p) * 2]; q += g_spart[(c * P + p) * 2 + 1]; }
    float m = s / count;
    g_mean[id][c] = m;
    g_rstd[id][c] = rsqrtf(q / count - m * m + 1e-5f);
}

// conv2 implicit-im2col GEMM (unchanged)
__global__ void __launch_bounds__(256) conv2_gemm() {
    __shared__ float As[2][16][132], Bs[2][16][132];
    __shared__ float sm[32], sr[32];
    int tid = threadIdx.x;
    if (tid < 32) {
        float s = 0.f, q = 0.f;
#pragma unroll
        for (int p = 0; p < 8; p++) { s += g_spart[(tid * 8 + p) * 2]; q += g_spart[(tid * 8 + p) * 2 + 1]; }
        float cnt = (float)NI * 196.f, m = s / cnt;
        sm[tid] = m; sr[tid] = rsqrtf(q / cnt - m * m + 1e-5f);
    }
    int M0 = blockIdx.x * 128;
    int aoff[8]; unsigned aval = 0;
#pragma unroll
    for (int q = 0; q < 8; q++) {
        int idx = q * 256 + tid, kk = idx >> 7, mm = idx & 127;
        int m = M0 + mm, n = m / 49, p = m - n * 49;
        int oy = p / 7, ox = p - (p / 7) * 7;
        int iy = 2 * oy - 1 + (kk >> 2), ix = 2 * ox - 1 + (kk & 3);
        if (iy >= 0 && iy < 14 && ix >= 0 && ix < 14) aval |= 1u << q;
        aoff[q] = n * 6272 + iy * 14 + ix;
    }
    __syncthreads();
    {
        float mc = sm[0], rc = sr[0];
#pragma unroll
        for (int q = 0; q < 8; q++) {
            int idx = q * 256 + tid, kk = idx >> 7, mm = idx & 127;
            float v = 0.f;
            if (aval & (1u << q)) v = fmaxf((g_y1[aoff[q]] - mc) * rc, 0.f);
            As[0][kk][mm] = v;
            Bs[0][kk][mm] = g_W2t[kk * 128 + mm];
        }
    }
    __syncthreads();
    float acc[8][8] = {};
    int ty = tid >> 4, tx = tid & 15;
    for (int ic = 0; ic < 32; ic++) {
        int cur = ic & 1, nxt = cur ^ 1;
        if (ic < 31) {
            float mc = sm[ic + 1], rc = sr[ic + 1];
            int base = (ic + 1) * 196, k0 = (ic + 1) * 16;
#pragma unroll
            for (int q = 0; q < 8; q++) {
                int idx = q * 256 + tid, kk = idx >> 7, mm = idx & 127;
                float v = 0.f;
                if (aval & (1u << q)) v = fmaxf((g_y1[aoff[q] + base] - mc) * rc, 0.f);
                As[nxt][kk][mm] = v;
                Bs[nxt][kk][mm] = g_W2t[(k0 + kk) * 128 + mm];
            }
        }
#pragma unroll
        for (int k = 0; k < 16; k++) {
            float4 a0 = *(const float4*)&As[cur][k][ty * 8], a1 = *(const float4*)&As[cur][k][ty * 8 + 4];
            float4 b0 = *(const float4*)&Bs[cur][k][tx * 8], b1 = *(const float4*)&Bs[cur][k][tx * 8 + 4];
            float av[8] = {a0.x, a0.y, a0.z, a0.w, a1.x, a1.y, a1.z, a1.w};
            float bv[8] = {b0.x, b0.y, b0.z, b0.w, b1.x, b1.y, b1.z, b1.w};
#pragma unroll
            for (int i = 0; i < 8; i++)
#pragma unroll
                for (int j = 0; j < 8; j++) acc[i][j] += av[i] * bv[j];
        }
        __syncthreads();
    }
    float* tr = &As[0][0][0];
#pragma unroll
    for (int ch = 0; ch < 4; ch++) {
        if ((tx >> 2) == ch) {
#pragma unroll
            for (int i = 0; i < 8; i++)
#pragma unroll
                for (int j = 0; j < 8; j++)
                    tr[(ty * 8 + i) * 33 + (tx & 3) * 8 + j] = acc[i][j];
        }
        __syncthreads();
        for (int t = tid; t < 4096; t += 256) {
            int row = t & 127, ocl = t >> 7;
            int m = M0 + row, n = m / 49, p = m - n * 49;
            g_y2[(size_t)n * 6272 + (ch * 32 + ocl) * 49 + p] = tr[row * 33 + ocl];
        }
        __syncthreads();
    }
}

// ---------------- conv3 via mma.sync bf16 (h+l split, 3 products) ----------------
#define C3_STRIDE 80
#define C3_BUF 10240
#define C3_AH 0
#define C3_AL 20480
#define C3_BH 40960
#define C3_BL 61440
#define C3_SMEM 81920

__global__ void __launch_bounds__(256) conv3_mma() {
    extern __shared__ char dsm[];
    __shared__ float m2s[128], r2s[128];
    uint32_t sb = smem_u32(dsm);
    int tid = threadIdx.x, lane = tid & 31, wid = tid >> 5;
    int wm = wid >> 2, wn = wid & 3;
    if (tid < 128) {
        float s = 0.f, q = 0.f;
#pragma unroll
        for (int p = 0; p < 8; p++) { s += g_spart[(tid * 8 + p) * 2]; q += g_spart[(tid * 8 + p) * 2 + 1]; }
        float cnt = (float)NI * 49.f, m = s / cnt;
        m2s[tid] = m; r2s[tid] = rsqrtf(q / cnt - m * m + 1e-5f);
    }
    __syncthreads();
    int M0 = blockIdx.x * 128, N0 = blockIdx.y * 128;

#define LOADC(buf, k0) do { \
    _Pragma("unroll") \
    for (int q = 0; q < 4; q++) { \
        int f = q * 256 + tid; \
        int row = f >> 3, c4 = (f & 7) << 2; \
        float4 v = *(const float4*)&g_y2[(size_t)(M0 + row) * 6272 + (k0) + c4]; \
        float xx[4] = {v.x, v.y, v.z, v.w}; \
        unsigned short hs[4], ls[4]; \
        _Pragma("unroll") \
        for (int j = 0; j < 4; j++) { \
            int cch = ((k0) + c4 + j) / 49; \
            float t = fmaxf((xx[j] - m2s[cch]) * r2s[cch], 0.f); \
            __nv_bfloat16 h = __float2bfloat16(t); \
            hs[j] = __bfloat16_as_ushort(h); \
            ls[j] = __bfloat16_as_ushort(__float2bfloat16(t - __bfloat162float(h))); \
        } \
        uint32_t off = (buf) * C3_BUF + row * C3_STRIDE + c4 * 2; \
        *(uint2*)(dsm + C3_AH + off) = make_uint2((uint32_t)hs[0] | ((uint32_t)hs[1] << 16), (uint32_t)hs[2] | ((uint32_t)hs[3] << 16)); \
        *(uint2*)(dsm + C3_AL + off) = make_uint2((uint32_t)ls[0] | ((uint32_t)ls[1] << 16), (uint32_t)ls[2] | ((uint32_t)ls[3] << 16)); \
        size_t bi = (size_t)(N0 + row) * 6272 + (k0) + c4; \
        *(uint2*)(dsm + C3_BH + off) = *(const uint2*)&g_W3h[bi]; \
        *(uint2*)(dsm + C3_BL + off) = *(const uint2*)&g_W3l[bi]; \
    } } while (0)

    float c[4][4][4] = {};
    LOADC(0, 0);
    __syncthreads();
    int lm = lane & 15, lkb = (lane >> 4) * 16;
    for (int ch = 0; ch < 196; ch++) {
        int cur = ch & 1;
        if (ch < 195) LOADC(cur ^ 1, (ch + 1) * 32);
        uint32_t aA = sb + cur * C3_BUF + (wm * 64 + lm) * C3_STRIDE + lkb;
        uint32_t aB = sb + cur * C3_BUF + (wn * 32 + lm) * C3_STRIDE + lkb;
#pragma unroll
        for (int ks = 0; ks < 2; ks++) {
            uint32_t kb = ks * 32;
            uint32_t ah[4][4], al[4][4], bh[2][4], bl[2][4];
#pragma unroll
            for (int mt = 0; mt < 4; mt++) {
                ldsm4(ah[mt], aA + C3_AH + mt * (16 * C3_STRIDE) + kb);
                ldsm4(al[mt], aA + C3_AL + mt * (16 * C3_STRIDE) + kb);
            }
#pragma unroll
            for (int np = 0; np < 2; np++) {
                ldsm4(bh[np], aB + C3_BH + np * (16 * C3_STRIDE) + kb);
                ldsm4(bl[np], aB + C3_BL + np * (16 * C3_STRIDE) + kb);
            }
#pragma unroll
            for (int mt = 0; mt < 4; mt++)
#pragma unroll
                for (int nt = 0; nt < 4; nt++) {
                    int np = nt >> 1, hi = nt & 1;
                    uint32_t b2h[2] = {bh[np][hi], bh[np][hi + 2]};
                    uint32_t b2l[2] = {bl[np][hi], bl[np][hi + 2]};
                    mma_bf16(c[mt][nt], ah[mt], b2h);
                    mma_bf16(c[mt][nt], ah[mt], b2l);
                    mma_bf16(c[mt][nt], al[mt], b2h);
                }
        }
        __syncthreads();
    }
#pragma unroll
    for (int mt = 0; mt < 4; mt++)
#pragma unroll
        for (int nt = 0; nt < 4; nt++) {
            int row = M0 + wm * 64 + mt * 16 + (lane >> 2);
            int col = N0 + wn * 32 + nt * 8 + (lane & 3) * 2;
            *(float2*)&g_y3[(size_t)row * 512 + col] = make_float2(c[mt][nt][0], c[mt][nt][1]);
            *(float2*)&g_y3[(size_t)(row + 8) * 512 + col] = make_float2(c[mt][nt][2], c[mt][nt][3]);
        }
#undef LOADC
}

__global__ void __launch_bounds__(64) latent_kernel(const float* __restrict__ eps, const float* __restrict__ Wfc,
                                                    const float* __restrict__ bfc) {
    __shared__ float sa[512], smu[32], slv[32];
    int n = blockIdx.x, tid = threadIdx.x;
    for (int i = tid; i < 512; i += 64)
        sa[i] = fmaxf((g_y3[(size_t)n * 512 + i] - g_mean[2][i]) * g_rstd[2][i], 0.f);
    __syncthreads();
    float dot = g_cb[tid];
#pragma unroll 8
    for (int ic = 0; ic < 512; ic++) dot += sa[ic] * g_Wc[ic * 64 + tid];
    if (tid < 32) smu[tid] = dot; else slv[tid - 32] = dot;
    __syncthreads();
    if (tid < 32) {
        float mu = smu[tid], lv = slv[tid], sd = expf(0.5f * lv);
        float z = mu + sd * eps[(size_t)n * 32 + tid];
        g_z[(size_t)n * 32 + tid] = z;
        float kl = mu * mu + sd * sd - lv - 1.f;
        float lc = z * Wfc[tid];
#pragma unroll
        for (int o = 16; o > 0; o >>= 1) { kl += __shfl_xor_sync(~0u, kl, o); lc += __shfl_xor_sync(~0u, lc, o); }
        if (tid == 0) { g_klrow[n] = kl; g_loc[n] = lc + bfc[0]; }
    }
}

__global__ void __launch_bounds__(256) bagmax_kernel(const int* __restrict__ bi, const float* __restrict__ lab) {
    __shared__ float sv[8]; __shared__ int si[8]; __shared__ float smx;
    int b = blockIdx.x, tid = threadIdx.x, lane = tid & 31, w = tid >> 5;
    float mx = -3.4e38f;
    for (int n = tid; n < NI; n += 256) if (bi[n] == b) mx = fmaxf(mx, g_loc[n]);
#pragma unroll
    for (int o = 16; o > 0; o >>= 1) mx = fmaxf(mx, __shfl_xor_sync(~0u, mx, o));
    if (lane == 0) sv[w] = mx;
    __syncthreads();
    if (tid == 0) { float v = sv[0]; for (int i = 1; i < 8; i++) v = fmaxf(v, sv[i]); smx = v; }
    __syncthreads();
    float mval = smx; int mn = NI;
    for (int n = tid; n < NI; n += 256) if (bi[n] == b && g_loc[n] == mval) mn = min(mn, n);
#pragma unroll
    for (int o = 16; o > 0; o >>= 1) mn = min(mn, __shfl_xor_sync(~0u, mn, o));
    if (lane == 0) si[w] = mn;
    __syncthreads();
    if (tid == 0) {
        int a = si[0]; for (int i = 1; i < 8; i++) a = min(a, si[i]);
        g_arg[b] = a;
        float M = g_loc[a], y = lab[b];
        g_term[b] = fmaxf(M, 0.f) - M * y + log1pf(expf(-fabsf(M)));
    }
}

__global__ void __launch_bounds__(512) dec1_kernel(const float* __restrict__ D1) {
    __shared__ float zz[32];
    int b = blockIdx.x, tid = threadIdx.x;
    if (tid < 32) zz[tid] = g_z[(size_t)g_arg[b] * 32 + tid];
    __syncthreads();
    float a = 0.f;
#pragma unroll
    for (int ic = 0; ic < 32; ic++) a += zz[ic] * D1[ic * 512 + tid];
    g_t1[b * 512 + tid] = a;
}

__global__ void __launch_bounds__(256) dec2_kernel(const float* __restrict__ D2) {
    __shared__ float at[4096];
    int B0 = blockIdx.x * 8, tid = threadIdx.x;
    for (int i = tid; i < 4096; i += 256) {
        int bl = i >> 9, ic = i & 511;
        at[ic * 8 + bl] = fmaxf((g_t1[(B0 + bl) * 512 + ic] - g_mean[3][ic]) * g_rstd[3][ic], 0.f);
    }
    __syncthreads();
    for (int o = tid; o < 6272; o += 256) {
        float acc[8] = {};
        for (int ic = 0; ic < 512; ic++) {
            float w = D2[(size_t)ic * 6272 + o];
            float4 x0 = *(const float4*)&at[ic * 8], x1 = *(const float4*)&at[ic * 8 + 4];
            acc[0] += x0.x * w; acc[1] += x0.y * w; acc[2] += x0.z * w; acc[3] += x0.w * w;
            acc[4] += x1.x * w; acc[5] += x1.y * w; acc[6] += x1.z * w; acc[7] += x1.w * w;
        }
#pragma unroll
        for (int j = 0; j < 8; j++) g_t2[(size_t)(B0 + j) * 6272 + o] = acc[j];
    }
}

__global__ void __launch_bounds__(256) dec3_kernel(const float* __restrict__ D3) {
    __shared__ float a2[6272], wt[2048];
    int b = blockIdx.x, tid = threadIdx.x;
    for (int i = tid; i < 6272; i += 256) {
        int c = i / 49;
        a2[i] = fmaxf((g_t2[(size_t)b * 6272 + i] - g_mean[4][c]) * g_rstd[4][c], 0.f);
    }
    __syncthreads();
    int oy = tid / 14, ox = tid - (tid / 14) * 14;
    for (int oc = 0; oc < 32; oc++) {
        for (int i = tid; i < 2048; i += 256) wt[i] = D3[(i >> 4) * 512 + oc * 16 + (i & 15)];
        __syncthreads();
        if (tid < 196) {
            float a = 0.f;
#pragma unroll
            for (int ky = 0; ky < 4; ky++) {
                int t = oy + 1 - ky;
                if (t >= 0 && !(t & 1) && (t >> 1) < 7) {
                    int iy = t >> 1;
#pragma unroll
                    for (int kx = 0; kx < 4; kx++) {
                        int u = ox + 1 - kx;
                        if (u >= 0 && !(u & 1) && (u >> 1) < 7) {
                            int sB = iy * 7 + (u >> 1), wB = ky * 4 + kx;
#pragma unroll 16
                            for (int ic = 0; ic < 128; ic++) a += a2[ic * 49 + sB] * wt[ic * 16 + wB];
                        }
                    }
                }
            }
            g_t3[(size_t)b * 6272 + oc * 196 + tid] = a;
        }
        __syncthreads();
    }
}

__global__ void __launch_bounds__(256) dec4_kernel(const float* __restrict__ D4, const float* __restrict__ d4,
                                                   const float* __restrict__ bag) {
    __shared__ float a3[6272], w4s[512];
    int b = blockIdx.x, tid = threadIdx.x;
    for (int i = tid; i < 6272; i += 256) {
        int c = i / 196;
        a3[i] = fmaxf((g_t3[(size_t)b * 6272 + i] - g_mean[5][c]) * g_rstd[5][c], 0.f);
    }
    for (int i = tid; i < 512; i += 256) w4s[i] = D4[i];
    __syncthreads();
    float bias = d4[0]; int arg = g_arg[b];
    float sq = 0.f;
    for (int o = tid; o < 784; o += 256) {
        int oy = o / 28, ox = o - (o / 28) * 28;
        float a = bias;
#pragma unroll
        for (int ky = 0; ky < 4; ky++) {
            int t = oy + 1 - ky;
            if (t >= 0 && !(t & 1) && (t >> 1) < 14) {
                int iy = t >> 1;
#pragma unroll
                for (int kx = 0; kx < 4; kx++) {
                    int u = ox + 1 - kx;
                    if (u >= 0 && !(u & 1) && (u >> 1) < 14) {
                        int sB = iy * 14 + (u >> 1), wB = ky * 4 + kx;
#pragma unroll
                        for (int ic = 0; ic < 32; ic++) a += a3[ic * 196 + sB] * w4s[ic * 16 + wB];
                    }
                }
            }
        }
        float s = 1.f / (1.f + expf(-a));
        float d = s - bag[(size_t)arg * 784 + o];
        sq += d * d;
    }
    float2 r = bsum2(make_float2(sq, 0.f));
    if (tid == 0) g_rec[b] = r.x;
}

__global__ void __launch_bounds__(256) final_kernel(float* __restrict__ out) {
    int tid = threadIdx.x;
    float kl = 0.f;
    for (int n = tid; n < NI; n += 256) kl += g_klrow[n];
    float tm = 0.f, rc = 0.f;
    if (tid < NB) { tm = g_term[tid]; rc = g_rec[tid]; }
    float2 a = bsum2(make_float2(kl, tm));
    __syncthreads();
    float2 bb = bsum2(make_float2(rc, 0.f));
    if (tid == 0) {
        out[0] = bb.x / (256.f * 784.f);
        out[1] = 0.5f * a.x / (16384.f * 32.f);
        out[2] = a.y / 256.f;
    }
}

extern "C" void kernel_launch(void* const* d_in, const int* in_sizes, int n_in,
                              void* d_out, int out_size) {
    const float* bag = (const float*)d_in[0];
    const int* bag_idx = (const int*)d_in[1];
    const float* lab = (const float*)d_in[2];
    const float* eps = (const float*)d_in[3];
    const float* W1 = (const float*)d_in[4];
    const float* W2 = (const float*)d_in[6];
    const float* W3 = (const float*)d_in[8];
    const float* W4 = (const float*)d_in[10];
    const float* b4 = (const float*)d_in[11];
    const float* Wm = (const float*)d_in[12];
    const float* bm = (const float*)d_in[13];
    const float* Wlv = (const float*)d_in[14];
    const float* blv = (const float*)d_in[15];
    const float* Wfc = (const float*)d_in[16];
    const float* bfc = (const float*)d_in[17];
    const float* D1 = (const float*)d_in[18];
    const float* D2 = (const float*)d_in[20];
    const float* D3 = (const float*)d_in[22];
    const float* D4 = (const float*)d_in[24];
    const float* d4 = (const float*)d_in[25];

    float *y1, *y2, *y3, *t1, *t2, *t3;
    cudaGetSymbolAddress((void**)&y1, g_y1);
    cudaGetSymbolAddress((void**)&y2, g_y2);
    cudaGetSymbolAddress((void**)&y3, g_y3);
    cudaGetSymbolAddress((void**)&t1, g_t1);
    cudaGetSymbolAddress((void**)&t2, g_t2);
    cudaGetSymbolAddress((void**)&t3, g_t3);

    cudaFuncSetAttribute(conv3_mma, cudaFuncAttributeMaxDynamicSharedMemorySize, C3_SMEM);

    prep_kernel<<<12544, 256>>>(W2, W3, Wm, Wlv, W4, b4, bm, blv);
    conv1_kernel<<<NI, 256>>>(bag, W1);
    stats_part<<<dim3(32, 8), 256>>>(y1, 196, NI, 6272, 196, 1);
    conv2_gemm<<<6272, 256>>>();
    stats_part<<<dim3(128, 8), 256>>>(y2, 49, NI, 6272, 49, 1);
    conv3_mma<<<dim3(128, 4), 256, C3_SMEM>>>();
    stats_part<<<dim3(512, 8), 256>>>(y3, 1, NI, 512, 1, 0);
    stats_fin<<<1, 512>>>(2, 8, NI);
    latent_kernel<<<NI, 64>>>(eps, Wfc, bfc);
    bagmax_kernel<<<NB, 256>>>(bag_idx, lab);
    dec1_kernel<<<NB, 512>>>(D1);
    stats_part<<<dim3(512, 2), 256>>>(t1, 1, NB, 512, 1, 0);
    stats_fin<<<1, 512>>>(3, 2, NB);
    dec2_kernel<<<32, 256>>>(D2);
    stats_part<<<dim3(128, 2), 256>>>(t2, 49, NB, 6272, 49, 1);
    stats_fin<<<1, 128>>>(4, 2, NB * 49);
    dec3_kernel<<<NB, 256>>>(D3);
    stats_part<<<dim3(32, 2), 256>>>(t3, 196, NB, 6272, 196, 1);
    stats_fin<<<1, 32>>>(5, 2, NB * 196);
    dec4_kernel<<<NB, 256>>>(D4, d4, bag);
    final_kernel<<<1, 256>>>((float*)d_out);
}

// round 11
// speedup vs baseline: 1.5576x; 1.1562x over previous
#include <cuda_runtime.h>
#include <cuda_bf16.h>
#include <math.h>
#include <stdint.h>
#define NI 16384
#define NB 256

__device__ float g_y1[102760448];
__device__ float g_y2[102760448];          // packed raw conv2 out: [n][c*49+p]
__device__ float g_y3[8388608];
__device__ __nv_bfloat16 g_W2h[65536], g_W2l[65536];
__device__ __nv_bfloat16 g_W3h[3211264], g_W3l[3211264];
__device__ float g_Wc[32768];
__device__ float g_cb[64];
__device__ float g_mean[6][512], g_rstd[6][512];
__device__ float g_spart[16384];
__device__ float g_z[524288];
__device__ float g_loc[NI];
__device__ float g_klrow[NI];
__device__ int   g_arg[NB];
__device__ float g_term[NB];
__device__ float g_rec[NB];
__device__ float g_t1[131072];
__device__ float g_t2[1605632];
__device__ float g_t3[1605632];

__device__ __forceinline__ uint32_t smem_u32(const void* p) {
    uint32_t a;
    asm("{ .reg .u64 t; cvta.to.shared.u64 t, %1; cvt.u32.u64 %0, t; }" : "=r"(a) : "l"(p));
    return a;
}
__device__ __forceinline__ void ldsm4(uint32_t* r, uint32_t addr) {
    asm volatile("ldmatrix.sync.aligned.m8n8.x4.shared.b16 {%0,%1,%2,%3}, [%4];"
        : "=r"(r[0]), "=r"(r[1]), "=r"(r[2]), "=r"(r[3]) : "r"(addr));
}
__device__ __forceinline__ void mma_bf16(float* c, const uint32_t* a, const uint32_t* b) {
    asm volatile("mma.sync.aligned.m16n8k16.row.col.f32.bf16.bf16.f32 "
        "{%0,%1,%2,%3}, {%4,%5,%6,%7}, {%8,%9}, {%0,%1,%2,%3};"
        : "+f"(c[0]), "+f"(c[1]), "+f"(c[2]), "+f"(c[3])
        : "r"(a[0]), "r"(a[1]), "r"(a[2]), "r"(a[3]), "r"(b[0]), "r"(b[1]));
}

__device__ __forceinline__ float2 bsum2(float2 v) {
    __shared__ float2 sh[32];
    int lane = threadIdx.x & 31, w = threadIdx.x >> 5;
#pragma unroll
    for (int o = 16; o > 0; o >>= 1) { v.x += __shfl_xor_sync(~0u, v.x, o); v.y += __shfl_xor_sync(~0u, v.y, o); }
    __syncthreads();
    if (lane == 0) sh[w] = v;
    __syncthreads();
    int nw = (blockDim.x + 31) >> 5;
    if (w == 0) {
        v = (lane < nw) ? sh[lane] : make_float2(0.f, 0.f);
#pragma unroll
        for (int o = 16; o > 0; o >>= 1) { v.x += __shfl_xor_sync(~0u, v.x, o); v.y += __shfl_xor_sync(~0u, v.y, o); }
    }
    return v;
}

__global__ void prep_kernel(const float* W2, const float* W3, const float* Wm, const float* Wlv,
                            const float* W4, const float* b4, const float* bm, const float* blv) {
    int i = blockIdx.x * 256 + threadIdx.x;
    if (i < 65536) {
        float w = W2[i];
        __nv_bfloat16 h = __float2bfloat16(w);
        g_W2h[i] = h;
        g_W2l[i] = __float2bfloat16(w - __bfloat162float(h));
    }
    if (i < 3211264) {
        float w = W3[i];
        __nv_bfloat16 h = __float2bfloat16(w);
        g_W3h[i] = h;
        g_W3l[i] = __float2bfloat16(w - __bfloat162float(h));
    }
    if (i < 32768) {
        int ic = i >> 6, r = i & 63;
        const float* row = (r < 32) ? (Wm + r * 200) : (Wlv + (r - 32) * 200);
        float s = 0.f;
        for (int j = 0; j < 200; j++) s += row[j] * W4[j * 512 + ic];
        g_Wc[ic * 64 + r] = s;
        if (ic == 0) {
            float cb = (r < 32) ? bm[r] : blv[r - 32];
            for (int j = 0; j < 200; j++) cb += row[j] * b4[j];
            g_cb[r] = cb;
        }
    }
}

__global__ void __launch_bounds__(256) conv1_kernel(const float* __restrict__ bag, const float* __restrict__ W1) {
    __shared__ float xs[784], ws[512];
    int n = blockIdx.x, tid = threadIdx.x;
    for (int i = tid; i < 784; i += 256) xs[i] = bag[(size_t)n * 784 + i];
    for (int i = tid; i < 512; i += 256) ws[i] = W1[i];
    __syncthreads();
    int oc = tid >> 3, sub = tid & 7;
    float w[16];
#pragma unroll
    for (int t = 0; t < 16; t++) w[t] = ws[oc * 16 + t];
    for (int p = sub; p < 196; p += 8) {
        int oy = p / 14, ox = p - (p / 14) * 14;
        float a = 0.f;
#pragma unroll
        for (int ky = 0; ky < 4; ky++) {
            int iy = 2 * oy - 1 + ky;
            if ((unsigned)iy < 28u)
#pragma unroll
                for (int kx = 0; kx < 4; kx++) {
                    int ix = 2 * ox - 1 + kx;
                    if ((unsigned)ix < 28u) a += xs[iy * 28 + ix] * w[ky * 4 + kx];
                }
        }
        g_y1[(size_t)n * 6272 + oc * 196 + p] = a;
    }
}

__global__ void __launch_bounds__(256) stats_part(const float* __restrict__ src, int HW, int Nn, int sN, int sC, int sI) {
    int c = blockIdx.x, p = blockIdx.y, P = gridDim.y, tid = threadIdx.x;
    int total = Nn * HW;
    float s = 0.f, q = 0.f;
    for (int j = p * 256 + tid; j < total; j += P * 256) {
        int n = j / HW, i = j - n * HW;
        float v = src[(size_t)n * sN + (size_t)c * sC + (size_t)i * sI];
        s += v; q += v * v;
    }
    float2 r = bsum2(make_float2(s, q));
    if (tid == 0) { g_spart[(c * P + p) * 2] = r.x; g_spart[(c * P + p) * 2 + 1] = r.y; }
}

__global__ void stats_fin(int id, int P, int count) {
    int c = threadIdx.x;
    float s = 0.f, q = 0.f;
    for (int p = 0; p < P; p++) { s += g_spart[(c * P + p) * 2]; q += g_spart[(c * P + p) * 2 + 1]; }
    float m = s / count;
    g_mean[id][c] = m;
    g_rstd[id][c] = rsqrtf(q / count - m * m + 1e-5f);
}

// shared smem geometry for both mma GEMMs
#define C3_STRIDE 80
#define C3_BUF 10240
#define C3_AH 0
#define C3_AL 20480
#define C3_BH 40960
#define C3_BL 61440
#define C3_SMEM 81920

// ---------------- conv2 via mma.sync bf16 (implicit im2col, h+l split) ----------------
__global__ void __launch_bounds__(256) conv2_mma() {
    extern __shared__ char dsm[];
    __shared__ float m1s[32], r1s[32];
    uint32_t sb = smem_u32(dsm);
    int tid = threadIdx.x, lane = tid & 31, wid = tid >> 5;
    int wm = wid >> 2, wn = wid & 3;
    if (tid < 32) {
        float s = 0.f, q = 0.f;
#pragma unroll
        for (int p = 0; p < 8; p++) { s += g_spart[(tid * 8 + p) * 2]; q += g_spart[(tid * 8 + p) * 2 + 1]; }
        float cnt = (float)NI * 196.f, m = s / cnt;
        m1s[tid] = m; r1s[tid] = rsqrtf(q / cnt - m * m + 1e-5f);
    }
    int M0 = blockIdx.x * 128;
    int aoff[4][4]; unsigned aval = 0;
    int c4 = (tid & 7) << 2, hb = c4 >> 4;
#pragma unroll
    for (int q = 0; q < 4; q++) {
        int f = q * 256 + tid, row = f >> 3;
        int m = M0 + row, n = m / 49, p = m - n * 49;
        int oy = p / 7, ox = p - (p / 7) * 7;
#pragma unroll
        for (int j = 0; j < 4; j++) {
            int r = (c4 + j) & 15;
            int iy = 2 * oy - 1 + (r >> 2), ix = 2 * ox - 1 + (r & 3);
            if (iy >= 0 && iy < 14 && ix >= 0 && ix < 14) aval |= 1u << (q * 4 + j);
            aoff[q][j] = n * 6272 + iy * 14 + ix;
        }
    }
    __syncthreads();

#define LOADC2(buf, kt) do { \
    int ic = (kt) * 2 + hb; \
    float mc = m1s[ic], rc = r1s[ic]; \
    int add = ic * 196; \
    _Pragma("unroll") \
    for (int q = 0; q < 4; q++) { \
        int f = q * 256 + tid, row = f >> 3; \
        unsigned short hs[4], ls[4]; \
        _Pragma("unroll") \
        for (int j = 0; j < 4; j++) { \
            float t = 0.f; \
            if (aval & (1u << (q * 4 + j))) t = fmaxf((g_y1[aoff[q][j] + add] - mc) * rc, 0.f); \
            __nv_bfloat16 h = __float2bfloat16(t); \
            hs[j] = __bfloat16_as_ushort(h); \
            ls[j] = __bfloat16_as_ushort(__float2bfloat16(t - __bfloat162float(h))); \
        } \
        uint32_t off = (buf) * C3_BUF + row * C3_STRIDE + c4 * 2; \
        *(uint2*)(dsm + C3_AH + off) = make_uint2((uint32_t)hs[0] | ((uint32_t)hs[1] << 16), (uint32_t)hs[2] | ((uint32_t)hs[3] << 16)); \
        *(uint2*)(dsm + C3_AL + off) = make_uint2((uint32_t)ls[0] | ((uint32_t)ls[1] << 16), (uint32_t)ls[2] | ((uint32_t)ls[3] << 16)); \
        size_t bi = (size_t)row * 512 + (kt) * 32 + c4; \
        *(uint2*)(dsm + C3_BH + off) = *(const uint2*)&g_W2h[bi]; \
        *(uint2*)(dsm + C3_BL + off) = *(const uint2*)&g_W2l[bi]; \
    } } while (0)

    float c[4][4][4] = {};
    LOADC2(0, 0);
    __syncthreads();
    int lm = lane & 15, lkb = (lane >> 4) * 16;
    for (int ch = 0; ch < 16; ch++) {
        int cur = ch & 1;
        if (ch < 15) LOADC2(cur ^ 1, ch + 1);
        uint32_t aA = sb + cur * C3_BUF + (wm * 64 + lm) * C3_STRIDE + lkb;
        uint32_t aB = sb + cur * C3_BUF + (wn * 32 + lm) * C3_STRIDE + lkb;
#pragma unroll
        for (int ks = 0; ks < 2; ks++) {
            uint32_t kb = ks * 32;
            uint32_t ah[4][4], al[4][4], bh[2][4], bl[2][4];
#pragma unroll
            for (int mt = 0; mt < 4; mt++) {
                ldsm4(ah[mt], aA + C3_AH + mt * (16 * C3_STRIDE) + kb);
                ldsm4(al[mt], aA + C3_AL + mt * (16 * C3_STRIDE) + kb);
            }
#pragma unroll
            for (int np = 0; np < 2; np++) {
                ldsm4(bh[np], aB + C3_BH + np * (16 * C3_STRIDE) + kb);
                ldsm4(bl[np], aB + C3_BL + np * (16 * C3_STRIDE) + kb);
            }
#pragma unroll
            for (int mt = 0; mt < 4; mt++)
#pragma unroll
                for (int nt = 0; nt < 4; nt++) {
                    int np = nt >> 1, hi = nt & 1;
                    uint32_t b2h[2] = {bh[np][hi], bh[np][hi + 2]};
                    uint32_t b2l[2] = {bl[np][hi], bl[np][hi + 2]};
                    mma_bf16(c[mt][nt], ah[mt], b2h);
                    mma_bf16(c[mt][nt], ah[mt], b2l);
                    mma_bf16(c[mt][nt], al[mt], b2h);
                }
        }
        __syncthreads();
    }
#undef LOADC2
    float* cs = (float*)dsm;
#pragma unroll
    for (int mt = 0; mt < 4; mt++)
#pragma unroll
        for (int nt = 0; nt < 4; nt++) {
            int r0 = wm * 64 + mt * 16 + (lane >> 2);
            int cc = wn * 32 + nt * 8 + (lane & 3) * 2;
            cs[r0 * 133 + cc] = c[mt][nt][0];
            cs[r0 * 133 + cc + 1] = c[mt][nt][1];
            cs[(r0 + 8) * 133 + cc] = c[mt][nt][2];
            cs[(r0 + 8) * 133 + cc + 1] = c[mt][nt][3];
        }
    __syncthreads();
    for (int i = tid; i < 16384; i += 256) {
        int oc = i >> 7, row = i & 127;
        int m = M0 + row, n = m / 49, p = m - n * 49;
        g_y2[(size_t)n * 6272 + oc * 49 + p] = cs[row * 133 + oc];
    }
}

// ---------------- conv3 via mma.sync bf16 (h+l split) ----------------
__global__ void __launch_bounds__(256) conv3_mma() {
    extern __shared__ char dsm[];
    __shared__ float m2s[128], r2s[128];
    uint32_t sb = smem_u32(dsm);
    int tid = threadIdx.x, lane = tid & 31, wid = tid >> 5;
    int wm = wid >> 2, wn = wid & 3;
    if (tid < 128) {
        float s = 0.f, q = 0.f;
#pragma unroll
        for (int p = 0; p < 8; p++) { s += g_spart[(tid * 8 + p) * 2]; q += g_spart[(tid * 8 + p) * 2 + 1]; }
        float cnt = (float)NI * 49.f, m = s / cnt;
        m2s[tid] = m; r2s[tid] = rsqrtf(q / cnt - m * m + 1e-5f);
    }
    __syncthreads();
    int M0 = blockIdx.x * 128, N0 = blockIdx.y * 128;

#define LOADC(buf, k0) do { \
    _Pragma("unroll") \
    for (int q = 0; q < 4; q++) { \
        int f = q * 256 + tid; \
        int row = f >> 3, c4 = (f & 7) << 2; \
        float4 v = *(const float4*)&g_y2[(size_t)(M0 + row) * 6272 + (k0) + c4]; \
        float xx[4] = {v.x, v.y, v.z, v.w}; \
        unsigned short hs[4], ls[4]; \
        _Pragma("unroll") \
        for (int j = 0; j < 4; j++) { \
            int cch = ((k0) + c4 + j) / 49; \
            float t = fmaxf((xx[j] - m2s[cch]) * r2s[cch], 0.f); \
            __nv_bfloat16 h = __float2bfloat16(t); \
            hs[j] = __bfloat16_as_ushort(h); \
            ls[j] = __bfloat16_as_ushort(__float2bfloat16(t - __bfloat162float(h))); \
        } \
        uint32_t off = (buf) * C3_BUF + row * C3_STRIDE + c4 * 2; \
        *(uint2*)(dsm + C3_AH + off) = make_uint2((uint32_t)hs[0] | ((uint32_t)hs[1] << 16), (uint32_t)hs[2] | ((uint32_t)hs[3] << 16)); \
        *(uint2*)(dsm + C3_AL + off) = make_uint2((uint32_t)ls[0] | ((uint32_t)ls[1] << 16), (uint32_t)ls[2] | ((uint32_t)ls[3] << 16)); \
        size_t bi = (size_t)(N0 + row) * 6272 + (k0) + c4; \
        *(uint2*)(dsm + C3_BH + off) = *(const uint2*)&g_W3h[bi]; \
        *(uint2*)(dsm + C3_BL + off) = *(const uint2*)&g_W3l[bi]; \
    } } while (0)

    float c[4][4][4] = {};
    LOADC(0, 0);
    __syncthreads();
    int lm = lane & 15, lkb = (lane >> 4) * 16;
    for (int ch = 0; ch < 196; ch++) {
        int cur = ch & 1;
        if (ch < 195) LOADC(cur ^ 1, (ch + 1) * 32);
        uint32_t aA = sb + cur * C3_BUF + (wm * 64 + lm) * C3_STRIDE + lkb;
        uint32_t aB = sb + cur * C3_BUF + (wn * 32 + lm) * C3_STRIDE + lkb;
#pragma unroll
        for (int ks = 0; ks < 2; ks++) {
            uint32_t kb = ks * 32;
            uint32_t ah[4][4], al[4][4], bh[2][4], bl[2][4];
#pragma unroll
            for (int mt = 0; mt < 4; mt++) {
                ldsm4(ah[mt], aA + C3_AH + mt * (16 * C3_STRIDE) + kb);
                ldsm4(al[mt], aA + C3_AL + mt * (16 * C3_STRIDE) + kb);
            }
#pragma unroll
            for (int np = 0; np < 2; np++) {
                ldsm4(bh[np], aB + C3_BH + np * (16 * C3_STRIDE) + kb);
                ldsm4(bl[np], aB + C3_BL + np * (16 * C3_STRIDE) + kb);
            }
#pragma unroll
            for (int mt = 0; mt < 4; mt++)
#pragma unroll
                for (int nt = 0; nt < 4; nt++) {
                    int np = nt >> 1, hi = nt & 1;
                    uint32_t b2h[2] = {bh[np][hi], bh[np][hi + 2]};
                    uint32_t b2l[2] = {bl[np][hi], bl[np][hi + 2]};
                    mma_bf16(c[mt][nt], ah[mt], b2h);
                    mma_bf16(c[mt][nt], ah[mt], b2l);
                    mma_bf16(c[mt][nt], al[mt], b2h);
                }
        }
        __syncthreads();
    }
#pragma unroll
    for (int mt = 0; mt < 4; mt++)
#pragma unroll
        for (int nt = 0; nt < 4; nt++) {
            int row = M0 + wm * 64 + mt * 16 + (lane >> 2);
            int col = N0 + wn * 32 + nt * 8 + (lane & 3) * 2;
            *(float2*)&g_y3[(size_t)row * 512 + col] = make_float2(c[mt][nt][0], c[mt][nt][1]);
            *(float2*)&g_y3[(size_t)(row + 8) * 512 + col] = make_float2(c[mt][nt][2], c[mt][nt][3]);
        }
#undef LOADC
}

__global__ void __launch_bounds__(64) latent_kernel(const float* __restrict__ eps, const float* __restrict__ Wfc,
                                                    const float* __restrict__ bfc) {
    __shared__ float sa[512], smu[32], slv[32];
    int n = blockIdx.x, tid = threadIdx.x;
    for (int i = tid; i < 512; i += 64)
        sa[i] = fmaxf((g_y3[(size_t)n * 512 + i] - g_mean[2][i]) * g_rstd[2][i], 0.f);
    __syncthreads();
    float dot = g_cb[tid];
#pragma unroll 8
    for (int ic = 0; ic < 512; ic++) dot += sa[ic] * g_Wc[ic * 64 + tid];
    if (tid < 32) smu[tid] = dot; else slv[tid - 32] = dot;
    __syncthreads();
    if (tid < 32) {
        float mu = smu[tid], lv = slv[tid], sd = expf(0.5f * lv);
        float z = mu + sd * eps[(size_t)n * 32 + tid];
        g_z[(size_t)n * 32 + tid] = z;
        float kl = mu * mu + sd * sd - lv - 1.f;
        float lc = z * Wfc[tid];
#pragma unroll
        for (int o = 16; o > 0; o >>= 1) { kl += __shfl_xor_sync(~0u, kl, o); lc += __shfl_xor_sync(~0u, lc, o); }
        if (tid == 0) { g_klrow[n] = kl; g_loc[n] = lc + bfc[0]; }
    }
}

__global__ void __launch_bounds__(256) bagmax_kernel(const int* __restrict__ bi, const float* __restrict__ lab) {
    __shared__ float sv[8]; __shared__ int si[8]; __shared__ float smx;
    int b = blockIdx.x, tid = threadIdx.x, lane = tid & 31, w = tid >> 5;
    float mx = -3.4e38f;
    for (int n = tid; n < NI; n += 256) if (bi[n] == b) mx = fmaxf(mx, g_loc[n]);
#pragma unroll
    for (int o = 16; o > 0; o >>= 1) mx = fmaxf(mx, __shfl_xor_sync(~0u, mx, o));
    if (lane == 0) sv[w] = mx;
    __syncthreads();
    if (tid == 0) { float v = sv[0]; for (int i = 1; i < 8; i++) v = fmaxf(v, sv[i]); smx = v; }
    __syncthreads();
    float mval = smx; int mn = NI;
    for (int n = tid; n < NI; n += 256) if (bi[n] == b && g_loc[n] == mval) mn = min(mn, n);
#pragma unroll
    for (int o = 16; o > 0; o >>= 1) mn = min(mn, __shfl_xor_sync(~0u, mn, o));
    if (lane == 0) si[w] = mn;
    __syncthreads();
    if (tid == 0) {
        int a = si[0]; for (int i = 1; i < 8; i++) a = min(a, si[i]);
        g_arg[b] = a;
        float M = g_loc[a], y = lab[b];
        g_term[b] = fmaxf(M, 0.f) - M * y + log1pf(expf(-fabsf(M)));
    }
}

__global__ void __launch_bounds__(512) dec1_kernel(const float* __restrict__ D1) {
    __shared__ float zz[32];
    int b = blockIdx.x, tid = threadIdx.x;
    if (tid < 32) zz[tid] = g_z[(size_t)g_arg[b] * 32 + tid];
    __syncthreads();
    float a = 0.f;
#pragma unroll
    for (int ic = 0; ic < 32; ic++) a += zz[ic] * D1[ic * 512 + tid];
    g_t1[b * 512 + tid] = a;
}

__global__ void __launch_bounds__(256) dec2_kernel(const float* __restrict__ D2) {
    __shared__ float at[4096];
    int B0 = blockIdx.x * 8, tid = threadIdx.x;
    for (int i = tid; i < 4096; i += 256) {
        int bl = i >> 9, ic = i & 511;
        at[ic * 8 + bl] = fmaxf((g_t1[(B0 + bl) * 512 + ic] - g_mean[3][ic]) * g_rstd[3][ic], 0.f);
    }
    __syncthreads();
    for (int o = tid; o < 6272; o += 256) {
        float acc[8] = {};
        for (int ic = 0; ic < 512; ic++) {
            float w = D2[(size_t)ic * 6272 + o];
            float4 x0 = *(const float4*)&at[ic * 8], x1 = *(const float4*)&at[ic * 8 + 4];
            acc[0] += x0.x * w; acc[1] += x0.y * w; acc[2] += x0.z * w; acc[3] += x0.w * w;
            acc[4] += x1.x * w; acc[5] += x1.y * w; acc[6] += x1.z * w; acc[7] += x1.w * w;
        }
#pragma unroll
        for (int j = 0; j < 8; j++) g_t2[(size_t)(B0 + j) * 6272 + o] = acc[j];
    }
}

__global__ void __launch_bounds__(256) dec3_kernel(const float* __restrict__ D3) {
    __shared__ float a2[6272], wt[2048];
    int b = blockIdx.x, tid = threadIdx.x;
    for (int i = tid; i < 6272; i += 256) {
        int c = i / 49;
        a2[i] = fmaxf((g_t2[(size_t)b * 6272 + i] - g_mean[4][c]) * g_rstd[4][c], 0.f);
    }
    __syncthreads();
    int oy = tid / 14, ox = tid - (tid / 14) * 14;
    for (int oc = 0; oc < 32; oc++) {
        for (int i = tid; i < 2048; i += 256) wt[i] = D3[(i >> 4) * 512 + oc * 16 + (i & 15)];
        __syncthreads();
        if (tid < 196) {
            float a = 0.f;
#pragma unroll
            for (int ky = 0; ky < 4; ky++) {
                int t = oy + 1 - ky;
                if (t >= 0 && !(t & 1) && (t >> 1) < 7) {
                    int iy = t >> 1;
#pragma unroll
                    for (int kx = 0; kx < 4; kx++) {
                        int u = ox + 1 - kx;
                        if (u >= 0 && !(u & 1) && (u >> 1) < 7) {
                            int sB = iy * 7 + (u >> 1), wB = ky * 4 + kx;
#pragma unroll 16
                            for (int ic = 0; ic < 128; ic++) a += a2[ic * 49 + sB] * wt[ic * 16 + wB];
                        }
                    }
                }
            }
            g_t3[(size_t)b * 6272 + oc * 196 + tid] = a;
        }
        __syncthreads();
    }
}

__global__ void __launch_bounds__(256) dec4_kernel(const float* __restrict__ D4, const float* __restrict__ d4,
                                                   const float* __restrict__ bag) {
    __shared__ float a3[6272], w4s[512];
    int b = blockIdx.x, tid = threadIdx.x;
    for (int i = tid; i < 6272; i += 256) {
        int c = i / 196;
        a3[i] = fmaxf((g_t3[(size_t)b * 6272 + i] - g_mean[5][c]) * g_rstd[5][c], 0.f);
    }
    for (int i = tid; i < 512; i += 256) w4s[i] = D4[i];
    __syncthreads();
    float bias = d4[0]; int arg = g_arg[b];
    float sq = 0.f;
    for (int o = tid; o < 784; o += 256) {
        int oy = o / 28, ox = o - (o / 28) * 28;
        float a = bias;
#pragma unroll
        for (int ky = 0; ky < 4; ky++) {
            int t = oy + 1 - ky;
            if (t >= 0 && !(t & 1) && (t >> 1) < 14) {
                int iy = t >> 1;
#pragma unroll
                for (int kx = 0; kx < 4; kx++) {
                    int u = ox + 1 - kx;
                    if (u >= 0 && !(u & 1) && (u >> 1) < 14) {
                        int sB = iy * 14 + (u >> 1), wB = ky * 4 + kx;
#pragma unroll
                        for (int ic = 0; ic < 32; ic++) a += a3[ic * 196 + sB] * w4s[ic * 16 + wB];
                    }
                }
            }
        }
        float s = 1.f / (1.f + expf(-a));
        float d = s - bag[(size_t)arg * 784 + o];
        sq += d * d;
    }
    float2 r = bsum2(make_float2(sq, 0.f));
    if (tid == 0) g_rec[b] = r.x;
}

__global__ void __launch_bounds__(256) final_kernel(float* __restrict__ out) {
    int tid = threadIdx.x;
    float kl = 0.f;
    for (int n = tid; n < NI; n += 256) kl += g_klrow[n];
    float tm = 0.f, rc = 0.f;
    if (tid < NB) { tm = g_term[tid]; rc = g_rec[tid]; }
    float2 a = bsum2(make_float2(kl, tm));
    __syncthreads();
    float2 bb = bsum2(make_float2(rc, 0.f));
    if (tid == 0) {
        out[0] = bb.x / (256.f * 784.f);
        out[1] = 0.5f * a.x / (16384.f * 32.f);
        out[2] = a.y / 256.f;
    }
}

extern "C" void kernel_launch(void* const* d_in, const int* in_sizes, int n_in,
                              void* d_out, int out_size) {
    const float* bag = (const float*)d_in[0];
    const int* bag_idx = (const int*)d_in[1];
    const float* lab = (const float*)d_in[2];
    const float* eps = (const float*)d_in[3];
    const float* W1 = (const float*)d_in[4];
    const float* W2 = (const float*)d_in[6];
    const float* W3 = (const float*)d_in[8];
    const float* W4 = (const float*)d_in[10];
    const float* b4 = (const float*)d_in[11];
    const float* Wm = (const float*)d_in[12];
    const float* bm = (const float*)d_in[13];
    const float* Wlv = (const float*)d_in[14];
    const float* blv = (const float*)d_in[15];
    const float* Wfc = (const float*)d_in[16];
    const float* bfc = (const float*)d_in[17];
    const float* D1 = (const float*)d_in[18];
    const float* D2 = (const float*)d_in[20];
    const float* D3 = (const float*)d_in[22];
    const float* D4 = (const float*)d_in[24];
    const float* d4 = (const float*)d_in[25];

    float *y1, *y2, *y3, *t1, *t2, *t3;
    cudaGetSymbolAddress((void**)&y1, g_y1);
    cudaGetSymbolAddress((void**)&y2, g_y2);
    cudaGetSymbolAddress((void**)&y3, g_y3);
    cudaGetSymbolAddress((void**)&t1, g_t1);
    cudaGetSymbolAddress((void**)&t2, g_t2);
    cudaGetSymbolAddress((void**)&t3, g_t3);

    cudaFuncSetAttribute(conv2_mma, cudaFuncAttributeMaxDynamicSharedMemorySize, C3_SMEM);
    cudaFuncSetAttribute(conv3_mma, cudaFuncAttributeMaxDynamicSharedMemorySize, C3_SMEM);

    prep_kernel<<<12544, 256>>>(W2, W3, Wm, Wlv, W4, b4, bm, blv);
    conv1_kernel<<<NI, 256>>>(bag, W1);
    stats_part<<<dim3(32, 8), 256>>>(y1, 196, NI, 6272, 196, 1);
    conv2_mma<<<6272, 256, C3_SMEM>>>();
    stats_part<<<dim3(128, 8), 256>>>(y2, 49, NI, 6272, 49, 1);
    conv3_mma<<<dim3(128, 4), 256, C3_SMEM>>>();
    stats_part<<<dim3(512, 8), 256>>>(y3, 1, NI, 512, 1, 0);
    stats_fin<<<1, 512>>>(2, 8, NI);
    latent_kernel<<<NI, 64>>>(eps, Wfc, bfc);
    bagmax_kernel<<<NB, 256>>>(bag_idx, lab);
    dec1_kernel<<<NB, 512>>>(D1);
    stats_part<<<dim3(512, 2), 256>>>(t1, 1, NB, 512, 1, 0);
    stats_fin<<<1, 512>>>(3, 2, NB);
    dec2_kernel<<<32, 256>>>(D2);
    stats_part<<<dim3(128, 2), 256>>>(t2, 49, NB, 6272, 49, 1);
    stats_fin<<<1, 128>>>(4, 2, NB * 49);
    dec3_kernel<<<NB, 256>>>(D3);
    stats_part<<<dim3(32, 2), 256>>>(t3, 196, NB, 6272, 196, 1);
    stats_fin<<<1, 32>>>(5, 2, NB * 196);
    dec4_kernel<<<NB, 256>>>(D4, d4, bag);
    final_kernel<<<1, 256>>>((float*)d_out);
}

// round 12
// speedup vs baseline: 1.6491x; 1.0587x over previous
#include <cuda_runtime.h>
#include <cuda_bf16.h>
#include <math.h>
#include <stdint.h>
#define NI 16384
#define NB 256

__device__ float g_y1[102760448];
__device__ float g_y2[102760448];
__device__ float g_y3[8388608];
__device__ __nv_bfloat16 g_W2h[65536], g_W2l[65536];
__device__ __nv_bfloat16 g_W3h[3211264], g_W3l[3211264];
__device__ float g_Wc[32768];
__device__ float g_cb[64];
__device__ float g_mean[6][512], g_rstd[6][512];
__device__ float g_spart[16384];
__device__ float g_z[524288];
__device__ float g_loc[NI];
__device__ float g_klrow[NI];
__device__ int   g_arg[NB];
__device__ float g_term[NB];
__device__ float g_rec[NB];
__device__ float g_t1[131072];
__device__ float g_t2[1605632];
__device__ float g_t3[1605632];

__device__ __forceinline__ uint32_t smem_u32(const void* p) {
    uint32_t a;
    asm("{ .reg .u64 t; cvta.to.shared.u64 t, %1; cvt.u32.u64 %0, t; }" : "=r"(a) : "l"(p));
    return a;
}
__device__ __forceinline__ void ldsm4(uint32_t* r, uint32_t addr) {
    asm volatile("ldmatrix.sync.aligned.m8n8.x4.shared.b16 {%0,%1,%2,%3}, [%4];"
        : "=r"(r[0]), "=r"(r[1]), "=r"(r[2]), "=r"(r[3]) : "r"(addr));
}
__device__ __forceinline__ void mma_bf16(float* c, const uint32_t* a, const uint32_t* b) {
    asm volatile("mma.sync.aligned.m16n8k16.row.col.f32.bf16.bf16.f32 "
        "{%0,%1,%2,%3}, {%4,%5,%6,%7}, {%8,%9}, {%0,%1,%2,%3};"
        : "+f"(c[0]), "+f"(c[1]), "+f"(c[2]), "+f"(c[3])
        : "r"(a[0]), "r"(a[1]), "r"(a[2]), "r"(a[3]), "r"(b[0]), "r"(b[1]));
}

__device__ __forceinline__ float2 bsum2(float2 v) {
    __shared__ float2 sh[32];
    int lane = threadIdx.x & 31, w = threadIdx.x >> 5;
#pragma unroll
    for (int o = 16; o > 0; o >>= 1) { v.x += __shfl_xor_sync(~0u, v.x, o); v.y += __shfl_xor_sync(~0u, v.y, o); }
    __syncthreads();
    if (lane == 0) sh[w] = v;
    __syncthreads();
    int nw = (blockDim.x + 31) >> 5;
    if (w == 0) {
        v = (lane < nw) ? sh[lane] : make_float2(0.f, 0.f);
#pragma unroll
        for (int o = 16; o > 0; o >>= 1) { v.x += __shfl_xor_sync(~0u, v.x, o); v.y += __shfl_xor_sync(~0u, v.y, o); }
    }
    return v;
}

__global__ void prep_kernel(const float* W2, const float* W3, const float* Wm, const float* Wlv,
                            const float* W4, const float* b4, const float* bm, const float* blv) {
    int i = blockIdx.x * 256 + threadIdx.x;
    if (i < 65536) {
        float w = W2[i];
        __nv_bfloat16 h = __float2bfloat16(w);
        g_W2h[i] = h;
        g_W2l[i] = __float2bfloat16(w - __bfloat162float(h));
    }
    if (i < 3211264) {
        float w = W3[i];
        __nv_bfloat16 h = __float2bfloat16(w);
        g_W3h[i] = h;
        g_W3l[i] = __float2bfloat16(w - __bfloat162float(h));
    }
    if (i < 32768) {
        int ic = i >> 6, r = i & 63;
        const float* row = (r < 32) ? (Wm + r * 200) : (Wlv + (r - 32) * 200);
        float s = 0.f;
        for (int j = 0; j < 200; j++) s += row[j] * W4[j * 512 + ic];
        g_Wc[ic * 64 + r] = s;
        if (ic == 0) {
            float cb = (r < 32) ? bm[r] : blv[r - 32];
            for (int j = 0; j < 200; j++) cb += row[j] * b4[j];
            g_cb[r] = cb;
        }
    }
}

__global__ void __launch_bounds__(256) conv1_kernel(const float* __restrict__ bag, const float* __restrict__ W1) {
    __shared__ float xs[784], ws[512];
    int n = blockIdx.x, tid = threadIdx.x;
    for (int i = tid; i < 784; i += 256) xs[i] = bag[(size_t)n * 784 + i];
    for (int i = tid; i < 512; i += 256) ws[i] = W1[i];
    __syncthreads();
    int oc = tid >> 3, sub = tid & 7;
    float w[16];
#pragma unroll
    for (int t = 0; t < 16; t++) w[t] = ws[oc * 16 + t];
    for (int p = sub; p < 196; p += 8) {
        int oy = p / 14, ox = p - (p / 14) * 14;
        float a = 0.f;
#pragma unroll
        for (int ky = 0; ky < 4; ky++) {
            int iy = 2 * oy - 1 + ky;
            if ((unsigned)iy < 28u)
#pragma unroll
                for (int kx = 0; kx < 4; kx++) {
                    int ix = 2 * ox - 1 + kx;
                    if ((unsigned)ix < 28u) a += xs[iy * 28 + ix] * w[ky * 4 + kx];
                }
        }
        g_y1[(size_t)n * 6272 + oc * 196 + p] = a;
    }
}

__global__ void __launch_bounds__(256) stats_part(const float* __restrict__ src, int HW, int Nn, int sN, int sC, int sI) {
    int c = blockIdx.x, p = blockIdx.y, P = gridDim.y, tid = threadIdx.x;
    int total = Nn * HW;
    float s = 0.f, q = 0.f;
    for (int j = p * 256 + tid; j < total; j += P * 256) {
        int n = j / HW, i = j - n * HW;
        float v = src[(size_t)n * sN + (size_t)c * sC + (size_t)i * sI];
        s += v; q += v * v;
    }
    float2 r = bsum2(make_float2(s, q));
    if (tid == 0) { g_spart[(c * P + p) * 2] = r.x; g_spart[(c * P + p) * 2 + 1] = r.y; }
}

__global__ void stats_fin(int id, int P, int count) {
    int c = threadIdx.x;
    float s = 0.f, q = 0.f;
    for (int p = 0; p < P; p++) { s += g_spart[(c * P + p) * 2]; q += g_spart[(c * P + p) * 2 + 1]; }
    float m = s / count;
    g_mean[id][c] = m;
    g_rstd[id][c] = rsqrtf(q / count - m * m + 1e-5f);
}

#define C3_STRIDE 80
#define C3_BUF 10240
#define C3_AH 0
#define C3_AL 20480
#define C3_BH 40960
#define C3_BL 61440
#define C3_SMEM 81920

// ---- conv2 mma: LDG issued before MMA, STS after (latency overlap) ----
__global__ void __launch_bounds__(256) conv2_mma() {
    extern __shared__ char dsm[];
    __shared__ float m1s[32], r1s[32];
    uint32_t sb = smem_u32(dsm);
    int tid = threadIdx.x, lane = tid & 31, wid = tid >> 5;
    int wm = wid >> 2, wn = wid & 3;
    if (tid < 32) {
        float s = 0.f, q = 0.f;
#pragma unroll
        for (int p = 0; p < 8; p++) { s += g_spart[(tid * 8 + p) * 2]; q += g_spart[(tid * 8 + p) * 2 + 1]; }
        float cnt = (float)NI * 196.f, m = s / cnt;
        m1s[tid] = m; r1s[tid] = rsqrtf(q / cnt - m * m + 1e-5f);
    }
    int M0 = blockIdx.x * 128;
    int aoff[4][4]; unsigned aval = 0;
    int c4 = (tid & 7) << 2, hb = c4 >> 4;
#pragma unroll
    for (int q = 0; q < 4; q++) {
        int f = q * 256 + tid, row = f >> 3;
        int m = M0 + row, n = m / 49, p = m - n * 49;
        int oy = p / 7, ox = p - (p / 7) * 7;
#pragma unroll
        for (int j = 0; j < 4; j++) {
            int r = (c4 + j) & 15;
            int iy = 2 * oy - 1 + (r >> 2), ix = 2 * ox - 1 + (r & 3);
            if (iy >= 0 && iy < 14 && ix >= 0 && ix < 14) aval |= 1u << (q * 4 + j);
            aoff[q][j] = n * 6272 + iy * 14 + ix;
        }
    }
    __syncthreads();
    float ar[4][4]; uint2 bhr[4], blr[4]; float l_mc, l_rc;

#define LOADG2(kt) do { \
    int ic = (kt) * 2 + hb; \
    l_mc = m1s[ic]; l_rc = r1s[ic]; \
    int add = ic * 196; \
    _Pragma("unroll") \
    for (int q = 0; q < 4; q++) { \
        int f = q * 256 + tid, row = f >> 3; \
        _Pragma("unroll") \
        for (int j = 0; j < 4; j++) \
            ar[q][j] = (aval & (1u << (q * 4 + j))) ? g_y1[aoff[q][j] + add] : 0.f; \
        size_t bi = (size_t)row * 512 + (kt) * 32 + c4; \
        bhr[q] = *(const uint2*)&g_W2h[bi]; \
        blr[q] = *(const uint2*)&g_W2l[bi]; \
    } } while (0)

#define STORE2(buf) do { \
    _Pragma("unroll") \
    for (int q = 0; q < 4; q++) { \
        int f = q * 256 + tid, row = f >> 3; \
        unsigned short hs[4], ls[4]; \
        _Pragma("unroll") \
        for (int j = 0; j < 4; j++) { \
            float t = (aval & (1u << (q * 4 + j))) ? fmaxf((ar[q][j] - l_mc) * l_rc, 0.f) : 0.f; \
            __nv_bfloat16 h = __float2bfloat16(t); \
            hs[j] = __bfloat16_as_ushort(h); \
            ls[j] = __bfloat16_as_ushort(__float2bfloat16(t - __bfloat162float(h))); \
        } \
        uint32_t off = (buf) * C3_BUF + row * C3_STRIDE + c4 * 2; \
        *(uint2*)(dsm + C3_AH + off) = make_uint2((uint32_t)hs[0] | ((uint32_t)hs[1] << 16), (uint32_t)hs[2] | ((uint32_t)hs[3] << 16)); \
        *(uint2*)(dsm + C3_AL + off) = make_uint2((uint32_t)ls[0] | ((uint32_t)ls[1] << 16), (uint32_t)ls[2] | ((uint32_t)ls[3] << 16)); \
        *(uint2*)(dsm + C3_BH + off) = bhr[q]; \
        *(uint2*)(dsm + C3_BL + off) = blr[q]; \
    } } while (0)

    float c[4][4][4] = {};
    LOADG2(0); STORE2(0);
    __syncthreads();
    int lm = lane & 15, lkb = (lane >> 4) * 16;
    for (int ch = 0; ch < 16; ch++) {
        int cur = ch & 1;
        if (ch < 15) LOADG2(ch + 1);
        uint32_t aA = sb + cur * C3_BUF + (wm * 64 + lm) * C3_STRIDE + lkb;
        uint32_t aB = sb + cur * C3_BUF + (wn * 32 + lm) * C3_STRIDE + lkb;
#pragma unroll
        for (int ks = 0; ks < 2; ks++) {
            uint32_t kb = ks * 32;
            uint32_t ah[4][4], al[4][4], bh[2][4], bl[2][4];
#pragma unroll
            for (int mt = 0; mt < 4; mt++) {
                ldsm4(ah[mt], aA + C3_AH + mt * (16 * C3_STRIDE) + kb);
                ldsm4(al[mt], aA + C3_AL + mt * (16 * C3_STRIDE) + kb);
            }
#pragma unroll
            for (int np = 0; np < 2; np++) {
                ldsm4(bh[np], aB + C3_BH + np * (16 * C3_STRIDE) + kb);
                ldsm4(bl[np], aB + C3_BL + np * (16 * C3_STRIDE) + kb);
            }
#pragma unroll
            for (int mt = 0; mt < 4; mt++)
#pragma unroll
                for (int nt = 0; nt < 4; nt++) {
                    int np = nt >> 1, hi = nt & 1;
                    uint32_t b2h[2] = {bh[np][hi], bh[np][hi + 2]};
                    uint32_t b2l[2] = {bl[np][hi], bl[np][hi + 2]};
                    mma_bf16(c[mt][nt], ah[mt], b2h);
                    mma_bf16(c[mt][nt], ah[mt], b2l);
                    mma_bf16(c[mt][nt], al[mt], b2h);
                }
        }
        if (ch < 15) STORE2(cur ^ 1);
        __syncthreads();
    }
#undef LOADG2
#undef STORE2
    float* cs = (float*)dsm;
#pragma unroll
    for (int mt = 0; mt < 4; mt++)
#pragma unroll
        for (int nt = 0; nt < 4; nt++) {
            int r0 = wm * 64 + mt * 16 + (lane >> 2);
            int cc = wn * 32 + nt * 8 + (lane & 3) * 2;
            cs[r0 * 133 + cc] = c[mt][nt][0];
            cs[r0 * 133 + cc + 1] = c[mt][nt][1];
            cs[(r0 + 8) * 133 + cc] = c[mt][nt][2];
            cs[(r0 + 8) * 133 + cc + 1] = c[mt][nt][3];
        }
    __syncthreads();
    for (int i = tid; i < 16384; i += 256) {
        int oc = i >> 7, row = i & 127;
        int m = M0 + row, n = m / 49, p = m - n * 49;
        g_y2[(size_t)n * 6272 + oc * 49 + p] = cs[row * 133 + oc];
    }
}

// ---- conv3 mma: same overlap structure ----
__global__ void __launch_bounds__(256) conv3_mma() {
    extern __shared__ char dsm[];
    __shared__ float m2s[128], r2s[128];
    uint32_t sb = smem_u32(dsm);
    int tid = threadIdx.x, lane = tid & 31, wid = tid >> 5;
    int wm = wid >> 2, wn = wid & 3;
    if (tid < 128) {
        float s = 0.f, q = 0.f;
#pragma unroll
        for (int p = 0; p < 8; p++) { s += g_spart[(tid * 8 + p) * 2]; q += g_spart[(tid * 8 + p) * 2 + 1]; }
        float cnt = (float)NI * 49.f, m = s / cnt;
        m2s[tid] = m; r2s[tid] = rsqrtf(q / cnt - m * m + 1e-5f);
    }
    __syncthreads();
    int M0 = blockIdx.x * 128, N0 = blockIdx.y * 128;
    int arow = tid >> 3, ac4 = (tid & 7) << 2;
    float4 vr[4]; uint2 bhr[4], blr[4];

#define LOADG3(k0) do { \
    _Pragma("unroll") \
    for (int q = 0; q < 4; q++) { \
        int row = q * 32 + arow; \
        vr[q] = *(const float4*)&g_y2[(size_t)(M0 + row) * 6272 + (k0) + ac4]; \
        size_t bi = (size_t)(N0 + row) * 6272 + (k0) + ac4; \
        bhr[q] = *(const uint2*)&g_W3h[bi]; \
        blr[q] = *(const uint2*)&g_W3l[bi]; \
    } } while (0)

#define STORE3(buf, k0) do { \
    _Pragma("unroll") \
    for (int q = 0; q < 4; q++) { \
        int row = q * 32 + arow; \
        float xx[4] = {vr[q].x, vr[q].y, vr[q].z, vr[q].w}; \
        unsigned short hs[4], ls[4]; \
        _Pragma("unroll") \
        for (int j = 0; j < 4; j++) { \
            int cch = ((k0) + ac4 + j) / 49; \
            float t = fmaxf((xx[j] - m2s[cch]) * r2s[cch], 0.f); \
            __nv_bfloat16 h = __float2bfloat16(t); \
            hs[j] = __bfloat16_as_ushort(h); \
            ls[j] = __bfloat16_as_ushort(__float2bfloat16(t - __bfloat162float(h))); \
        } \
        uint32_t off = (buf) * C3_BUF + row * C3_STRIDE + ac4 * 2; \
        *(uint2*)(dsm + C3_AH + off) = make_uint2((uint32_t)hs[0] | ((uint32_t)hs[1] << 16), (uint32_t)hs[2] | ((uint32_t)hs[3] << 16)); \
        *(uint2*)(dsm + C3_AL + off) = make_uint2((uint32_t)ls[0] | ((uint32_t)ls[1] << 16), (uint32_t)ls[2] | ((uint32_t)ls[3] << 16)); \
        *(uint2*)(dsm + C3_BH + off) = bhr[q]; \
        *(uint2*)(dsm + C3_BL + off) = blr[q]; \
    } } while (0)

    float c[4][4][4] = {};
    LOADG3(0); STORE3(0, 0);
    __syncthreads();
    int lm = lane & 15, lkb = (lane >> 4) * 16;
    for (int ch = 0; ch < 196; ch++) {
        int cur = ch & 1;
        if (ch < 195) LOADG3((ch + 1) * 32);
        uint32_t aA = sb + cur * C3_BUF + (wm * 64 + lm) * C3_STRIDE + lkb;
        uint32_t aB = sb + cur * C3_BUF + (wn * 32 + lm) * C3_STRIDE + lkb;
#pragma unroll
        for (int ks = 0; ks < 2; ks++) {
            uint32_t kb = ks * 32;
            uint32_t ah[4][4], al[4][4], bh[2][4], bl[2][4];
#pragma unroll
            for (int mt = 0; mt < 4; mt++) {
                ldsm4(ah[mt], aA + C3_AH + mt * (16 * C3_STRIDE) + kb);
                ldsm4(al[mt], aA + C3_AL + mt * (16 * C3_STRIDE) + kb);
            }
#pragma unroll
            for (int np = 0; np < 2; np++) {
                ldsm4(bh[np], aB + C3_BH + np * (16 * C3_STRIDE) + kb);
                ldsm4(bl[np], aB + C3_BL + np * (16 * C3_STRIDE) + kb);
            }
#pragma unroll
            for (int mt = 0; mt < 4; mt++)
#pragma unroll
                for (int nt = 0; nt < 4; nt++) {
                    int np = nt >> 1, hi = nt & 1;
                    uint32_t b2h[2] = {bh[np][hi], bh[np][hi + 2]};
                    uint32_t b2l[2] = {bl[np][hi], bl[np][hi + 2]};
                    mma_bf16(c[mt][nt], ah[mt], b2h);
                    mma_bf16(c[mt][nt], ah[mt], b2l);
                    mma_bf16(c[mt][nt], al[mt], b2h);
                }
        }
        if (ch < 195) STORE3(cur ^ 1, (ch + 1) * 32);
        __syncthreads();
    }
#undef LOADG3
#undef STORE3
#pragma unroll
    for (int mt = 0; mt < 4; mt++)
#pragma unroll
        for (int nt = 0; nt < 4; nt++) {
            int row = M0 + wm * 64 + mt * 16 + (lane >> 2);
            int col = N0 + wn * 32 + nt * 8 + (lane & 3) * 2;
            *(float2*)&g_y3[(size_t)row * 512 + col] = make_float2(c[mt][nt][0], c[mt][nt][1]);
            *(float2*)&g_y3[(size_t)(row + 8) * 512 + col] = make_float2(c[mt][nt][2], c[mt][nt][3]);
        }
}

// ---- latent: 4 instances per block (Wc reuse x4) ----
__global__ void __launch_bounds__(256) latent_kernel(const float* __restrict__ eps, const float* __restrict__ Wfc,
                                                     const float* __restrict__ bfc) {
    __shared__ float sa[4][512];
    __shared__ float sres[4][64];
    int n0 = blockIdx.x * 4, tid = threadIdx.x;
    for (int i = tid; i < 2048; i += 256) {
        int inst = i >> 9, ic = i & 511;
        sa[inst][ic] = fmaxf((g_y3[(size_t)(n0 + inst) * 512 + ic] - g_mean[2][ic]) * g_rstd[2][ic], 0.f);
    }
    __syncthreads();
    int inst = tid >> 6, r = tid & 63;
    float dot = g_cb[r];
#pragma unroll 8
    for (int ic = 0; ic < 512; ic++) dot += sa[inst][ic] * g_Wc[ic * 64 + r];
    sres[inst][r] = dot;
    __syncthreads();
    if (r < 32) {
        float mu = sres[inst][r], lv = sres[inst][r + 32], sd = expf(0.5f * lv);
        float z = mu + sd * eps[(size_t)(n0 + inst) * 32 + r];
        g_z[(size_t)(n0 + inst) * 32 + r] = z;
        float kl = mu * mu + sd * sd - lv - 1.f;
        float lc = z * Wfc[r];
#pragma unroll
        for (int o = 16; o > 0; o >>= 1) { kl += __shfl_xor_sync(~0u, kl, o); lc += __shfl_xor_sync(~0u, lc, o); }
        if (r == 0) { g_klrow[n0 + inst] = kl; g_loc[n0 + inst] = lc + bfc[0]; }
    }
}

__global__ void __launch_bounds__(256) bagmax_kernel(const int* __restrict__ bi, const float* __restrict__ lab) {
    __shared__ float sv[8]; __shared__ int si[8]; __shared__ float smx;
    int b = blockIdx.x, tid = threadIdx.x, lane = tid & 31, w = tid >> 5;
    float mx = -3.4e38f;
    for (int n = tid; n < NI; n += 256) if (bi[n] == b) mx = fmaxf(mx, g_loc[n]);
#pragma unroll
    for (int o = 16; o > 0; o >>= 1) mx = fmaxf(mx, __shfl_xor_sync(~0u, mx, o));
    if (lane == 0) sv[w] = mx;
    __syncthreads();
    if (tid == 0) { float v = sv[0]; for (int i = 1; i < 8; i++) v = fmaxf(v, sv[i]); smx = v; }
    __syncthreads();
    float mval = smx; int mn = NI;
    for (int n = tid; n < NI; n += 256) if (bi[n] == b && g_loc[n] == mval) mn = min(mn, n);
#pragma unroll
    for (int o = 16; o > 0; o >>= 1) mn = min(mn, __shfl_xor_sync(~0u, mn, o));
    if (lane == 0) si[w] = mn;
    __syncthreads();
    if (tid == 0) {
        int a = si[0]; for (int i = 1; i < 8; i++) a = min(a, si[i]);
        g_arg[b] = a;
        float M = g_loc[a], y = lab[b];
        g_term[b] = fmaxf(M, 0.f) - M * y + log1pf(expf(-fabsf(M)));
    }
}

__global__ void __launch_bounds__(512) dec1_kernel(const float* __restrict__ D1) {
    __shared__ float zz[32];
    int b = blockIdx.x, tid = threadIdx.x;
    if (tid < 32) zz[tid] = g_z[(size_t)g_arg[b] * 32 + tid];
    __syncthreads();
    float a = 0.f;
#pragma unroll
    for (int ic = 0; ic < 32; ic++) a += zz[ic] * D1[ic * 512 + tid];
    g_t1[b * 512 + tid] = a;
}

__global__ void __launch_bounds__(256) dec2_kernel(const float* __restrict__ D2) {
    __shared__ float at[4096];
    int B0 = blockIdx.x * 8, tid = threadIdx.x;
    for (int i = tid; i < 4096; i += 256) {
        int bl = i >> 9, ic = i & 511;
        at[ic * 8 + bl] = fmaxf((g_t1[(B0 + bl) * 512 + ic] - g_mean[3][ic]) * g_rstd[3][ic], 0.f);
    }
    __syncthreads();
    for (int o = tid; o < 6272; o += 256) {
        float acc[8] = {};
        for (int ic = 0; ic < 512; ic++) {
            float w = D2[(size_t)ic * 6272 + o];
            float4 x0 = *(const float4*)&at[ic * 8], x1 = *(const float4*)&at[ic * 8 + 4];
            acc[0] += x0.x * w; acc[1] += x0.y * w; acc[2] += x0.z * w; acc[3] += x0.w * w;
            acc[4] += x1.x * w; acc[5] += x1.y * w; acc[6] += x1.z * w; acc[7] += x1.w * w;
        }
#pragma unroll
        for (int j = 0; j < 8; j++) g_t2[(size_t)(B0 + j) * 6272 + o] = acc[j];
    }
}

__global__ void __launch_bounds__(256) dec3_kernel(const float* __restrict__ D3) {
    __shared__ float a2[6272], wt[2048];
    int b = blockIdx.x, tid = threadIdx.x;
    for (int i = tid; i < 6272; i += 256) {
        int c = i / 49;
        a2[i] = fmaxf((g_t2[(size_t)b * 6272 + i] - g_mean[4][c]) * g_rstd[4][c], 0.f);
    }
    __syncthreads();
    int oy = tid / 14, ox = tid - (tid / 14) * 14;
    for (int oc = 0; oc < 32; oc++) {
        for (int i = tid; i < 2048; i += 256) wt[i] = D3[(i >> 4) * 512 + oc * 16 + (i & 15)];
        __syncthreads();
        if (tid < 196) {
            float a = 0.f;
#pragma unroll
            for (int ky = 0; ky < 4; ky++) {
                int t = oy + 1 - ky;
                if (t >= 0 && !(t & 1) && (t >> 1) < 7) {
                    int iy = t >> 1;
#pragma unroll
                    for (int kx = 0; kx < 4; kx++) {
                        int u = ox + 1 - kx;
                        if (u >= 0 && !(u & 1) && (u >> 1) < 7) {
                            int sB = iy * 7 + (u >> 1), wB = ky * 4 + kx;
#pragma unroll 16
                            for (int ic = 0; ic < 128; ic++) a += a2[ic * 49 + sB] * wt[ic * 16 + wB];
                        }
                    }
                }
            }
            g_t3[(size_t)b * 6272 + oc * 196 + tid] = a;
        }
        __syncthreads();
    }
}

__global__ void __launch_bounds__(256) dec4_kernel(const float* __restrict__ D4, const float* __restrict__ d4,
                                                   const float* __restrict__ bag) {
    __shared__ float a3[6272], w4s[512];
    int b = blockIdx.x, tid = threadIdx.x;
    for (int i = tid; i < 6272; i += 256) {
        int c = i / 196;
        a3[i] = fmaxf((g_t3[(size_t)b * 6272 + i] - g_mean[5][c]) * g_rstd[5][c], 0.f);
    }
    for (int i = tid; i < 512; i += 256) w4s[i] = D4[i];
    __syncthreads();
    float bias = d4[0]; int arg = g_arg[b];
    float sq = 0.f;
    for (int o = tid; o < 784; o += 256) {
        int oy = o / 28, ox = o - (o / 28) * 28;
        float a = bias;
#pragma unroll
        for (int ky = 0; ky < 4; ky++) {
            int t = oy + 1 - ky;
            if (t >= 0 && !(t & 1) && (t >> 1) < 14) {
                int iy = t >> 1;
#pragma unroll
                for (int kx = 0; kx < 4; kx++) {
                    int u = ox + 1 - kx;
                    if (u >= 0 && !(u & 1) && (u >> 1) < 14) {
                        int sB = iy * 14 + (u >> 1), wB = ky * 4 + kx;
#pragma unroll
                        for (int ic = 0; ic < 32; ic++) a += a3[ic * 196 + sB] * w4s[ic * 16 + wB];
                    }
                }
            }
        }
        float s = 1.f / (1.f + expf(-a));
        float d = s - bag[(size_t)arg * 784 + o];
        sq += d * d;
    }
    float2 r = bsum2(make_float2(sq, 0.f));
    if (tid == 0) g_rec[b] = r.x;
}

__global__ void __launch_bounds__(256) final_kernel(float* __restrict__ out) {
    int tid = threadIdx.x;
    float kl = 0.f;
    for (int n = tid; n < NI; n += 256) kl += g_klrow[n];
    float tm = 0.f, rc = 0.f;
    if (tid < NB) { tm = g_term[tid]; rc = g_rec[tid]; }
    float2 a = bsum2(make_float2(kl, tm));
    __syncthreads();
    float2 bb = bsum2(make_float2(rc, 0.f));
    if (tid == 0) {
        out[0] = bb.x / (256.f * 784.f);
        out[1] = 0.5f * a.x / (16384.f * 32.f);
        out[2] = a.y / 256.f;
    }
}

extern "C" void kernel_launch(void* const* d_in, const int* in_sizes, int n_in,
                              void* d_out, int out_size) {
    const float* bag = (const float*)d_in[0];
    const int* bag_idx = (const int*)d_in[1];
    const float* lab = (const float*)d_in[2];
    const float* eps = (const float*)d_in[3];
    const float* W1 = (const float*)d_in[4];
    const float* W2 = (const float*)d_in[6];
    const float* W3 = (const float*)d_in[8];
    const float* W4 = (const float*)d_in[10];
    const float* b4 = (const float*)d_in[11];
    const float* Wm = (const float*)d_in[12];
    const float* bm = (const float*)d_in[13];
    const float* Wlv = (const float*)d_in[14];
    const float* blv = (const float*)d_in[15];
    const float* Wfc = (const float*)d_in[16];
    const float* bfc = (const float*)d_in[17];
    const float* D1 = (const float*)d_in[18];
    const float* D2 = (const float*)d_in[20];
    const float* D3 = (const float*)d_in[22];
    const float* D4 = (const float*)d_in[24];
    const float* d4 = (const float*)d_in[25];

    float *y1, *y2, *y3, *t1, *t2, *t3;
    cudaGetSymbolAddress((void**)&y1, g_y1);
    cudaGetSymbolAddress((void**)&y2, g_y2);
    cudaGetSymbolAddress((void**)&y3, g_y3);
    cudaGetSymbolAddress((void**)&t1, g_t1);
    cudaGetSymbolAddress((void**)&t2, g_t2);
    cudaGetSymbolAddress((void**)&t3, g_t3);

    cudaFuncSetAttribute(conv2_mma, cudaFuncAttributeMaxDynamicSharedMemorySize, C3_SMEM);
    cudaFuncSetAttribute(conv3_mma, cudaFuncAttributeMaxDynamicSharedMemorySize, C3_SMEM);

    prep_kernel<<<12544, 256>>>(W2, W3, Wm, Wlv, W4, b4, bm, blv);
    conv1_kernel<<<NI, 256>>>(bag, W1);
    stats_part<<<dim3(32, 8), 256>>>(y1, 196, NI, 6272, 196, 1);
    conv2_mma<<<6272, 256, C3_SMEM>>>();
    stats_part<<<dim3(128, 8), 256>>>(y2, 49, NI, 6272, 49, 1);
    conv3_mma<<<dim3(128, 4), 256, C3_SMEM>>>();
    stats_part<<<dim3(512, 8), 256>>>(y3, 1, NI, 512, 1, 0);
    stats_fin<<<1, 512>>>(2, 8, NI);
    latent_kernel<<<4096, 256>>>(eps, Wfc, bfc);
    bagmax_kernel<<<NB, 256>>>(bag_idx, lab);
    dec1_kernel<<<NB, 512>>>(D1);
    stats_part<<<dim3(512, 2), 256>>>(t1, 1, NB, 512, 1, 0);
    stats_fin<<<1, 512>>>(3, 2, NB);
    dec2_kernel<<<32, 256>>>(D2);
    stats_part<<<dim3(128, 2), 256>>>(t2, 49, NB, 6272, 49, 1);
    stats_fin<<<1, 128>>>(4, 2, NB * 49);
    dec3_kernel<<<NB, 256>>>(D3);
    stats_part<<<dim3(32, 2), 256>>>(t3, 196, NB, 6272, 196, 1);
    stats_fin<<<1, 32>>>(5, 2, NB * 196);
    dec4_kernel<<<NB, 256>>>(D4, d4, bag);
    final_kernel<<<1, 256>>>((float*)d_out);
}

// round 13
// speedup vs baseline: 1.7418x; 1.0562x over previous
#include <cuda_runtime.h>
#include <cuda_bf16.h>
#include <math.h>
#include <stdint.h>
#define NI 16384
#define NB 256

__device__ float g_y1[102760448];
__device__ float g_y2[102760448];
__device__ float g_y3[8388608];
__device__ __nv_bfloat16 g_W2h[65536], g_W2l[65536];
__device__ __nv_bfloat16 g_W3h[3211264], g_W3l[3211264];
__device__ float g_Wc[32768];
__device__ float g_cb[64];
__device__ float g_mean[6][512], g_rstd[6][512];
__device__ float g_spart[16384];
__device__ float g_z[524288];
__device__ float g_loc[NI];
__device__ float g_klrow[NI];
__device__ int   g_arg[NB];
__device__ float g_term[NB];
__device__ float g_rec[NB];
__device__ float g_t1[131072];
__device__ float g_t2[1605632];
__device__ float g_t3[1605632];

__device__ __forceinline__ uint32_t smem_u32(const void* p) {
    uint32_t a;
    asm("{ .reg .u64 t; cvta.to.shared.u64 t, %1; cvt.u32.u64 %0, t; }" : "=r"(a) : "l"(p));
    return a;
}
__device__ __forceinline__ void ldsm4(uint32_t* r, uint32_t addr) {
    asm volatile("ldmatrix.sync.aligned.m8n8.x4.shared.b16 {%0,%1,%2,%3}, [%4];"
        : "=r"(r[0]), "=r"(r[1]), "=r"(r[2]), "=r"(r[3]) : "r"(addr));
}
__device__ __forceinline__ void mma_bf16(float* c, const uint32_t* a, const uint32_t* b) {
    asm volatile("mma.sync.aligned.m16n8k16.row.col.f32.bf16.bf16.f32 "
        "{%0,%1,%2,%3}, {%4,%5,%6,%7}, {%8,%9}, {%0,%1,%2,%3};"
        : "+f"(c[0]), "+f"(c[1]), "+f"(c[2]), "+f"(c[3])
        : "r"(a[0]), "r"(a[1]), "r"(a[2]), "r"(a[3]), "r"(b[0]), "r"(b[1]));
}

__device__ __forceinline__ float2 bsum2(float2 v) {
    __shared__ float2 sh[32];
    int lane = threadIdx.x & 31, w = threadIdx.x >> 5;
#pragma unroll
    for (int o = 16; o > 0; o >>= 1) { v.x += __shfl_xor_sync(~0u, v.x, o); v.y += __shfl_xor_sync(~0u, v.y, o); }
    __syncthreads();
    if (lane == 0) sh[w] = v;
    __syncthreads();
    int nw = (blockDim.x + 31) >> 5;
    if (w == 0) {
        v = (lane < nw) ? sh[lane] : make_float2(0.f, 0.f);
#pragma unroll
        for (int o = 16; o > 0; o >>= 1) { v.x += __shfl_xor_sync(~0u, v.x, o); v.y += __shfl_xor_sync(~0u, v.y, o); }
    }
    return v;
}

__global__ void prep_kernel(const float* W2, const float* W3, const float* Wm, const float* Wlv,
                            const float* W4, const float* b4, const float* bm, const float* blv) {
    int i = blockIdx.x * 256 + threadIdx.x;
    if (i < 65536) {
        float w = W2[i];
        __nv_bfloat16 h = __float2bfloat16(w);
        g_W2h[i] = h;
        g_W2l[i] = __float2bfloat16(w - __bfloat162float(h));
    }
    if (i < 3211264) {
        float w = W3[i];
        __nv_bfloat16 h = __float2bfloat16(w);
        g_W3h[i] = h;
        g_W3l[i] = __float2bfloat16(w - __bfloat162float(h));
    }
    if (i < 32768) {
        int ic = i >> 6, r = i & 63;
        const float* row = (r < 32) ? (Wm + r * 200) : (Wlv + (r - 32) * 200);
        float s = 0.f;
        for (int j = 0; j < 200; j++) s += row[j] * W4[j * 512 + ic];
        g_Wc[ic * 64 + r] = s;
        if (ic == 0) {
            float cb = (r < 32) ? bm[r] : blv[r - 32];
            for (int j = 0; j < 200; j++) cb += row[j] * b4[j];
            g_cb[r] = cb;
        }
    }
}

__global__ void __launch_bounds__(256) conv1_kernel(const float* __restrict__ bag, const float* __restrict__ W1) {
    __shared__ float xs[784], ws[512];
    int n = blockIdx.x, tid = threadIdx.x;
    for (int i = tid; i < 784; i += 256) xs[i] = bag[(size_t)n * 784 + i];
    for (int i = tid; i < 512; i += 256) ws[i] = W1[i];
    __syncthreads();
    int oc = tid >> 3, sub = tid & 7;
    float w[16];
#pragma unroll
    for (int t = 0; t < 16; t++) w[t] = ws[oc * 16 + t];
    for (int p = sub; p < 196; p += 8) {
        int oy = p / 14, ox = p - (p / 14) * 14;
        float a = 0.f;
#pragma unroll
        for (int ky = 0; ky < 4; ky++) {
            int iy = 2 * oy - 1 + ky;
            if ((unsigned)iy < 28u)
#pragma unroll
                for (int kx = 0; kx < 4; kx++) {
                    int ix = 2 * ox - 1 + kx;
                    if ((unsigned)ix < 28u) a += xs[iy * 28 + ix] * w[ky * 4 + kx];
                }
        }
        g_y1[(size_t)n * 6272 + oc * 196 + p] = a;
    }
}

__global__ void __launch_bounds__(256) stats_part(const float* __restrict__ src, int HW, int Nn, int sN, int sC, int sI) {
    int c = blockIdx.x, p = blockIdx.y, P = gridDim.y, tid = threadIdx.x;
    int total = Nn * HW;
    float s = 0.f, q = 0.f;
    for (int j = p * 256 + tid; j < total; j += P * 256) {
        int n = j / HW, i = j - n * HW;
        float v = src[(size_t)n * sN + (size_t)c * sC + (size_t)i * sI];
        s += v; q += v * v;
    }
    float2 r = bsum2(make_float2(s, q));
    if (tid == 0) { g_spart[(c * P + p) * 2] = r.x; g_spart[(c * P + p) * 2 + 1] = r.y; }
}

__global__ void stats_fin(int id, int P, int count) {
    int c = threadIdx.x;
    float s = 0.f, q = 0.f;
    for (int p = 0; p < P; p++) { s += g_spart[(c * P + p) * 2]; q += g_spart[(c * P + p) * 2 + 1]; }
    float m = s / count;
    g_mean[id][c] = m;
    g_rstd[id][c] = rsqrtf(q / count - m * m + 1e-5f);
}

#define C3_STRIDE 80
#define C3_BUF 10240
#define C3_AH 0
#define C3_AL 20480
#define C3_BH 40960
#define C3_BL 61440
#define C3_SMEM 81920

// ---- conv2 mma: 512 threads (16 warps, 32x32 per warp), LDG||MMA overlap ----
__global__ void __launch_bounds__(512) conv2_mma() {
    extern __shared__ char dsm[];
    __shared__ float m1s[32], r1s[32];
    uint32_t sb = smem_u32(dsm);
    int tid = threadIdx.x, lane = tid & 31, wid = tid >> 5;
    int wm = wid >> 2, wn = wid & 3;
    if (tid < 32) {
        float s = 0.f, q = 0.f;
#pragma unroll
        for (int p = 0; p < 8; p++) { s += g_spart[(tid * 8 + p) * 2]; q += g_spart[(tid * 8 + p) * 2 + 1]; }
        float cnt = (float)NI * 196.f, m = s / cnt;
        m1s[tid] = m; r1s[tid] = rsqrtf(q / cnt - m * m + 1e-5f);
    }
    int M0 = blockIdx.x * 128;
    int aoff[2][4]; unsigned aval = 0;
    int c4 = (tid & 7) << 2, hb = c4 >> 4;
#pragma unroll
    for (int q = 0; q < 2; q++) {
        int f = q * 512 + tid, row = f >> 3;
        int m = M0 + row, n = m / 49, p = m - n * 49;
        int oy = p / 7, ox = p - (p / 7) * 7;
#pragma unroll
        for (int j = 0; j < 4; j++) {
            int r = (c4 + j) & 15;
            int iy = 2 * oy - 1 + (r >> 2), ix = 2 * ox - 1 + (r & 3);
            if (iy >= 0 && iy < 14 && ix >= 0 && ix < 14) aval |= 1u << (q * 4 + j);
            aoff[q][j] = n * 6272 + iy * 14 + ix;
        }
    }
    __syncthreads();
    float ar[2][4]; uint2 bhr[2], blr[2]; float l_mc, l_rc;

#define LOADG2(kt) do { \
    int ic = (kt) * 2 + hb; \
    l_mc = m1s[ic]; l_rc = r1s[ic]; \
    int add = ic * 196; \
    _Pragma("unroll") \
    for (int q = 0; q < 2; q++) { \
        int f = q * 512 + tid, row = f >> 3; \
        _Pragma("unroll") \
        for (int j = 0; j < 4; j++) \
            ar[q][j] = (aval & (1u << (q * 4 + j))) ? g_y1[aoff[q][j] + add] : 0.f; \
        size_t bi = (size_t)row * 512 + (kt) * 32 + c4; \
        bhr[q] = *(const uint2*)&g_W2h[bi]; \
        blr[q] = *(const uint2*)&g_W2l[bi]; \
    } } while (0)

#define STORE2(buf) do { \
    _Pragma("unroll") \
    for (int q = 0; q < 2; q++) { \
        int f = q * 512 + tid, row = f >> 3; \
        unsigned short hs[4], ls[4]; \
        _Pragma("unroll") \
        for (int j = 0; j < 4; j++) { \
            float t = (aval & (1u << (q * 4 + j))) ? fmaxf((ar[q][j] - l_mc) * l_rc, 0.f) : 0.f; \
            __nv_bfloat16 h = __float2bfloat16(t); \
            hs[j] = __bfloat16_as_ushort(h); \
            ls[j] = __bfloat16_as_ushort(__float2bfloat16(t - __bfloat162float(h))); \
        } \
        uint32_t off = (buf) * C3_BUF + row * C3_STRIDE + c4 * 2; \
        *(uint2*)(dsm + C3_AH + off) = make_uint2((uint32_t)hs[0] | ((uint32_t)hs[1] << 16), (uint32_t)hs[2] | ((uint32_t)hs[3] << 16)); \
        *(uint2*)(dsm + C3_AL + off) = make_uint2((uint32_t)ls[0] | ((uint32_t)ls[1] << 16), (uint32_t)ls[2] | ((uint32_t)ls[3] << 16)); \
        *(uint2*)(dsm + C3_BH + off) = bhr[q]; \
        *(uint2*)(dsm + C3_BL + off) = blr[q]; \
    } } while (0)

    float c[2][4][4] = {};
    LOADG2(0); STORE2(0);
    __syncthreads();
    int lm = lane & 15, lkb = (lane >> 4) * 16;
    for (int ch = 0; ch < 16; ch++) {
        int cur = ch & 1;
        if (ch < 15) LOADG2(ch + 1);
        uint32_t aA = sb + cur * C3_BUF + (wm * 32 + lm) * C3_STRIDE + lkb;
        uint32_t aB = sb + cur * C3_BUF + (wn * 32 + lm) * C3_STRIDE + lkb;
#pragma unroll
        for (int ks = 0; ks < 2; ks++) {
            uint32_t kb = ks * 32;
            uint32_t ah[2][4], al[2][4], bh[2][4], bl[2][4];
#pragma unroll
            for (int mt = 0; mt < 2; mt++) {
                ldsm4(ah[mt], aA + C3_AH + mt * (16 * C3_STRIDE) + kb);
                ldsm4(al[mt], aA + C3_AL + mt * (16 * C3_STRIDE) + kb);
            }
#pragma unroll
            for (int np = 0; np < 2; np++) {
                ldsm4(bh[np], aB + C3_BH + np * (16 * C3_STRIDE) + kb);
                ldsm4(bl[np], aB + C3_BL + np * (16 * C3_STRIDE) + kb);
            }
#pragma unroll
            for (int mt = 0; mt < 2; mt++)
#pragma unroll
                for (int nt = 0; nt < 4; nt++) {
                    int np = nt >> 1, hi = nt & 1;
                    uint32_t b2h[2] = {bh[np][hi], bh[np][hi + 2]};
                    uint32_t b2l[2] = {bl[np][hi], bl[np][hi + 2]};
                    mma_bf16(c[mt][nt], ah[mt], b2h);
                    mma_bf16(c[mt][nt], ah[mt], b2l);
                    mma_bf16(c[mt][nt], al[mt], b2h);
                }
        }
        if (ch < 15) STORE2(cur ^ 1);
        __syncthreads();
    }
#undef LOADG2
#undef STORE2
    float* cs = (float*)dsm;
#pragma unroll
    for (int mt = 0; mt < 2; mt++)
#pragma unroll
        for (int nt = 0; nt < 4; nt++) {
            int r0 = wm * 32 + mt * 16 + (lane >> 2);
            int cc = wn * 32 + nt * 8 + (lane & 3) * 2;
            cs[r0 * 133 + cc] = c[mt][nt][0];
            cs[r0 * 133 + cc + 1] = c[mt][nt][1];
            cs[(r0 + 8) * 133 + cc] = c[mt][nt][2];
            cs[(r0 + 8) * 133 + cc + 1] = c[mt][nt][3];
        }
    __syncthreads();
    for (int i = tid; i < 16384; i += 512) {
        int oc = i >> 7, row = i & 127;
        int m = M0 + row, n = m / 49, p = m - n * 49;
        g_y2[(size_t)n * 6272 + oc * 49 + p] = cs[row * 133 + oc];
    }
}

// ---- conv3 mma: 512 threads (16 warps, 32x32 per warp) ----
__global__ void __launch_bounds__(512) conv3_mma() {
    extern __shared__ char dsm[];
    __shared__ float m2s[128], r2s[128];
    uint32_t sb = smem_u32(dsm);
    int tid = threadIdx.x, lane = tid & 31, wid = tid >> 5;
    int wm = wid >> 2, wn = wid & 3;
    if (tid < 128) {
        float s = 0.f, q = 0.f;
#pragma unroll
        for (int p = 0; p < 8; p++) { s += g_spart[(tid * 8 + p) * 2]; q += g_spart[(tid * 8 + p) * 2 + 1]; }
        float cnt = (float)NI * 49.f, m = s / cnt;
        m2s[tid] = m; r2s[tid] = rsqrtf(q / cnt - m * m + 1e-5f);
    }
    __syncthreads();
    int M0 = blockIdx.x * 128, N0 = blockIdx.y * 128;
    int arow = tid >> 3, ac4 = (tid & 7) << 2;
    float4 vr[2]; uint2 bhr[2], blr[2];

#define LOADG3(k0) do { \
    _Pragma("unroll") \
    for (int q = 0; q < 2; q++) { \
        int row = q * 64 + arow; \
        vr[q] = *(const float4*)&g_y2[(size_t)(M0 + row) * 6272 + (k0) + ac4]; \
        size_t bi = (size_t)(N0 + row) * 6272 + (k0) + ac4; \
        bhr[q] = *(const uint2*)&g_W3h[bi]; \
        blr[q] = *(const uint2*)&g_W3l[bi]; \
    } } while (0)

#define STORE3(buf, k0) do { \
    _Pragma("unroll") \
    for (int q = 0; q < 2; q++) { \
        int row = q * 64 + arow; \
        float xx[4] = {vr[q].x, vr[q].y, vr[q].z, vr[q].w}; \
        unsigned short hs[4], ls[4]; \
        _Pragma("unroll") \
        for (int j = 0; j < 4; j++) { \
            int cch = ((k0) + ac4 + j) / 49; \
            float t = fmaxf((xx[j] - m2s[cch]) * r2s[cch], 0.f); \
            __nv_bfloat16 h = __float2bfloat16(t); \
            hs[j] = __bfloat16_as_ushort(h); \
            ls[j] = __bfloat16_as_ushort(__float2bfloat16(t - __bfloat162float(h))); \
        } \
        uint32_t off = (buf) * C3_BUF + row * C3_STRIDE + ac4 * 2; \
        *(uint2*)(dsm + C3_AH + off) = make_uint2((uint32_t)hs[0] | ((uint32_t)hs[1] << 16), (uint32_t)hs[2] | ((uint32_t)hs[3] << 16)); \
        *(uint2*)(dsm + C3_AL + off) = make_uint2((uint32_t)ls[0] | ((uint32_t)ls[1] << 16), (uint32_t)ls[2] | ((uint32_t)ls[3] << 16)); \
        *(uint2*)(dsm + C3_BH + off) = bhr[q]; \
        *(uint2*)(dsm + C3_BL + off) = blr[q]; \
    } } while (0)

    float c[2][4][4] = {};
    LOADG3(0); STORE3(0, 0);
    __syncthreads();
    int lm = lane & 15, lkb = (lane >> 4) * 16;
    for (int ch = 0; ch < 196; ch++) {
        int cur = ch & 1;
        if (ch < 195) LOADG3((ch + 1) * 32);
        uint32_t aA = sb + cur * C3_BUF + (wm * 32 + lm) * C3_STRIDE + lkb;
        uint32_t aB = sb + cur * C3_BUF + (wn * 32 + lm) * C3_STRIDE + lkb;
#pragma unroll
        for (int ks = 0; ks < 2; ks++) {
            uint32_t kb = ks * 32;
            uint32_t ah[2][4], al[2][4], bh[2][4], bl[2][4];
#pragma unroll
            for (int mt = 0; mt < 2; mt++) {
                ldsm4(ah[mt], aA + C3_AH + mt * (16 * C3_STRIDE) + kb);
                ldsm4(al[mt], aA + C3_AL + mt * (16 * C3_STRIDE) + kb);
            }
#pragma unroll
            for (int np = 0; np < 2; np++) {
                ldsm4(bh[np], aB + C3_BH + np * (16 * C3_STRIDE) + kb);
                ldsm4(bl[np], aB + C3_BL + np * (16 * C3_STRIDE) + kb);
            }
#pragma unroll
            for (int mt = 0; mt < 2; mt++)
#pragma unroll
                for (int nt = 0; nt < 4; nt++) {
                    int np = nt >> 1, hi = nt & 1;
                    uint32_t b2h[2] = {bh[np][hi], bh[np][hi + 2]};
                    uint32_t b2l[2] = {bl[np][hi], bl[np][hi + 2]};
                    mma_bf16(c[mt][nt], ah[mt], b2h);
                    mma_bf16(c[mt][nt], ah[mt], b2l);
                    mma_bf16(c[mt][nt], al[mt], b2h);
                }
        }
        if (ch < 195) STORE3(cur ^ 1, (ch + 1) * 32);
        __syncthreads();
    }
#undef LOADG3
#undef STORE3
#pragma unroll
    for (int mt = 0; mt < 2; mt++)
#pragma unroll
        for (int nt = 0; nt < 4; nt++) {
            int row = M0 + wm * 32 + mt * 16 + (lane >> 2);
            int col = N0 + wn * 32 + nt * 8 + (lane & 3) * 2;
            *(float2*)&g_y3[(size_t)row * 512 + col] = make_float2(c[mt][nt][0], c[mt][nt][1]);
            *(float2*)&g_y3[(size_t)(row + 8) * 512 + col] = make_float2(c[mt][nt][2], c[mt][nt][3]);
        }
}

__global__ void __launch_bounds__(256) latent_kernel(const float* __restrict__ eps, const float* __restrict__ Wfc,
                                                     const float* __restrict__ bfc) {
    __shared__ float sa[4][512];
    __shared__ float sres[4][64];
    int n0 = blockIdx.x * 4, tid = threadIdx.x;
    for (int i = tid; i < 2048; i += 256) {
        int inst = i >> 9, ic = i & 511;
        sa[inst][ic] = fmaxf((g_y3[(size_t)(n0 + inst) * 512 + ic] - g_mean[2][ic]) * g_rstd[2][ic], 0.f);
    }
    __syncthreads();
    int inst = tid >> 6, r = tid & 63;
    float dot = g_cb[r];
#pragma unroll 8
    for (int ic = 0; ic < 512; ic++) dot += sa[inst][ic] * g_Wc[ic * 64 + r];
    sres[inst][r] = dot;
    __syncthreads();
    if (r < 32) {
        float mu = sres[inst][r], lv = sres[inst][r + 32], sd = expf(0.5f * lv);
        float z = mu + sd * eps[(size_t)(n0 + inst) * 32 + r];
        g_z[(size_t)(n0 + inst) * 32 + r] = z;
        float kl = mu * mu + sd * sd - lv - 1.f;
        float lc = z * Wfc[r];
#pragma unroll
        for (int o = 16; o > 0; o >>= 1) { kl += __shfl_xor_sync(~0u, kl, o); lc += __shfl_xor_sync(~0u, lc, o); }
        if (r == 0) { g_klrow[n0 + inst] = kl; g_loc[n0 + inst] = lc + bfc[0]; }
    }
}

__global__ void __launch_bounds__(256) bagmax_kernel(const int* __restrict__ bi, const float* __restrict__ lab) {
    __shared__ float sv[8]; __shared__ int si[8]; __shared__ float smx;
    int b = blockIdx.x, tid = threadIdx.x, lane = tid & 31, w = tid >> 5;
    float mx = -3.4e38f;
    for (int n = tid; n < NI; n += 256) if (bi[n] == b) mx = fmaxf(mx, g_loc[n]);
#pragma unroll
    for (int o = 16; o > 0; o >>= 1) mx = fmaxf(mx, __shfl_xor_sync(~0u, mx, o));
    if (lane == 0) sv[w] = mx;
    __syncthreads();
    if (tid == 0) { float v = sv[0]; for (int i = 1; i < 8; i++) v = fmaxf(v, sv[i]); smx = v; }
    __syncthreads();
    float mval = smx; int mn = NI;
    for (int n = tid; n < NI; n += 256) if (bi[n] == b && g_loc[n] == mval) mn = min(mn, n);
#pragma unroll
    for (int o = 16; o > 0; o >>= 1) mn = min(mn, __shfl_xor_sync(~0u, mn, o));
    if (lane == 0) si[w] = mn;
    __syncthreads();
    if (tid == 0) {
        int a = si[0]; for (int i = 1; i < 8; i++) a = min(a, si[i]);
        g_arg[b] = a;
        float M = g_loc[a], y = lab[b];
        g_term[b] = fmaxf(M, 0.f) - M * y + log1pf(expf(-fabsf(M)));
    }
}

__global__ void __launch_bounds__(512) dec1_kernel(const float* __restrict__ D1) {
    __shared__ float zz[32];
    int b = blockIdx.x, tid = threadIdx.x;
    if (tid < 32) zz[tid] = g_z[(size_t)g_arg[b] * 32 + tid];
    __syncthreads();
    float a = 0.f;
#pragma unroll
    for (int ic = 0; ic < 32; ic++) a += zz[ic] * D1[ic * 512 + tid];
    g_t1[b * 512 + tid] = a;
}

__global__ void __launch_bounds__(256) dec2_kernel(const float* __restrict__ D2) {
    __shared__ float at[4096];
    int B0 = blockIdx.x * 8, tid = threadIdx.x;
    for (int i = tid; i < 4096; i += 256) {
        int bl = i >> 9, ic = i & 511;
        at[ic * 8 + bl] = fmaxf((g_t1[(B0 + bl) * 512 + ic] - g_mean[3][ic]) * g_rstd[3][ic], 0.f);
    }
    __syncthreads();
    for (int o = tid; o < 6272; o += 256) {
        float acc[8] = {};
        for (int ic = 0; ic < 512; ic++) {
            float w = D2[(size_t)ic * 6272 + o];
            float4 x0 = *(const float4*)&at[ic * 8], x1 = *(const float4*)&at[ic * 8 + 4];
            acc[0] += x0.x * w; acc[1] += x0.y * w; acc[2] += x0.z * w; acc[3] += x0.w * w;
            acc[4] += x1.x * w; acc[5] += x1.y * w; acc[6] += x1.z * w; acc[7] += x1.w * w;
        }
#pragma unroll
        for (int j = 0; j < 8; j++) g_t2[(size_t)(B0 + j) * 6272 + o] = acc[j];
    }
}

__global__ void __launch_bounds__(256) dec3_kernel(const float* __restrict__ D3) {
    __shared__ float a2[6272], wt[2048];
    int b = blockIdx.x, tid = threadIdx.x;
    for (int i = tid; i < 6272; i += 256) {
        int c = i / 49;
        a2[i] = fmaxf((g_t2[(size_t)b * 6272 + i] - g_mean[4][c]) * g_rstd[4][c], 0.f);
    }
    __syncthreads();
    int oy = tid / 14, ox = tid - (tid / 14) * 14;
    for (int oc = 0; oc < 32; oc++) {
        for (int i = tid; i < 2048; i += 256) wt[i] = D3[(i >> 4) * 512 + oc * 16 + (i & 15)];
        __syncthreads();
        if (tid < 196) {
            float a = 0.f;
#pragma unroll
            for (int ky = 0; ky < 4; ky++) {
                int t = oy + 1 - ky;
                if (t >= 0 && !(t & 1) && (t >> 1) < 7) {
                    int iy = t >> 1;
#pragma unroll
                    for (int kx = 0; kx < 4; kx++) {
                        int u = ox + 1 - kx;
                        if (u >= 0 && !(u & 1) && (u >> 1) < 7) {
                            int sB = iy * 7 + (u >> 1), wB = ky * 4 + kx;
#pragma unroll 16
                            for (int ic = 0; ic < 128; ic++) a += a2[ic * 49 + sB] * wt[ic * 16 + wB];
                        }
                    }
                }
            }
            g_t3[(size_t)b * 6272 + oc * 196 + tid] = a;
        }
        __syncthreads();
    }
}

__global__ void __launch_bounds__(256) dec4_kernel(const float* __restrict__ D4, const float* __restrict__ d4,
                                                   const float* __restrict__ bag) {
    __shared__ float a3[6272], w4s[512];
    int b = blockIdx.x, tid = threadIdx.x;
    for (int i = tid; i < 6272; i += 256) {
        int c = i / 196;
        a3[i] = fmaxf((g_t3[(size_t)b * 6272 + i] - g_mean[5][c]) * g_rstd[5][c], 0.f);
    }
    for (int i = tid; i < 512; i += 256) w4s[i] = D4[i];
    __syncthreads();
    float bias = d4[0]; int arg = g_arg[b];
    float sq = 0.f;
    for (int o = tid; o < 784; o += 256) {
        int oy = o / 28, ox = o - (o / 28) * 28;
        float a = bias;
#pragma unroll
        for (int ky = 0; ky < 4; ky++) {
            int t = oy + 1 - ky;
            if (t >= 0 && !(t & 1) && (t >> 1) < 14) {
                int iy = t >> 1;
#pragma unroll
                for (int kx = 0; kx < 4; kx++) {
                    int u = ox + 1 - kx;
                    if (u >= 0 && !(u & 1) && (u >> 1) < 14) {
                        int sB = iy * 14 + (u >> 1), wB = ky * 4 + kx;
#pragma unroll
                        for (int ic = 0; ic < 32; ic++) a += a3[ic * 196 + sB] * w4s[ic * 16 + wB];
                    }
                }
            }
        }
        float s = 1.f / (1.f + expf(-a));
        float d = s - bag[(size_t)arg * 784 + o];
        sq += d * d;
    }
    float2 r = bsum2(make_float2(sq, 0.f));
    if (tid == 0) g_rec[b] = r.x;
}

__global__ void __launch_bounds__(256) final_kernel(float* __restrict__ out) {
    int tid = threadIdx.x;
    float kl = 0.f;
    for (int n = tid; n < NI; n += 256) kl += g_klrow[n];
    float tm = 0.f, rc = 0.f;
    if (tid < NB) { tm = g_term[tid]; rc = g_rec[tid]; }
    float2 a = bsum2(make_float2(kl, tm));
    __syncthreads();
    float2 bb = bsum2(make_float2(rc, 0.f));
    if (tid == 0) {
        out[0] = bb.x / (256.f * 784.f);
        out[1] = 0.5f * a.x / (16384.f * 32.f);
        out[2] = a.y / 256.f;
    }
}

extern "C" void kernel_launch(void* const* d_in, const int* in_sizes, int n_in,
                              void* d_out, int out_size) {
    const float* bag = (const float*)d_in[0];
    const int* bag_idx = (const int*)d_in[1];
    const float* lab = (const float*)d_in[2];
    const float* eps = (const float*)d_in[3];
    const float* W1 = (const float*)d_in[4];
    const float* W2 = (const float*)d_in[6];
    const float* W3 = (const float*)d_in[8];
    const float* W4 = (const float*)d_in[10];
    const float* b4 = (const float*)d_in[11];
    const float* Wm = (const float*)d_in[12];
    const float* bm = (const float*)d_in[13];
    const float* Wlv = (const float*)d_in[14];
    const float* blv = (const float*)d_in[15];
    const float* Wfc = (const float*)d_in[16];
    const float* bfc = (const float*)d_in[17];
    const float* D1 = (const float*)d_in[18];
    const float* D2 = (const float*)d_in[20];
    const float* D3 = (const float*)d_in[22];
    const float* D4 = (const float*)d_in[24];
    const float* d4 = (const float*)d_in[25];

    float *y1, *y2, *y3, *t1, *t2, *t3;
    cudaGetSymbolAddress((void**)&y1, g_y1);
    cudaGetSymbolAddress((void**)&y2, g_y2);
    cudaGetSymbolAddress((void**)&y3, g_y3);
    cudaGetSymbolAddress((void**)&t1, g_t1);
    cudaGetSymbolAddress((void**)&t2, g_t2);
    cudaGetSymbolAddress((void**)&t3, g_t3);

    cudaFuncSetAttribute(conv2_mma, cudaFuncAttributeMaxDynamicSharedMemorySize, C3_SMEM);
    cudaFuncSetAttribute(conv3_mma, cudaFuncAttributeMaxDynamicSharedMemorySize, C3_SMEM);

    prep_kernel<<<12544, 256>>>(W2, W3, Wm, Wlv, W4, b4, bm, blv);
    conv1_kernel<<<NI, 256>>>(bag, W1);
    stats_part<<<dim3(32, 8), 256>>>(y1, 196, NI, 6272, 196, 1);
    conv2_mma<<<6272, 512, C3_SMEM>>>();
    stats_part<<<dim3(128, 8), 256>>>(y2, 49, NI, 6272, 49, 1);
    conv3_mma<<<dim3(128, 4), 512, C3_SMEM>>>();
    stats_part<<<dim3(512, 8), 256>>>(y3, 1, NI, 512, 1, 0);
    stats_fin<<<1, 512>>>(2, 8, NI);
    latent_kernel<<<4096, 256>>>(eps, Wfc, bfc);
    bagmax_kernel<<<NB, 256>>>(bag_idx, lab);
    dec1_kernel<<<NB, 512>>>(D1);
    stats_part<<<dim3(512, 2), 256>>>(t1, 1, NB, 512, 1, 0);
    stats_fin<<<1, 512>>>(3, 2, NB);
    dec2_kernel<<<32, 256>>>(D2);
    stats_part<<<dim3(128, 2), 256>>>(t2, 49, NB, 6272, 49, 1);
    stats_fin<<<1, 128>>>(4, 2, NB * 49);
    dec3_kernel<<<NB, 256>>>(D3);
    stats_part<<<dim3(32, 2), 256>>>(t3, 196, NB, 6272, 196, 1);
    stats_fin<<<1, 32>>>(5, 2, NB * 196);
    dec4_kernel<<<NB, 256>>>(D4, d4, bag);
    final_kernel<<<1, 256>>>((float*)d_out);
}

// round 14
// speedup vs baseline: 1.8799x; 1.0793x over previous
#include <cuda_runtime.h>
#include <cuda_bf16.h>
#include <math.h>
#include <stdint.h>
#define NI 16384
#define NB 256

__device__ float g_y1[102760448];          // channel-last: [n][p(196)][ic(32)]
__device__ float g_y2[102760448];
__device__ float g_y3[8388608];
__device__ float g_p1[1048576];            // conv1 per-block BN partials [n][32][2]
__device__ __nv_bfloat16 g_W2h[65536], g_W2l[65536];   // reordered [oc][kykx*32+ic]
__device__ __nv_bfloat16 g_W3h[3211264], g_W3l[3211264];
__device__ float g_Wc[32768];
__device__ float g_cb[64];
__device__ float g_mean[6][512], g_rstd[6][512];
__device__ float g_spart[16384];
__device__ float g_z[524288];
__device__ float g_loc[NI];
__device__ float g_klrow[NI];
__device__ int   g_arg[NB];
__device__ float g_term[NB];
__device__ float g_rec[NB];
__device__ float g_t1[131072];
__device__ float g_t2[1605632];
__device__ float g_t3[1605632];

__device__ __forceinline__ uint32_t smem_u32(const void* p) {
    uint32_t a;
    asm("{ .reg .u64 t; cvta.to.shared.u64 t, %1; cvt.u32.u64 %0, t; }" : "=r"(a) : "l"(p));
    return a;
}
__device__ __forceinline__ void ldsm4(uint32_t* r, uint32_t addr) {
    asm volatile("ldmatrix.sync.aligned.m8n8.x4.shared.b16 {%0,%1,%2,%3}, [%4];"
        : "=r"(r[0]), "=r"(r[1]), "=r"(r[2]), "=r"(r[3]) : "r"(addr));
}
__device__ __forceinline__ void mma_bf16(float* c, const uint32_t* a, const uint32_t* b) {
    asm volatile("mma.sync.aligned.m16n8k16.row.col.f32.bf16.bf16.f32 "
        "{%0,%1,%2,%3}, {%4,%5,%6,%7}, {%8,%9}, {%0,%1,%2,%3};"
        : "+f"(c[0]), "+f"(c[1]), "+f"(c[2]), "+f"(c[3])
        : "r"(a[0]), "r"(a[1]), "r"(a[2]), "r"(a[3]), "r"(b[0]), "r"(b[1]));
}

__device__ __forceinline__ float2 bsum2(float2 v) {
    __shared__ float2 sh[32];
    int lane = threadIdx.x & 31, w = threadIdx.x >> 5;
#pragma unroll
    for (int o = 16; o > 0; o >>= 1) { v.x += __shfl_xor_sync(~0u, v.x, o); v.y += __shfl_xor_sync(~0u, v.y, o); }
    __syncthreads();
    if (lane == 0) sh[w] = v;
    __syncthreads();
    int nw = (blockDim.x + 31) >> 5;
    if (w == 0) {
        v = (lane < nw) ? sh[lane] : make_float2(0.f, 0.f);
#pragma unroll
        for (int o = 16; o > 0; o >>= 1) { v.x += __shfl_xor_sync(~0u, v.x, o); v.y += __shfl_xor_sync(~0u, v.y, o); }
    }
    return v;
}

__global__ void prep_kernel(const float* W2, const float* W3, const float* Wm, const float* Wlv,
                            const float* W4, const float* b4, const float* bm, const float* blv) {
    int i = blockIdx.x * 256 + threadIdx.x;
    if (i < 65536) {
        int oc = i >> 9, kk = (i >> 5) & 15, ic = i & 31;
        float w = W2[oc * 512 + ic * 16 + kk];
        __nv_bfloat16 h = __float2bfloat16(w);
        g_W2h[i] = h;
        g_W2l[i] = __float2bfloat16(w - __bfloat162float(h));
    }
    if (i < 3211264) {
        float w = W3[i];
        __nv_bfloat16 h = __float2bfloat16(w);
        g_W3h[i] = h;
        g_W3l[i] = __float2bfloat16(w - __bfloat162float(h));
    }
    if (i < 32768) {
        int ic = i >> 6, r = i & 63;
        const float* row = (r < 32) ? (Wm + r * 200) : (Wlv + (r - 32) * 200);
        float s = 0.f;
        for (int j = 0; j < 200; j++) s += row[j] * W4[j * 512 + ic];
        g_Wc[ic * 64 + r] = s;
        if (ic == 0) {
            float cb = (r < 32) ? bm[r] : blv[r - 32];
            for (int j = 0; j < 200; j++) cb += row[j] * b4[j];
            g_cb[r] = cb;
        }
    }
}

// conv1: channel-last out + fused BN1 partial stats
__global__ void __launch_bounds__(256) conv1_kernel(const float* __restrict__ bag, const float* __restrict__ W1) {
    __shared__ float xs[784], ws[512], sm[196 * 33];
    int n = blockIdx.x, tid = threadIdx.x;
    for (int i = tid; i < 784; i += 256) xs[i] = bag[(size_t)n * 784 + i];
    for (int i = tid; i < 512; i += 256) ws[i] = W1[i];
    __syncthreads();
    if (tid < 196) {
        int oy = tid / 14, ox = tid - (tid / 14) * 14;
        float xv[16];
#pragma unroll
        for (int ky = 0; ky < 4; ky++)
#pragma unroll
            for (int kx = 0; kx < 4; kx++) {
                int iy = 2 * oy - 1 + ky, ix = 2 * ox - 1 + kx;
                xv[ky * 4 + kx] = ((unsigned)iy < 28u && (unsigned)ix < 28u) ? xs[iy * 28 + ix] : 0.f;
            }
#pragma unroll 4
        for (int oc = 0; oc < 32; oc++) {
            float a = 0.f;
#pragma unroll
            for (int k = 0; k < 16; k++) a += xv[k] * ws[oc * 16 + k];
            sm[tid * 33 + oc] = a;
        }
    }
    __syncthreads();
    for (int i = tid; i < 6272; i += 256) g_y1[(size_t)n * 6272 + i] = sm[(i >> 5) * 33 + (i & 31)];
    if (tid < 32) {
        float s = 0.f, q = 0.f;
        for (int p = 0; p < 196; p++) { float v = sm[p * 33 + tid]; s += v; q += v * v; }
        g_p1[n * 64 + tid * 2] = s;
        g_p1[n * 64 + tid * 2 + 1] = q;
    }
}

__global__ void __launch_bounds__(256) bn1fin() {
    int c = blockIdx.x, tid = threadIdx.x;
    float s = 0.f, q = 0.f;
    for (int n = tid; n < NI; n += 256) { s += g_p1[n * 64 + c * 2]; q += g_p1[n * 64 + c * 2 + 1]; }
    float2 r = bsum2(make_float2(s, q));
    if (tid == 0) {
        float cnt = (float)NI * 196.f, m = r.x / cnt;
        g_mean[0][c] = m;
        g_rstd[0][c] = rsqrtf(r.y / cnt - m * m + 1e-5f);
    }
}

__global__ void __launch_bounds__(256) stats_part(const float* __restrict__ src, int HW, int Nn, int sN, int sC, int sI) {
    int c = blockIdx.x, p = blockIdx.y, P = gridDim.y, tid = threadIdx.x;
    int total = Nn * HW;
    float s = 0.f, q = 0.f;
    for (int j = p * 256 + tid; j < total; j += P * 256) {
        int n = j / HW, i = j - n * HW;
        float v = src[(size_t)n * sN + (size_t)c * sC + (size_t)i * sI];
        s += v; q += v * v;
    }
    float2 r = bsum2(make_float2(s, q));
    if (tid == 0) { g_spart[(c * P + p) * 2] = r.x; g_spart[(c * P + p) * 2 + 1] = r.y; }
}

__global__ void stats_fin(int id, int P, int count) {
    int c = threadIdx.x;
    float s = 0.f, q = 0.f;
    for (int p = 0; p < P; p++) { s += g_spart[(c * P + p) * 2]; q += g_spart[(c * P + p) * 2 + 1]; }
    float m = s / count;
    g_mean[id][c] = m;
    g_rstd[id][c] = rsqrtf(q / count - m * m + 1e-5f);
}

#define C3_STRIDE 80
#define C3_BUF 10240
#define C3_AH 0
#define C3_AL 20480
#define C3_BH 40960
#define C3_BL 61440
#define C3_SMEM 81920

// ---- conv2 mma: spatial-major K, coalesced float4 A loads ----
__global__ void __launch_bounds__(512) conv2_mma() {
    extern __shared__ char dsm[];
    __shared__ float m1s[32], r1s[32];
    uint32_t sb = smem_u32(dsm);
    int tid = threadIdx.x, lane = tid & 31, wid = tid >> 5;
    int wm = wid >> 2, wn = wid & 3;
    if (tid < 32) { m1s[tid] = g_mean[0][tid]; r1s[tid] = g_rstd[0][tid]; }
    int M0 = blockIdx.x * 128;
    int anb[2], aoy[2], aox[2];
    int c4 = (tid & 7) << 2;
#pragma unroll
    for (int q = 0; q < 2; q++) {
        int f = q * 512 + tid, row = f >> 3;
        int m = M0 + row, n = m / 49, p = m - n * 49;
        aoy[q] = p / 7; aox[q] = p - (p / 7) * 7;
        anb[q] = n * 6272;
    }
    __syncthreads();
    float4 m4 = *(const float4*)&m1s[c4], r4 = *(const float4*)&r1s[c4];
    float4 vr2[2]; uint2 bhr[2], blr[2]; bool vv[2];

#define LOADG2(kt) do { \
    int ky = (kt) >> 2, kx = (kt) & 3; \
    _Pragma("unroll") \
    for (int q = 0; q < 2; q++) { \
        int iy = 2 * aoy[q] - 1 + ky, ix = 2 * aox[q] - 1 + kx; \
        vv[q] = ((unsigned)iy < 14u && (unsigned)ix < 14u); \
        vr2[q] = vv[q] ? *(const float4*)&g_y1[anb[q] + (iy * 14 + ix) * 32 + c4] \
                       : make_float4(0.f, 0.f, 0.f, 0.f); \
        int f = q * 512 + tid, row = f >> 3; \
        size_t bi = (size_t)row * 512 + (kt) * 32 + c4; \
        bhr[q] = *(const uint2*)&g_W2h[bi]; \
        blr[q] = *(const uint2*)&g_W2l[bi]; \
    } } while (0)

#define STORE2(buf) do { \
    _Pragma("unroll") \
    for (int q = 0; q < 2; q++) { \
        int f = q * 512 + tid, row = f >> 3; \
        float xx[4] = {vr2[q].x, vr2[q].y, vr2[q].z, vr2[q].w}; \
        float mm[4] = {m4.x, m4.y, m4.z, m4.w}; \
        float rr[4] = {r4.x, r4.y, r4.z, r4.w}; \
        unsigned short hs[4], ls[4]; \
        _Pragma("unroll") \
        for (int j = 0; j < 4; j++) { \
            float t = vv[q] ? fmaxf((xx[j] - mm[j]) * rr[j], 0.f) : 0.f; \
            __nv_bfloat16 h = __float2bfloat16(t); \
            hs[j] = __bfloat16_as_ushort(h); \
            ls[j] = __bfloat16_as_ushort(__float2bfloat16(t - __bfloat162float(h))); \
        } \
        uint32_t off = (buf) * C3_BUF + row * C3_STRIDE + c4 * 2; \
        *(uint2*)(dsm + C3_AH + off) = make_uint2((uint32_t)hs[0] | ((uint32_t)hs[1] << 16), (uint32_t)hs[2] | ((uint32_t)hs[3] << 16)); \
        *(uint2*)(dsm + C3_AL + off) = make_uint2((uint32_t)ls[0] | ((uint32_t)ls[1] << 16), (uint32_t)ls[2] | ((uint32_t)ls[3] << 16)); \
        *(uint2*)(dsm + C3_BH + off) = bhr[q]; \
        *(uint2*)(dsm + C3_BL + off) = blr[q]; \
    } } while (0)

    float c[2][4][4] = {};
    LOADG2(0); STORE2(0);
    __syncthreads();
    int lm = lane & 15, lkb = (lane >> 4) * 16;
    for (int ch = 0; ch < 16; ch++) {
        int cur = ch & 1;
        if (ch < 15) LOADG2(ch + 1);
        uint32_t aA = sb + cur * C3_BUF + (wm * 32 + lm) * C3_STRIDE + lkb;
        uint32_t aB = sb + cur * C3_BUF + (wn * 32 + lm) * C3_STRIDE + lkb;
#pragma unroll
        for (int ks = 0; ks < 2; ks++) {
            uint32_t kb = ks * 32;
            uint32_t ah[2][4], al[2][4], bh[2][4], bl[2][4];
#pragma unroll
            for (int mt = 0; mt < 2; mt++) {
                ldsm4(ah[mt], aA + C3_AH + mt * (16 * C3_STRIDE) + kb);
                ldsm4(al[mt], aA + C3_AL + mt * (16 * C3_STRIDE) + kb);
            }
#pragma unroll
            for (int np = 0; np < 2; np++) {
                ldsm4(bh[np], aB + C3_BH + np * (16 * C3_STRIDE) + kb);
                ldsm4(bl[np], aB + C3_BL + np * (16 * C3_STRIDE) + kb);
            }
#pragma unroll
            for (int mt = 0; mt < 2; mt++)
#pragma unroll
                for (int nt = 0; nt < 4; nt++) {
                    int np = nt >> 1, hi = nt & 1;
                    uint32_t b2h[2] = {bh[np][hi], bh[np][hi + 2]};
                    uint32_t b2l[2] = {bl[np][hi], bl[np][hi + 2]};
                    mma_bf16(c[mt][nt], ah[mt], b2h);
                    mma_bf16(c[mt][nt], ah[mt], b2l);
                    mma_bf16(c[mt][nt], al[mt], b2h);
                }
        }
        if (ch < 15) STORE2(cur ^ 1);
        __syncthreads();
    }
#undef LOADG2
#undef STORE2
    float* cs = (float*)dsm;
#pragma unroll
    for (int mt = 0; mt < 2; mt++)
#pragma unroll
        for (int nt = 0; nt < 4; nt++) {
            int r0 = wm * 32 + mt * 16 + (lane >> 2);
            int cc = wn * 32 + nt * 8 + (lane & 3) * 2;
            cs[r0 * 133 + cc] = c[mt][nt][0];
            cs[r0 * 133 + cc + 1] = c[mt][nt][1];
            cs[(r0 + 8) * 133 + cc] = c[mt][nt][2];
            cs[(r0 + 8) * 133 + cc + 1] = c[mt][nt][3];
        }
    __syncthreads();
    for (int i = tid; i < 16384; i += 512) {
        int oc = i >> 7, row = i & 127;
        int m = M0 + row, n = m / 49, p = m - n * 49;
        g_y2[(size_t)n * 6272 + oc * 49 + p] = cs[row * 133 + oc];
    }
}

// ---- conv3 mma (unchanged from R13) ----
__global__ void __launch_bounds__(512) conv3_mma() {
    extern __shared__ char dsm[];
    __shared__ float m2s[128], r2s[128];
    uint32_t sb = smem_u32(dsm);
    int tid = threadIdx.x, lane = tid & 31, wid = tid >> 5;
    int wm = wid >> 2, wn = wid & 3;
    if (tid < 128) {
        float s = 0.f, q = 0.f;
#pragma unroll
        for (int p = 0; p < 8; p++) { s += g_spart[(tid * 8 + p) * 2]; q += g_spart[(tid * 8 + p) * 2 + 1]; }
        float cnt = (float)NI * 49.f, m = s / cnt;
        m2s[tid] = m; r2s[tid] = rsqrtf(q / cnt - m * m + 1e-5f);
    }
    __syncthreads();
    int M0 = blockIdx.x * 128, N0 = blockIdx.y * 128;
    int arow = tid >> 3, ac4 = (tid & 7) << 2;
    float4 vr[2]; uint2 bhr[2], blr[2];

#define LOADG3(k0) do { \
    _Pragma("unroll") \
    for (int q = 0; q < 2; q++) { \
        int row = q * 64 + arow; \
        vr[q] = *(const float4*)&g_y2[(size_t)(M0 + row) * 6272 + (k0) + ac4]; \
        size_t bi = (size_t)(N0 + row) * 6272 + (k0) + ac4; \
        bhr[q] = *(const uint2*)&g_W3h[bi]; \
        blr[q] = *(const uint2*)&g_W3l[bi]; \
    } } while (0)

#define STORE3(buf, k0) do { \
    _Pragma("unroll") \
    for (int q = 0; q < 2; q++) { \
        int row = q * 64 + arow; \
        float xx[4] = {vr[q].x, vr[q].y, vr[q].z, vr[q].w}; \
        unsigned short hs[4], ls[4]; \
        _Pragma("unroll") \
        for (int j = 0; j < 4; j++) { \
            int cch = ((k0) + ac4 + j) / 49; \
            float t = fmaxf((xx[j] - m2s[cch]) * r2s[cch], 0.f); \
            __nv_bfloat16 h = __float2bfloat16(t); \
            hs[j] = __bfloat16_as_ushort(h); \
            ls[j] = __bfloat16_as_ushort(__float2bfloat16(t - __bfloat162float(h))); \
        } \
        uint32_t off = (buf) * C3_BUF + row * C3_STRIDE + ac4 * 2; \
        *(uint2*)(dsm + C3_AH + off) = make_uint2((uint32_t)hs[0] | ((uint32_t)hs[1] << 16), (uint32_t)hs[2] | ((uint32_t)hs[3] << 16)); \
        *(uint2*)(dsm + C3_AL + off) = make_uint2((uint32_t)ls[0] | ((uint32_t)ls[1] << 16), (uint32_t)ls[2] | ((uint32_t)ls[3] << 16)); \
        *(uint2*)(dsm + C3_BH + off) = bhr[q]; \
        *(uint2*)(dsm + C3_BL + off) = blr[q]; \
    } } while (0)

    float c[2][4][4] = {};
    LOADG3(0); STORE3(0, 0);
    __syncthreads();
    int lm = lane & 15, lkb = (lane >> 4) * 16;
    for (int ch = 0; ch < 196; ch++) {
        int cur = ch & 1;
        if (ch < 195) LOADG3((ch + 1) * 32);
        uint32_t aA = sb + cur * C3_BUF + (wm * 32 + lm) * C3_STRIDE + lkb;
        uint32_t aB = sb + cur * C3_BUF + (wn * 32 + lm) * C3_STRIDE + lkb;
#pragma unroll
        for (int ks = 0; ks < 2; ks++) {
            uint32_t kb = ks * 32;
            uint32_t ah[2][4], al[2][4], bh[2][4], bl[2][4];
#pragma unroll
            for (int mt = 0; mt < 2; mt++) {
                ldsm4(ah[mt], aA + C3_AH + mt * (16 * C3_STRIDE) + kb);
                ldsm4(al[mt], aA + C3_AL + mt * (16 * C3_STRIDE) + kb);
            }
#pragma unroll
            for (int np = 0; np < 2; np++) {
                ldsm4(bh[np], aB + C3_BH + np * (16 * C3_STRIDE) + kb);
                ldsm4(bl[np], aB + C3_BL + np * (16 * C3_STRIDE) + kb);
            }
#pragma unroll
            for (int mt = 0; mt < 2; mt++)
#pragma unroll
                for (int nt = 0; nt < 4; nt++) {
                    int np = nt >> 1, hi = nt & 1;
                    uint32_t b2h[2] = {bh[np][hi], bh[np][hi + 2]};
                    uint32_t b2l[2] = {bl[np][hi], bl[np][hi + 2]};
                    mma_bf16(c[mt][nt], ah[mt], b2h);
                    mma_bf16(c[mt][nt], ah[mt], b2l);
                    mma_bf16(c[mt][nt], al[mt], b2h);
                }
        }
        if (ch < 195) STORE3(cur ^ 1, (ch + 1) * 32);
        __syncthreads();
    }
#undef LOADG3
#undef STORE3
#pragma unroll
    for (int mt = 0; mt < 2; mt++)
#pragma unroll
        for (int nt = 0; nt < 4; nt++) {
            int row = M0 + wm * 32 + mt * 16 + (lane >> 2);
            int col = N0 + wn * 32 + nt * 8 + (lane & 3) * 2;
            *(float2*)&g_y3[(size_t)row * 512 + col] = make_float2(c[mt][nt][0], c[mt][nt][1]);
            *(float2*)&g_y3[(size_t)(row + 8) * 512 + col] = make_float2(c[mt][nt][2], c[mt][nt][3]);
        }
}

__global__ void __launch_bounds__(256) latent_kernel(const float* __restrict__ eps, const float* __restrict__ Wfc,
                                                     const float* __restrict__ bfc) {
    __shared__ float sa[4][512];
    __shared__ float sres[4][64];
    int n0 = blockIdx.x * 4, tid = threadIdx.x;
    for (int i = tid; i < 2048; i += 256) {
        int inst = i >> 9, ic = i & 511;
        sa[inst][ic] = fmaxf((g_y3[(size_t)(n0 + inst) * 512 + ic] - g_mean[2][ic]) * g_rstd[2][ic], 0.f);
    }
    __syncthreads();
    int inst = tid >> 6, r = tid & 63;
    float dot = g_cb[r];
#pragma unroll 8
    for (int ic = 0; ic < 512; ic++) dot += sa[inst][ic] * g_Wc[ic * 64 + r];
    sres[inst][r] = dot;
    __syncthreads();
    if (r < 32) {
        float mu = sres[inst][r], lv = sres[inst][r + 32], sd = expf(0.5f * lv);
        float z = mu + sd * eps[(size_t)(n0 + inst) * 32 + r];
        g_z[(size_t)(n0 + inst) * 32 + r] = z;
        float kl = mu * mu + sd * sd - lv - 1.f;
        float lc = z * Wfc[r];
#pragma unroll
        for (int o = 16; o > 0; o >>= 1) { kl += __shfl_xor_sync(~0u, kl, o); lc += __shfl_xor_sync(~0u, lc, o); }
        if (r == 0) { g_klrow[n0 + inst] = kl; g_loc[n0 + inst] = lc + bfc[0]; }
    }
}

__global__ void __launch_bounds__(256) bagmax_kernel(const int* __restrict__ bi, const float* __restrict__ lab) {
    __shared__ float sv[8]; __shared__ int si[8]; __shared__ float smx;
    int b = blockIdx.x, tid = threadIdx.x, lane = tid & 31, w = tid >> 5;
    float mx = -3.4e38f;
    for (int n = tid; n < NI; n += 256) if (bi[n] == b) mx = fmaxf(mx, g_loc[n]);
#pragma unroll
    for (int o = 16; o > 0; o >>= 1) mx = fmaxf(mx, __shfl_xor_sync(~0u, mx, o));
    if (lane == 0) sv[w] = mx;
    __syncthreads();
    if (tid == 0) { float v = sv[0]; for (int i = 1; i < 8; i++) v = fmaxf(v, sv[i]); smx = v; }
    __syncthreads();
    float mval = smx; int mn = NI;
    for (int n = tid; n < NI; n += 256) if (bi[n] == b && g_loc[n] == mval) mn = min(mn, n);
#pragma unroll
    for (int o = 16; o > 0; o >>= 1) mn = min(mn, __shfl_xor_sync(~0u, mn, o));
    if (lane == 0) si[w] = mn;
    __syncthreads();
    if (tid == 0) {
        int a = si[0]; for (int i = 1; i < 8; i++) a = min(a, si[i]);
        g_arg[b] = a;
        float M = g_loc[a], y = lab[b];
        g_term[b] = fmaxf(M, 0.f) - M * y + log1pf(expf(-fabsf(M)));
    }
}

__global__ void __launch_bounds__(512) dec1_kernel(const float* __restrict__ D1) {
    __shared__ float zz[32];
    int b = blockIdx.x, tid = threadIdx.x;
    if (tid < 32) zz[tid] = g_z[(size_t)g_arg[b] * 32 + tid];
    __syncthreads();
    float a = 0.f;
#pragma unroll
    for (int ic = 0; ic < 32; ic++) a += zz[ic] * D1[ic * 512 + tid];
    g_t1[b * 512 + tid] = a;
}

__global__ void __launch_bounds__(256) dec2_kernel(const float* __restrict__ D2) {
    __shared__ float at[4096];
    int B0 = blockIdx.x * 8, tid = threadIdx.x;
    for (int i = tid; i < 4096; i += 256) {
        int bl = i >> 9, ic = i & 511;
        at[ic * 8 + bl] = fmaxf((g_t1[(B0 + bl) * 512 + ic] - g_mean[3][ic]) * g_rstd[3][ic], 0.f);
    }
    __syncthreads();
    for (int o = tid; o < 6272; o += 256) {
        float acc[8] = {};
        for (int ic = 0; ic < 512; ic++) {
            float w = D2[(size_t)ic * 6272 + o];
            float4 x0 = *(const float4*)&at[ic * 8], x1 = *(const float4*)&at[ic * 8 + 4];
            acc[0] += x0.x * w; acc[1] += x0.y * w; acc[2] += x0.z * w; acc[3] += x0.w * w;
            acc[4] += x1.x * w; acc[5] += x1.y * w; acc[6] += x1.z * w; acc[7] += x1.w * w;
        }
#pragma unroll
        for (int j = 0; j < 8; j++) g_t2[(size_t)(B0 + j) * 6272 + o] = acc[j];
    }
}

__global__ void __launch_bounds__(256) dec3_kernel(const float* __restrict__ D3) {
    __shared__ float a2[6272], wt[2048];
    int b = blockIdx.x, tid = threadIdx.x;
    for (int i = tid; i < 6272; i += 256) {
        int c = i / 49;
        a2[i] = fmaxf((g_t2[(size_t)b * 6272 + i] - g_mean[4][c]) * g_rstd[4][c], 0.f);
    }
    __syncthreads();
    int oy = tid / 14, ox = tid - (tid / 14) * 14;
    for (int oc = 0; oc < 32; oc++) {
        for (int i = tid; i < 2048; i += 256) wt[i] = D3[(i >> 4) * 512 + oc * 16 + (i & 15)];
        __syncthreads();
        if (tid < 196) {
            float a = 0.f;
#pragma unroll
            for (int ky = 0; ky < 4; ky++) {
                int t = oy + 1 - ky;
                if (t >= 0 && !(t & 1) && (t >> 1) < 7) {
                    int iy = t >> 1;
#pragma unroll
                    for (int kx = 0; kx < 4; kx++) {
                        int u = ox + 1 - kx;
                        if (u >= 0 && !(u & 1) && (u >> 1) < 7) {
                            int sB = iy * 7 + (u >> 1), wB = ky * 4 + kx;
#pragma unroll 16
                            for (int ic = 0; ic < 128; ic++) a += a2[ic * 49 + sB] * wt[ic * 16 + wB];
                        }
                    }
                }
            }
            g_t3[(size_t)b * 6272 + oc * 196 + tid] = a;
        }
        __syncthreads();
    }
}

__global__ void __launch_bounds__(256) dec4_kernel(const float* __restrict__ D4, const float* __restrict__ d4,
                                                   const float* __restrict__ bag) {
    __shared__ float a3[6272], w4s[512];
    int b = blockIdx.x, tid = threadIdx.x;
    for (int i = tid; i < 6272; i += 256) {
        int c = i / 196;
        a3[i] = fmaxf((g_t3[(size_t)b * 6272 + i] - g_mean[5][c]) * g_rstd[5][c], 0.f);
    }
    for (int i = tid; i < 512; i += 256) w4s[i] = D4[i];
    __syncthreads();
    float bias = d4[0]; int arg = g_arg[b];
    float sq = 0.f;
    for (int o = tid; o < 784; o += 256) {
        int oy = o / 28, ox = o - (o / 28) * 28;
        float a = bias;
#pragma unroll
        for (int ky = 0; ky < 4; ky++) {
            int t = oy + 1 - ky;
            if (t >= 0 && !(t & 1) && (t >> 1) < 14) {
                int iy = t >> 1;
#pragma unroll
                for (int kx = 0; kx < 4; kx++) {
                    int u = ox + 1 - kx;
                    if (u >= 0 && !(u & 1) && (u >> 1) < 14) {
                        int sB = iy * 14 + (u >> 1), wB = ky * 4 + kx;
#pragma unroll
                        for (int ic = 0; ic < 32; ic++) a += a3[ic * 196 + sB] * w4s[ic * 16 + wB];
                    }
                }
            }
        }
        float s = 1.f / (1.f + expf(-a));
        float d = s - bag[(size_t)arg * 784 + o];
        sq += d * d;
    }
    float2 r = bsum2(make_float2(sq, 0.f));
    if (tid == 0) g_rec[b] = r.x;
}

__global__ void __launch_bounds__(256) final_kernel(float* __restrict__ out) {
    int tid = threadIdx.x;
    float kl = 0.f;
    for (int n = tid; n < NI; n += 256) kl += g_klrow[n];
    float tm = 0.f, rc = 0.f;
    if (tid < NB) { tm = g_term[tid]; rc = g_rec[tid]; }
    float2 a = bsum2(make_float2(kl, tm));
    __syncthreads();
    float2 bb = bsum2(make_float2(rc, 0.f));
    if (tid == 0) {
        out[0] = bb.x / (256.f * 784.f);
        out[1] = 0.5f * a.x / (16384.f * 32.f);
        out[2] = a.y / 256.f;
    }
}

extern "C" void kernel_launch(void* const* d_in, const int* in_sizes, int n_in,
                              void* d_out, int out_size) {
    const float* bag = (const float*)d_in[0];
    const int* bag_idx = (const int*)d_in[1];
    const float* lab = (const float*)d_in[2];
    const float* eps = (const float*)d_in[3];
    const float* W1 = (const float*)d_in[4];
    const float* W2 = (const float*)d_in[6];
    const float* W3 = (const float*)d_in[8];
    const float* W4 = (const float*)d_in[10];
    const float* b4 = (const float*)d_in[11];
    const float* Wm = (const float*)d_in[12];
    const float* bm = (const float*)d_in[13];
    const float* Wlv = (const float*)d_in[14];
    const float* blv = (const float*)d_in[15];
    const float* Wfc = (const float*)d_in[16];
    const float* bfc = (const float*)d_in[17];
    const float* D1 = (const float*)d_in[18];
    const float* D2 = (const float*)d_in[20];
    const float* D3 = (const float*)d_in[22];
    const float* D4 = (const float*)d_in[24];
    const float* d4 = (const float*)d_in[25];

    float *y2, *y3, *t1, *t2, *t3;
    cudaGetSymbolAddress((void**)&y2, g_y2);
    cudaGetSymbolAddress((void**)&y3, g_y3);
    cudaGetSymbolAddress((void**)&t1, g_t1);
    cudaGetSymbolAddress((void**)&t2, g_t2);
    cudaGetSymbolAddress((void**)&t3, g_t3);

    cudaFuncSetAttribute(conv2_mma, cudaFuncAttributeMaxDynamicSharedMemorySize, C3_SMEM);
    cudaFuncSetAttribute(conv3_mma, cudaFuncAttributeMaxDynamicSharedMemorySize, C3_SMEM);

    prep_kernel<<<12544, 256>>>(W2, W3, Wm, Wlv, W4, b4, bm, blv);
    conv1_kernel<<<NI, 256>>>(bag, W1);
    bn1fin<<<32, 256>>>();
    conv2_mma<<<6272, 512, C3_SMEM>>>();
    stats_part<<<dim3(128, 8), 256>>>(y2, 49, NI, 6272, 49, 1);
    conv3_mma<<<dim3(128, 4), 512, C3_SMEM>>>();
    stats_part<<<dim3(512, 8), 256>>>(y3, 1, NI, 512, 1, 0);
    stats_fin<<<1, 512>>>(2, 8, NI);
    latent_kernel<<<4096, 256>>>(eps, Wfc, bfc);
    bagmax_kernel<<<NB, 256>>>(bag_idx, lab);
    dec1_kernel<<<NB, 512>>>(D1);
    stats_part<<<dim3(512, 2), 256>>>(t1, 1, NB, 512, 1, 0);
    stats_fin<<<1, 512>>>(3, 2, NB);
    dec2_kernel<<<32, 256>>>(D2);
    stats_part<<<dim3(128, 2), 256>>>(t2, 49, NB, 6272, 49, 1);
    stats_fin<<<1, 128>>>(4, 2, NB * 49);
    dec3_kernel<<<NB, 256>>>(D3);
    stats_part<<<dim3(32, 2), 256>>>(t3, 196, NB, 6272, 196, 1);
    stats_fin<<<1, 32>>>(5, 2, NB * 196);
    dec4_kernel<<<NB, 256>>>(D4, d4, bag);
    final_kernel<<<1, 256>>>((float*)d_out);
}

// round 15
// speedup vs baseline: 2.3827x; 1.2674x over previous
#include <cuda_runtime.h>
#include <cuda_bf16.h>
#include <math.h>
#include <stdint.h>
#define NI 16384
#define NB 256

__device__ float g_y1[102760448];          // channel-last: [n][p(196)][ic(32)]
__device__ float g_y2[102760448];
__device__ float g_y3[8388608];
__device__ float g_p1[1048576];
__device__ float g_p2[1605632];            // conv2-block BN2 partials [6272][128][2]
__device__ __nv_bfloat16 g_W2h[65536], g_W2l[65536];
__device__ __nv_bfloat16 g_W3h[3211264], g_W3l[3211264];
__device__ float g_Wc[32768];
__device__ float g_cb[64];
__device__ float g_mean[6][512], g_rstd[6][512];
__device__ float g_spart[16384];
__device__ float g_z[524288];
__device__ float g_loc[NI];
__device__ float g_klrow[NI];
__device__ int   g_arg[NB];
__device__ float g_term[NB];
__device__ float g_rec[NB];
__device__ float g_t1[131072];
__device__ float g_t2[1605632];
__device__ float g_t3[1605632];

__device__ __forceinline__ uint32_t smem_u32(const void* p) {
    uint32_t a;
    asm("{ .reg .u64 t; cvta.to.shared.u64 t, %1; cvt.u32.u64 %0, t; }" : "=r"(a) : "l"(p));
    return a;
}
__device__ __forceinline__ void ldsm4(uint32_t* r, uint32_t addr) {
    asm volatile("ldmatrix.sync.aligned.m8n8.x4.shared.b16 {%0,%1,%2,%3}, [%4];"
        : "=r"(r[0]), "=r"(r[1]), "=r"(r[2]), "=r"(r[3]) : "r"(addr));
}
__device__ __forceinline__ void mma_bf16(float* c, const uint32_t* a, const uint32_t* b) {
    asm volatile("mma.sync.aligned.m16n8k16.row.col.f32.bf16.bf16.f32 "
        "{%0,%1,%2,%3}, {%4,%5,%6,%7}, {%8,%9}, {%0,%1,%2,%3};"
        : "+f"(c[0]), "+f"(c[1]), "+f"(c[2]), "+f"(c[3])
        : "r"(a[0]), "r"(a[1]), "r"(a[2]), "r"(a[3]), "r"(b[0]), "r"(b[1]));
}

__device__ __forceinline__ float2 bsum2(float2 v) {
    __shared__ float2 sh[32];
    int lane = threadIdx.x & 31, w = threadIdx.x >> 5;
#pragma unroll
    for (int o = 16; o > 0; o >>= 1) { v.x += __shfl_xor_sync(~0u, v.x, o); v.y += __shfl_xor_sync(~0u, v.y, o); }
    __syncthreads();
    if (lane == 0) sh[w] = v;
    __syncthreads();
    int nw = (blockDim.x + 31) >> 5;
    if (w == 0) {
        v = (lane < nw) ? sh[lane] : make_float2(0.f, 0.f);
#pragma unroll
        for (int o = 16; o > 0; o >>= 1) { v.x += __shfl_xor_sync(~0u, v.x, o); v.y += __shfl_xor_sync(~0u, v.y, o); }
    }
    return v;
}

__global__ void prep_kernel(const float* W2, const float* W3, const float* Wm, const float* Wlv,
                            const float* W4, const float* b4, const float* bm, const float* blv) {
    int i = blockIdx.x * 256 + threadIdx.x;
    if (i < 65536) {
        int oc = i >> 9, kk = (i >> 5) & 15, ic = i & 31;
        float w = W2[oc * 512 + ic * 16 + kk];
        __nv_bfloat16 h = __float2bfloat16(w);
        g_W2h[i] = h;
        g_W2l[i] = __float2bfloat16(w - __bfloat162float(h));
    }
    if (i < 3211264) {
        float w = W3[i];
        __nv_bfloat16 h = __float2bfloat16(w);
        g_W3h[i] = h;
        g_W3l[i] = __float2bfloat16(w - __bfloat162float(h));
    }
    if (i < 32768) {
        int ic = i >> 6, r = i & 63;
        const float* row = (r < 32) ? (Wm + r * 200) : (Wlv + (r - 32) * 200);
        float s = 0.f;
        for (int j = 0; j < 200; j++) s += row[j] * W4[j * 512 + ic];
        g_Wc[ic * 64 + r] = s;
        if (ic == 0) {
            float cb = (r < 32) ? bm[r] : blv[r - 32];
            for (int j = 0; j < 200; j++) cb += row[j] * b4[j];
            g_cb[r] = cb;
        }
    }
}

__global__ void __launch_bounds__(256) conv1_kernel(const float* __restrict__ bag, const float* __restrict__ W1) {
    __shared__ float xs[784], ws[512], sm[196 * 33];
    int n = blockIdx.x, tid = threadIdx.x;
    for (int i = tid; i < 784; i += 256) xs[i] = bag[(size_t)n * 784 + i];
    for (int i = tid; i < 512; i += 256) ws[i] = W1[i];
    __syncthreads();
    if (tid < 196) {
        int oy = tid / 14, ox = tid - (tid / 14) * 14;
        float xv[16];
#pragma unroll
        for (int ky = 0; ky < 4; ky++)
#pragma unroll
            for (int kx = 0; kx < 4; kx++) {
                int iy = 2 * oy - 1 + ky, ix = 2 * ox - 1 + kx;
                xv[ky * 4 + kx] = ((unsigned)iy < 28u && (unsigned)ix < 28u) ? xs[iy * 28 + ix] : 0.f;
            }
#pragma unroll 4
        for (int oc = 0; oc < 32; oc++) {
            float a = 0.f;
#pragma unroll
            for (int k = 0; k < 16; k++) a += xv[k] * ws[oc * 16 + k];
            sm[tid * 33 + oc] = a;
        }
    }
    __syncthreads();
    for (int i = tid; i < 6272; i += 256) g_y1[(size_t)n * 6272 + i] = sm[(i >> 5) * 33 + (i & 31)];
    if (tid < 32) {
        float s = 0.f, q = 0.f;
        for (int p = 0; p < 196; p++) { float v = sm[p * 33 + tid]; s += v; q += v * v; }
        g_p1[n * 64 + tid * 2] = s;
        g_p1[n * 64 + tid * 2 + 1] = q;
    }
}

__global__ void __launch_bounds__(256) bn1fin() {
    int c = blockIdx.x, tid = threadIdx.x;
    float s = 0.f, q = 0.f;
    for (int n = tid; n < NI; n += 256) { s += g_p1[n * 64 + c * 2]; q += g_p1[n * 64 + c * 2 + 1]; }
    float2 r = bsum2(make_float2(s, q));
    if (tid == 0) {
        float cnt = (float)NI * 196.f, m = r.x / cnt;
        g_mean[0][c] = m;
        g_rstd[0][c] = rsqrtf(r.y / cnt - m * m + 1e-5f);
    }
}

__global__ void __launch_bounds__(256) bn2fin() {
    int c = blockIdx.x, tid = threadIdx.x;
    float s = 0.f, q = 0.f;
    for (int b = tid; b < 6272; b += 256) { s += g_p2[(b * 128 + c) * 2]; q += g_p2[(b * 128 + c) * 2 + 1]; }
    float2 r = bsum2(make_float2(s, q));
    if (tid == 0) {
        float cnt = (float)NI * 49.f, m = r.x / cnt;
        g_mean[1][c] = m;
        g_rstd[1][c] = rsqrtf(r.y / cnt - m * m + 1e-5f);
    }
}

__global__ void __launch_bounds__(256) stats_part(const float* __restrict__ src, int HW, int Nn, int sN, int sC, int sI) {
    int c = blockIdx.x, p = blockIdx.y, P = gridDim.y, tid = threadIdx.x;
    int total = Nn * HW;
    float s = 0.f, q = 0.f;
    for (int j = p * 256 + tid; j < total; j += P * 256) {
        int n = j / HW, i = j - n * HW;
        float v = src[(size_t)n * sN + (size_t)c * sC + (size_t)i * sI];
        s += v; q += v * v;
    }
    float2 r = bsum2(make_float2(s, q));
    if (tid == 0) { g_spart[(c * P + p) * 2] = r.x; g_spart[(c * P + p) * 2 + 1] = r.y; }
}

__global__ void stats_fin(int id, int P, int count) {
    int c = threadIdx.x;
    float s = 0.f, q = 0.f;
    for (int p = 0; p < P; p++) { s += g_spart[(c * P + p) * 2]; q += g_spart[(c * P + p) * 2 + 1]; }
    float m = s / count;
    g_mean[id][c] = m;
    g_rstd[id][c] = rsqrtf(q / count - m * m + 1e-5f);
}

#define C3_STRIDE 80
#define C3_BUF 10240
#define C3_AH 0
#define C3_AL 20480
#define C3_BH 40960
#define C3_BL 61440
#define C3_SMEM 81920

// ---- conv2 mma: precomputed base+mask loader, BN2 partials fused in epilogue ----
__global__ void __launch_bounds__(512) conv2_mma() {
    extern __shared__ char dsm[];
    __shared__ float m1s[32], r1s[32];
    uint32_t sb = smem_u32(dsm);
    int tid = threadIdx.x, lane = tid & 31, wid = tid >> 5;
    int wm = wid >> 2, wn = wid & 3;
    if (tid < 32) { m1s[tid] = g_mean[0][tid]; r1s[tid] = g_rstd[0][tid]; }
    int M0 = blockIdx.x * 128;
    int abase[2]; unsigned vmask[2];
    int c4 = (tid & 7) << 2;
#pragma unroll
    for (int q = 0; q < 2; q++) {
        int f = q * 512 + tid, row = f >> 3;
        int m = M0 + row, n = m / 49, p = m - n * 49;
        int oy = p / 7, ox = p - (p / 7) * 7;
        int by = 2 * oy - 1, bx = 2 * ox - 1;
        abase[q] = n * 6272 + (by * 14 + bx) * 32 + c4;
        unsigned vm = 0;
#pragma unroll
        for (int ky = 0; ky < 4; ky++)
#pragma unroll
            for (int kx = 0; kx < 4; kx++)
                if ((unsigned)(by + ky) < 14u && (unsigned)(bx + kx) < 14u) vm |= 1u << (ky * 4 + kx);
        vmask[q] = vm;
    }
    __syncthreads();
    float4 m4 = *(const float4*)&m1s[c4], r4 = *(const float4*)&r1s[c4];
    float4 vr2[2]; uint2 bhr[2], blr[2]; bool vv[2];

#define LOADG2(kt) do { \
    int ko = (((kt) >> 2) * 14 + ((kt) & 3)) * 32; \
    _Pragma("unroll") \
    for (int q = 0; q < 2; q++) { \
        vv[q] = (vmask[q] >> (kt)) & 1; \
        vr2[q] = vv[q] ? *(const float4*)&g_y1[abase[q] + ko] : make_float4(0.f, 0.f, 0.f, 0.f); \
        int f = q * 512 + tid, row = f >> 3; \
        size_t bi = (size_t)row * 512 + (kt) * 32 + c4; \
        bhr[q] = *(const uint2*)&g_W2h[bi]; \
        blr[q] = *(const uint2*)&g_W2l[bi]; \
    } } while (0)

#define STORE2(buf) do { \
    _Pragma("unroll") \
    for (int q = 0; q < 2; q++) { \
        int f = q * 512 + tid, row = f >> 3; \
        float xx[4] = {vr2[q].x, vr2[q].y, vr2[q].z, vr2[q].w}; \
        float mm[4] = {m4.x, m4.y, m4.z, m4.w}; \
        float rr[4] = {r4.x, r4.y, r4.z, r4.w}; \
        unsigned short hs[4], ls[4]; \
        _Pragma("unroll") \
        for (int j = 0; j < 4; j++) { \
            float t = vv[q] ? fmaxf((xx[j] - mm[j]) * rr[j], 0.f) : 0.f; \
            __nv_bfloat16 h = __float2bfloat16(t); \
            hs[j] = __bfloat16_as_ushort(h); \
            ls[j] = __bfloat16_as_ushort(__float2bfloat16(t - __bfloat162float(h))); \
        } \
        uint32_t off = (buf) * C3_BUF + row * C3_STRIDE + c4 * 2; \
        *(uint2*)(dsm + C3_AH + off) = make_uint2((uint32_t)hs[0] | ((uint32_t)hs[1] << 16), (uint32_t)hs[2] | ((uint32_t)hs[3] << 16)); \
        *(uint2*)(dsm + C3_AL + off) = make_uint2((uint32_t)ls[0] | ((uint32_t)ls[1] << 16), (uint32_t)ls[2] | ((uint32_t)ls[3] << 16)); \
        *(uint2*)(dsm + C3_BH + off) = bhr[q]; \
        *(uint2*)(dsm + C3_BL + off) = blr[q]; \
    } } while (0)

    float c[2][4][4] = {};
    LOADG2(0); STORE2(0);
    __syncthreads();
    int lm = lane & 15, lkb = (lane >> 4) * 16;
    for (int ch = 0; ch < 16; ch++) {
        int cur = ch & 1;
        if (ch < 15) LOADG2(ch + 1);
        uint32_t aA = sb + cur * C3_BUF + (wm * 32 + lm) * C3_STRIDE + lkb;
        uint32_t aB = sb + cur * C3_BUF + (wn * 32 + lm) * C3_STRIDE + lkb;
#pragma unroll
        for (int ks = 0; ks < 2; ks++) {
            uint32_t kb = ks * 32;
            uint32_t ah[2][4], al[2][4], bh[2][4], bl[2][4];
#pragma unroll
            for (int mt = 0; mt < 2; mt++) {
                ldsm4(ah[mt], aA + C3_AH + mt * (16 * C3_STRIDE) + kb);
                ldsm4(al[mt], aA + C3_AL + mt * (16 * C3_STRIDE) + kb);
            }
#pragma unroll
            for (int np = 0; np < 2; np++) {
                ldsm4(bh[np], aB + C3_BH + np * (16 * C3_STRIDE) + kb);
                ldsm4(bl[np], aB + C3_BL + np * (16 * C3_STRIDE) + kb);
            }
#pragma unroll
            for (int mt = 0; mt < 2; mt++)
#pragma unroll
                for (int nt = 0; nt < 4; nt++) {
                    int np = nt >> 1, hi = nt & 1;
                    uint32_t b2h[2] = {bh[np][hi], bh[np][hi + 2]};
                    uint32_t b2l[2] = {bl[np][hi], bl[np][hi + 2]};
                    mma_bf16(c[mt][nt], ah[mt], b2h);
                    mma_bf16(c[mt][nt], ah[mt], b2l);
                    mma_bf16(c[mt][nt], al[mt], b2h);
                }
        }
        if (ch < 15) STORE2(cur ^ 1);
        __syncthreads();
    }
#undef LOADG2
#undef STORE2
    float* cs = (float*)dsm;
#pragma unroll
    for (int mt = 0; mt < 2; mt++)
#pragma unroll
        for (int nt = 0; nt < 4; nt++) {
            int r0 = wm * 32 + mt * 16 + (lane >> 2);
            int cc = wn * 32 + nt * 8 + (lane & 3) * 2;
            cs[r0 * 133 + cc] = c[mt][nt][0];
            cs[r0 * 133 + cc + 1] = c[mt][nt][1];
            cs[(r0 + 8) * 133 + cc] = c[mt][nt][2];
            cs[(r0 + 8) * 133 + cc + 1] = c[mt][nt][3];
        }
    __syncthreads();
    for (int i = tid; i < 16384; i += 512) {
        int oc = i >> 7, row = i & 127;
        int m = M0 + row, n = m / 49, p = m - n * 49;
        g_y2[(size_t)n * 6272 + oc * 49 + p] = cs[row * 133 + oc];
    }
    // BN2 partials: 4 threads per oc, 32 rows each
    {
        int oc = tid >> 2, sg = tid & 3;
        float s = 0.f, q = 0.f;
        for (int r = sg * 32; r < sg * 32 + 32; r++) {
            float v = cs[r * 133 + oc];
            s += v; q += v * v;
        }
        s += __shfl_xor_sync(~0u, s, 1); q += __shfl_xor_sync(~0u, q, 1);
        s += __shfl_xor_sync(~0u, s, 2); q += __shfl_xor_sync(~0u, q, 2);
        if (sg == 0) {
            g_p2[((size_t)blockIdx.x * 128 + oc) * 2] = s;
            g_p2[((size_t)blockIdx.x * 128 + oc) * 2 + 1] = q;
        }
    }
}

// ---- conv3 mma (BN2 from g_mean[1]) ----
__global__ void __launch_bounds__(512) conv3_mma() {
    extern __shared__ char dsm[];
    __shared__ float m2s[128], r2s[128];
    uint32_t sb = smem_u32(dsm);
    int tid = threadIdx.x, lane = tid & 31, wid = tid >> 5;
    int wm = wid >> 2, wn = wid & 3;
    if (tid < 128) { m2s[tid] = g_mean[1][tid]; r2s[tid] = g_rstd[1][tid]; }
    __syncthreads();
    int M0 = blockIdx.x * 128, N0 = blockIdx.y * 128;
    int arow = tid >> 3, ac4 = (tid & 7) << 2;
    float4 vr[2]; uint2 bhr[2], blr[2];

#define LOADG3(k0) do { \
    _Pragma("unroll") \
    for (int q = 0; q < 2; q++) { \
        int row = q * 64 + arow; \
        vr[q] = *(const float4*)&g_y2[(size_t)(M0 + row) * 6272 + (k0) + ac4]; \
        size_t bi = (size_t)(N0 + row) * 6272 + (k0) + ac4; \
        bhr[q] = *(const uint2*)&g_W3h[bi]; \
        blr[q] = *(const uint2*)&g_W3l[bi]; \
    } } while (0)

#define STORE3(buf, k0) do { \
    _Pragma("unroll") \
    for (int q = 0; q < 2; q++) { \
        int row = q * 64 + arow; \
        float xx[4] = {vr[q].x, vr[q].y, vr[q].z, vr[q].w}; \
        unsigned short hs[4], ls[4]; \
        _Pragma("unroll") \
        for (int j = 0; j < 4; j++) { \
            int cch = ((k0) + ac4 + j) / 49; \
            float t = fmaxf((xx[j] - m2s[cch]) * r2s[cch], 0.f); \
            __nv_bfloat16 h = __float2bfloat16(t); \
            hs[j] = __bfloat16_as_ushort(h); \
            ls[j] = __bfloat16_as_ushort(__float2bfloat16(t - __bfloat162float(h))); \
        } \
        uint32_t off = (buf) * C3_BUF + row * C3_STRIDE + ac4 * 2; \
        *(uint2*)(dsm + C3_AH + off) = make_uint2((uint32_t)hs[0] | ((uint32_t)hs[1] << 16), (uint32_t)hs[2] | ((uint32_t)hs[3] << 16)); \
        *(uint2*)(dsm + C3_AL + off) = make_uint2((uint32_t)ls[0] | ((uint32_t)ls[1] << 16), (uint32_t)ls[2] | ((uint32_t)ls[3] << 16)); \
        *(uint2*)(dsm + C3_BH + off) = bhr[q]; \
        *(uint2*)(dsm + C3_BL + off) = blr[q]; \
    } } while (0)

    float c[2][4][4] = {};
    LOADG3(0); STORE3(0, 0);
    __syncthreads();
    int lm = lane & 15, lkb = (lane >> 4) * 16;
    for (int ch = 0; ch < 196; ch++) {
        int cur = ch & 1;
        if (ch < 195) LOADG3((ch + 1) * 32);
        uint32_t aA = sb + cur * C3_BUF + (wm * 32 + lm) * C3_STRIDE + lkb;
        uint32_t aB = sb + cur * C3_BUF + (wn * 32 + lm) * C3_STRIDE + lkb;
#pragma unroll
        for (int ks = 0; ks < 2; ks++) {
            uint32_t kb = ks * 32;
            uint32_t ah[2][4], al[2][4], bh[2][4], bl[2][4];
#pragma unroll
            for (int mt = 0; mt < 2; mt++) {
                ldsm4(ah[mt], aA + C3_AH + mt * (16 * C3_STRIDE) + kb);
                ldsm4(al[mt], aA + C3_AL + mt * (16 * C3_STRIDE) + kb);
            }
#pragma unroll
            for (int np = 0; np < 2; np++) {
                ldsm4(bh[np], aB + C3_BH + np * (16 * C3_STRIDE) + kb);
                ldsm4(bl[np], aB + C3_BL + np * (16 * C3_STRIDE) + kb);
            }
#pragma unroll
            for (int mt = 0; mt < 2; mt++)
#pragma unroll
                for (int nt = 0; nt < 4; nt++) {
                    int np = nt >> 1, hi = nt & 1;
                    uint32_t b2h[2] = {bh[np][hi], bh[np][hi + 2]};
                    uint32_t b2l[2] = {bl[np][hi], bl[np][hi + 2]};
                    mma_bf16(c[mt][nt], ah[mt], b2h);
                    mma_bf16(c[mt][nt], ah[mt], b2l);
                    mma_bf16(c[mt][nt], al[mt], b2h);
                }
        }
        if (ch < 195) STORE3(cur ^ 1, (ch + 1) * 32);
        __syncthreads();
    }
#undef LOADG3
#undef STORE3
#pragma unroll
    for (int mt = 0; mt < 2; mt++)
#pragma unroll
        for (int nt = 0; nt < 4; nt++) {
            int row = M0 + wm * 32 + mt * 16 + (lane >> 2);
            int col = N0 + wn * 32 + nt * 8 + (lane & 3) * 2;
            *(float2*)&g_y3[(size_t)row * 512 + col] = make_float2(c[mt][nt][0], c[mt][nt][1]);
            *(float2*)&g_y3[(size_t)(row + 8) * 512 + col] = make_float2(c[mt][nt][2], c[mt][nt][3]);
        }
}

__global__ void __launch_bounds__(256) latent_kernel(const float* __restrict__ eps, const float* __restrict__ Wfc,
                                                     const float* __restrict__ bfc) {
    __shared__ float sa[4][512];
    __shared__ float sres[4][64];
    int n0 = blockIdx.x * 4, tid = threadIdx.x;
    for (int i = tid; i < 2048; i += 256) {
        int inst = i >> 9, ic = i & 511;
        sa[inst][ic] = fmaxf((g_y3[(size_t)(n0 + inst) * 512 + ic] - g_mean[2][ic]) * g_rstd[2][ic], 0.f);
    }
    __syncthreads();
    int inst = tid >> 6, r = tid & 63;
    float dot = g_cb[r];
#pragma unroll 8
    for (int ic = 0; ic < 512; ic++) dot += sa[inst][ic] * g_Wc[ic * 64 + r];
    sres[inst][r] = dot;
    __syncthreads();
    if (r < 32) {
        float mu = sres[inst][r], lv = sres[inst][r + 32], sd = expf(0.5f * lv);
        float z = mu + sd * eps[(size_t)(n0 + inst) * 32 + r];
        g_z[(size_t)(n0 + inst) * 32 + r] = z;
        float kl = mu * mu + sd * sd - lv - 1.f;
        float lc = z * Wfc[r];
#pragma unroll
        for (int o = 16; o > 0; o >>= 1) { kl += __shfl_xor_sync(~0u, kl, o); lc += __shfl_xor_sync(~0u, lc, o); }
        if (r == 0) { g_klrow[n0 + inst] = kl; g_loc[n0 + inst] = lc + bfc[0]; }
    }
}

__global__ void __launch_bounds__(256) bagmax_kernel(const int* __restrict__ bi, const float* __restrict__ lab) {
    __shared__ float sv[8]; __shared__ int si[8]; __shared__ float smx;
    int b = blockIdx.x, tid = threadIdx.x, lane = tid & 31, w = tid >> 5;
    float mx = -3.4e38f;
    for (int n = tid; n < NI; n += 256) if (bi[n] == b) mx = fmaxf(mx, g_loc[n]);
#pragma unroll
    for (int o = 16; o > 0; o >>= 1) mx = fmaxf(mx, __shfl_xor_sync(~0u, mx, o));
    if (lane == 0) sv[w] = mx;
    __syncthreads();
    if (tid == 0) { float v = sv[0]; for (int i = 1; i < 8; i++) v = fmaxf(v, sv[i]); smx = v; }
    __syncthreads();
    float mval = smx; int mn = NI;
    for (int n = tid; n < NI; n += 256) if (bi[n] == b && g_loc[n] == mval) mn = min(mn, n);
#pragma unroll
    for (int o = 16; o > 0; o >>= 1) mn = min(mn, __shfl_xor_sync(~0u, mn, o));
    if (lane == 0) si[w] = mn;
    __syncthreads();
    if (tid == 0) {
        int a = si[0]; for (int i = 1; i < 8; i++) a = min(a, si[i]);
        g_arg[b] = a;
        float M = g_loc[a], y = lab[b];
        g_term[b] = fmaxf(M, 0.f) - M * y + log1pf(expf(-fabsf(M)));
    }
}

__global__ void __launch_bounds__(512) dec1_kernel(const float* __restrict__ D1) {
    __shared__ float zz[32];
    int b = blockIdx.x, tid = threadIdx.x;
    if (tid < 32) zz[tid] = g_z[(size_t)g_arg[b] * 32 + tid];
    __syncthreads();
    float a = 0.f;
#pragma unroll
    for (int ic = 0; ic < 32; ic++) a += zz[ic] * D1[ic * 512 + tid];
    g_t1[b * 512 + tid] = a;
}

__global__ void __launch_bounds__(256) dec2_kernel(const float* __restrict__ D2) {
    __shared__ float at[4096];
    int B0 = blockIdx.x * 8, tid = threadIdx.x;
    int o0 = blockIdx.y * 784;
    for (int i = tid; i < 4096; i += 256) {
        int bl = i >> 9, ic = i & 511;
        at[ic * 8 + bl] = fmaxf((g_t1[(B0 + bl) * 512 + ic] - g_mean[3][ic]) * g_rstd[3][ic], 0.f);
    }
    __syncthreads();
    for (int o = o0 + tid; o < o0 + 784; o += 256) {
        float acc[8] = {};
        for (int ic = 0; ic < 512; ic++) {
            float w = D2[(size_t)ic * 6272 + o];
            float4 x0 = *(const float4*)&at[ic * 8], x1 = *(const float4*)&at[ic * 8 + 4];
            acc[0] += x0.x * w; acc[1] += x0.y * w; acc[2] += x0.z * w; acc[3] += x0.w * w;
            acc[4] += x1.x * w; acc[5] += x1.y * w; acc[6] += x1.z * w; acc[7] += x1.w * w;
        }
#pragma unroll
        for (int j = 0; j < 8; j++) g_t2[(size_t)(B0 + j) * 6272 + o] = acc[j];
    }
}

__global__ void __launch_bounds__(256) dec3_kernel(const float* __restrict__ D3) {
    __shared__ float a2[6272], wt[2048];
    int b = blockIdx.x, tid = threadIdx.x;
    int oc0 = blockIdx.y * 16;
    for (int i = tid; i < 6272; i += 256) {
        int c = i / 49;
        a2[i] = fmaxf((g_t2[(size_t)b * 6272 + i] - g_mean[4][c]) * g_rstd[4][c], 0.f);
    }
    __syncthreads();
    int oy = tid / 14, ox = tid - (tid / 14) * 14;
    for (int oc = oc0; oc < oc0 + 16; oc++) {
        for (int i = tid; i < 2048; i += 256) wt[i] = D3[(i >> 4) * 512 + oc * 16 + (i & 15)];
        __syncthreads();
        if (tid < 196) {
            float a = 0.f;
#pragma unroll
            for (int ky = 0; ky < 4; ky++) {
                int t = oy + 1 - ky;
                if (t >= 0 && !(t & 1) && (t >> 1) < 7) {
                    int iy = t >> 1;
#pragma unroll
                    for (int kx = 0; kx < 4; kx++) {
                        int u = ox + 1 - kx;
                        if (u >= 0 && !(u & 1) && (u >> 1) < 7) {
                            int sB = iy * 7 + (u >> 1), wB = ky * 4 + kx;
#pragma unroll 16
                            for (int ic = 0; ic < 128; ic++) a += a2[ic * 49 + sB] * wt[ic * 16 + wB];
                        }
                    }
                }
            }
            g_t3[(size_t)b * 6272 + oc * 196 + tid] = a;
        }
        __syncthreads();
    }
}

__global__ void __launch_bounds__(256) dec4_kernel(const float* __restrict__ D4, const float* __restrict__ d4,
                                                   const float* __restrict__ bag) {
    __shared__ float a3[6272], w4s[512];
    int b = blockIdx.x, tid = threadIdx.x;
    for (int i = tid; i < 6272; i += 256) {
        int c = i / 196;
        a3[i] = fmaxf((g_t3[(size_t)b * 6272 + i] - g_mean[5][c]) * g_rstd[5][c], 0.f);
    }
    for (int i = tid; i < 512; i += 256) w4s[i] = D4[i];
    __syncthreads();
    float bias = d4[0]; int arg = g_arg[b];
    float sq = 0.f;
    for (int o = tid; o < 784; o += 256) {
        int oy = o / 28, ox = o - (o / 28) * 28;
        float a = bias;
#pragma unroll
        for (int ky = 0; ky < 4; ky++) {
            int t = oy + 1 - ky;
            if (t >= 0 && !(t & 1) && (t >> 1) < 14) {
                int iy = t >> 1;
#pragma unroll
                for (int kx = 0; kx < 4; kx++) {
                    int u = ox + 1 - kx;
                    if (u >= 0 && !(u & 1) && (u >> 1) < 14) {
                        int sB = iy * 14 + (u >> 1), wB = ky * 4 + kx;
#pragma unroll
                        for (int ic = 0; ic < 32; ic++) a += a3[ic * 196 + sB] * w4s[ic * 16 + wB];
                    }
                }
            }
        }
        float s = 1.f / (1.f + expf(-a));
        float d = s - bag[(size_t)arg * 784 + o];
        sq += d * d;
    }
    float2 r = bsum2(make_float2(sq, 0.f));
    if (tid == 0) g_rec[b] = r.x;
}

__global__ void __launch_bounds__(256) final_kernel(float* __restrict__ out) {
    int tid = threadIdx.x;
    float kl = 0.f;
    for (int n = tid; n < NI; n += 256) kl += g_klrow[n];
    float tm = 0.f, rc = 0.f;
    if (tid < NB) { tm = g_term[tid]; rc = g_rec[tid]; }
    float2 a = bsum2(make_float2(kl, tm));
    __syncthreads();
    float2 bb = bsum2(make_float2(rc, 0.f));
    if (tid == 0) {
        out[0] = bb.x / (256.f * 784.f);
        out[1] = 0.5f * a.x / (16384.f * 32.f);
        out[2] = a.y / 256.f;
    }
}

extern "C" void kernel_launch(void* const* d_in, const int* in_sizes, int n_in,
                              void* d_out, int out_size) {
    const float* bag = (const float*)d_in[0];
    const int* bag_idx = (const int*)d_in[1];
    const float* lab = (const float*)d_in[2];
    const float* eps = (const float*)d_in[3];
    const float* W1 = (const float*)d_in[4];
    const float* W2 = (const float*)d_in[6];
    const float* W3 = (const float*)d_in[8];
    const float* W4 = (const float*)d_in[10];
    const float* b4 = (const float*)d_in[11];
    const float* Wm = (const float*)d_in[12];
    const float* bm = (const float*)d_in[13];
    const float* Wlv = (const float*)d_in[14];
    const float* blv = (const float*)d_in[15];
    const float* Wfc = (const float*)d_in[16];
    const float* bfc = (const float*)d_in[17];
    const float* D1 = (const float*)d_in[18];
    const float* D2 = (const float*)d_in[20];
    const float* D3 = (const float*)d_in[22];
    const float* D4 = (const float*)d_in[24];
    const float* d4 = (const float*)d_in[25];

    float *y3, *t1, *t2, *t3;
    cudaGetSymbolAddress((void**)&y3, g_y3);
    cudaGetSymbolAddress((void**)&t1, g_t1);
    cudaGetSymbolAddress((void**)&t2, g_t2);
    cudaGetSymbolAddress((void**)&t3, g_t3);

    cudaFuncSetAttribute(conv2_mma, cudaFuncAttributeMaxDynamicSharedMemorySize, C3_SMEM);
    cudaFuncSetAttribute(conv3_mma, cudaFuncAttributeMaxDynamicSharedMemorySize, C3_SMEM);

    prep_kernel<<<12544, 256>>>(W2, W3, Wm, Wlv, W4, b4, bm, blv);
    conv1_kernel<<<NI, 256>>>(bag, W1);
    bn1fin<<<32, 256>>>();
    conv2_mma<<<6272, 512, C3_SMEM>>>();
    bn2fin<<<128, 256>>>();
    conv3_mma<<<dim3(128, 4), 512, C3_SMEM>>>();
    stats_part<<<dim3(512, 8), 256>>>(y3, 1, NI, 512, 1, 0);
    stats_fin<<<1, 512>>>(2, 8, NI);
    latent_kernel<<<4096, 256>>>(eps, Wfc, bfc);
    bagmax_kernel<<<NB, 256>>>(bag_idx, lab);
    dec1_kernel<<<NB, 512>>>(D1);
    stats_part<<<dim3(512, 2), 256>>>(t1, 1, NB, 512, 1, 0);
    stats_fin<<<1, 512>>>(3, 2, NB);
    dec2_kernel<<<dim3(32, 8), 256>>>(D2);
    stats_part<<<dim3(128, 2), 256>>>(t2, 49, NB, 6272, 49, 1);
    stats_fin<<<1, 128>>>(4, 2, NB * 49);
    dec3_kernel<<<dim3(NB, 2), 256>>>(D3);
    stats_part<<<dim3(32, 2), 256>>>(t3, 196, NB, 6272, 196, 1);
    stats_fin<<<1, 32>>>(5, 2, NB * 196);
    dec4_kernel<<<NB, 256>>>(D4, d4, bag);
    final_kernel<<<1, 256>>>((float*)d_out);
}